// round 1
// baseline (speedup 1.0000x reference)
#include <cuda_runtime.h>
#include <math.h>

// ---------------- problem dims (fixed) ----------------
#define SQ   1024      // sequence
#define DM   1024      // model dim
#define NH   16        // heads
#define NG   4         // kv groups
#define HDIM 64        // head dim
#define HPG  4         // heads per group
#define GHD  256       // NG*HDIM
#define NL   4         // layers
#define DFF  4096
#define NV   32000
#define RTD  8.0f      // sqrt(HDIM)
#define RTDM 32.0f     // sqrt(DM)

// ---------------- device scratch (static, no allocs) ----------------
__device__ float g_h   [SQ * DM];
__device__ float g_q   [SQ * DM];
__device__ float g_k   [SQ * GHD];
__device__ float g_v   [SQ * GHD];
__device__ float g_sc  [(long)NH * SQ * SQ];   // attention scores (67MB)
__device__ float g_attn[SQ * DM];
__device__ float g_t   [SQ * DM];
__device__ float g_u   [SQ * DFF];
__device__ float g_g   [SQ * DFF];

// ---------------- generic tiled GEMM: C = epilogue(alpha * A @ op(B)) ----------------
// A: [M,K] row-major (lda). TRANSB: B [N,K] (ldb) -> C[m,n]=sum_k A[m,k]B[n,k]
//                    !TRANSB: B [K,N] (ldb) -> C[m,n]=sum_k A[m,k]B[k,n]
// batched over blockIdx.z: A += z*sA, B += (z/bdivB)*sB, C += z*sC
// epilogue: v = acc*alpha; if(bias) v += bias[n]; if(scalev) v *= scalev[n]*beta
#define BM 64
#define BN 64
#define BK 16

template<bool TRANSB>
__global__ void __launch_bounds__(256)
gemm_k(const float* __restrict__ A, const float* __restrict__ B, float* __restrict__ C,
       int M, int N, int K, int lda, int ldb, int ldc,
       long sA, long sB, long sC, int bdivB,
       float alpha, const float* __restrict__ bias,
       const float* __restrict__ scalev, float beta)
{
    __shared__ float As[BK][BM + 4];
    __shared__ float Bs[BK][BN + 4];

    int bz = blockIdx.z;
    A += (long)bz * sA;
    B += (long)(bz / bdivB) * sB;
    C += (long)bz * sC;

    int bm = blockIdx.y * BM;
    int bn = blockIdx.x * BN;
    int tid = threadIdx.x;
    int tx = tid & 15;          // 0..15 (n micro-tile)
    int ty = tid >> 4;          // 0..15 (m micro-tile)

    // A-tile load mapping: 64 rows x 16 k, float4 along k
    int ar = tid >> 2;          // 0..63
    int ak = (tid & 3) * 4;     // 0,4,8,12

    float acc[4][4] = {};

    for (int k0 = 0; k0 < K; k0 += BK) {
        float4 av = *(const float4*)(A + (long)(bm + ar) * lda + k0 + ak);
        As[ak + 0][ar] = av.x; As[ak + 1][ar] = av.y;
        As[ak + 2][ar] = av.z; As[ak + 3][ar] = av.w;

        if (TRANSB) {
            float4 bv = *(const float4*)(B + (long)(bn + ar) * ldb + k0 + ak);
            Bs[ak + 0][ar] = bv.x; Bs[ak + 1][ar] = bv.y;
            Bs[ak + 2][ar] = bv.z; Bs[ak + 3][ar] = bv.w;
        } else {
            int bk  = tid >> 4;          // 0..15
            int bn4 = (tid & 15) * 4;    // 0..60
            float4 bv = *(const float4*)(B + (long)(k0 + bk) * ldb + bn + bn4);
            *(float4*)&Bs[bk][bn4] = bv;
        }
        __syncthreads();

#pragma unroll
        for (int kk = 0; kk < BK; kk++) {
            float4 a4 = *(const float4*)&As[kk][ty * 4];
            float4 b4 = *(const float4*)&Bs[kk][tx * 4];
            float ai[4] = {a4.x, a4.y, a4.z, a4.w};
            float bj[4] = {b4.x, b4.y, b4.z, b4.w};
#pragma unroll
            for (int i = 0; i < 4; i++)
#pragma unroll
                for (int j = 0; j < 4; j++)
                    acc[i][j] = fmaf(ai[i], bj[j], acc[i][j]);
        }
        __syncthreads();
    }

#pragma unroll
    for (int i = 0; i < 4; i++) {
        int row = bm + ty * 4 + i;
        float4 o;
        float* ov = (float*)&o;
#pragma unroll
        for (int j = 0; j < 4; j++) {
            int col = bn + tx * 4 + j;
            float v = acc[i][j] * alpha;
            if (bias)   v += bias[col];
            if (scalev) v *= scalev[col] * beta;
            ov[j] = v;
        }
        *(float4*)(C + (long)row * ldc + bn + tx * 4) = o;
    }
}

// ---------------- embedding gather ----------------
__global__ void embed_k(const int* __restrict__ x, const float* __restrict__ emb,
                        float* __restrict__ h)
{
    int s = blockIdx.x;
    int t = threadIdx.x;   // 256
    const float4* src = (const float4*)(emb + (long)x[s] * DM);
    ((float4*)(h + (long)s * DM))[t] = src[t];
}

// ---------------- RoPE + cosine-norm, Q side (folds eff^2 into Q) ----------------
__global__ void rope_norm_q_k(float* __restrict__ q, const float* __restrict__ sqk)
{
    int s = blockIdx.x, hh = blockIdx.y;
    int j = threadIdx.x;                       // 0..31
    float* base = q + (long)s * DM + hh * HDIM;
    float x1 = base[j], x2 = base[j + 32];

    float inv = powf(10000.0f, -(float)j / 32.0f);
    float ang = (float)s * inv;
    float sn, cs; sincosf(ang, &sn, &cs);
    float o1 = x1 * cs - x2 * sn;
    float o2 = x2 * cs + x1 * sn;

    float ss = o1 * o1 + o2 * o2;
#pragma unroll
    for (int off = 16; off > 0; off >>= 1)
        ss += __shfl_xor_sync(0xffffffffu, ss, off);
    float n = fmaxf(sqrtf(ss), 1e-6f);

    float e1 = sqk[hh * HDIM + j]      * RTD;
    float e2 = sqk[hh * HDIM + j + 32] * RTD;
    base[j]      = (o1 / n) * e1 * e1;   // eff^2 folded into Q (K kept unit-norm)
    base[j + 32] = (o2 / n) * e2 * e2;
}

// ---------------- RoPE + cosine-norm, K side (unit norm only) ----------------
__global__ void rope_norm_kk(float* __restrict__ k)
{
    int s = blockIdx.x, g = blockIdx.y;
    int j = threadIdx.x;
    float* base = k + (long)s * GHD + g * HDIM;
    float x1 = base[j], x2 = base[j + 32];

    float inv = powf(10000.0f, -(float)j / 32.0f);
    float ang = (float)s * inv;
    float sn, cs; sincosf(ang, &sn, &cs);
    float o1 = x1 * cs - x2 * sn;
    float o2 = x2 * cs + x1 * sn;

    float ss = o1 * o1 + o2 * o2;
#pragma unroll
    for (int off = 16; off > 0; off >>= 1)
        ss += __shfl_xor_sync(0xffffffffu, ss, off);
    float n = fmaxf(sqrtf(ss), 1e-6f);

    base[j]      = o1 / n;
    base[j + 32] = o2 / n;
}

// ---------------- causal row softmax over scores ----------------
__global__ void softmax_causal_k(float* __restrict__ scores)
{
    int qr = blockIdx.x, hh = blockIdx.y;
    float* row = scores + (long)hh * SQ * SQ + (long)qr * SQ;
    int valid = qr + 1;
    int t = threadIdx.x;                       // 256
    __shared__ float red[256];

    float m = -1e30f;
    for (int j = t; j < valid; j += 256) m = fmaxf(m, row[j]);
    red[t] = m; __syncthreads();
    for (int o = 128; o > 0; o >>= 1) { if (t < o) red[t] = fmaxf(red[t], red[t + o]); __syncthreads(); }
    m = red[0]; __syncthreads();

    float sum = 0.0f;
    for (int j = t; j < valid; j += 256) { float e = __expf(row[j] - m); row[j] = e; sum += e; }
    red[t] = sum; __syncthreads();
    for (int o = 128; o > 0; o >>= 1) { if (t < o) red[t] += red[t + o]; __syncthreads(); }
    float invs = 1.0f / red[0];

    for (int j = t; j < valid; j += 256) row[j] *= invs;
    for (int j = valid + t; j < SQ; j += 256) row[j] = 0.0f;
}

// ---------------- residual lerp + cosine norm (in place on h) ----------------
__global__ void resid_norm_k(float* __restrict__ h, const float* __restrict__ t,
                             const float* __restrict__ eig)
{
    int row = blockIdx.x;
    int tid = threadIdx.x;                     // 256, one float4 each
    __shared__ float red[256];

    float4 tv = ((const float4*)(t + (long)row * DM))[tid];
    float ss = tv.x * tv.x + tv.y * tv.y + tv.z * tv.z + tv.w * tv.w;
    red[tid] = ss; __syncthreads();
    for (int o = 128; o > 0; o >>= 1) { if (tid < o) red[tid] += red[tid + o]; __syncthreads(); }
    float nt = fmaxf(sqrtf(red[0]), 1e-6f);
    __syncthreads();

    float4 hv = ((const float4*)(h + (long)row * DM))[tid];
    float4 ev = ((const float4*)eig)[tid];
    float4 r;
    r.x = hv.x + ev.x * RTDM * (tv.x / nt - hv.x);
    r.y = hv.y + ev.y * RTDM * (tv.y / nt - hv.y);
    r.z = hv.z + ev.z * RTDM * (tv.z / nt - hv.z);
    r.w = hv.w + ev.w * RTDM * (tv.w / nt - hv.w);

    float ss2 = r.x * r.x + r.y * r.y + r.z * r.z + r.w * r.w;
    red[tid] = ss2; __syncthreads();
    for (int o = 128; o > 0; o >>= 1) { if (tid < o) red[tid] += red[tid + o]; __syncthreads(); }
    float nr = fmaxf(sqrtf(red[0]), 1e-6f);

    r.x /= nr; r.y /= nr; r.z /= nr; r.w /= nr;
    ((float4*)(h + (long)row * DM))[tid] = r;
}

// ---------------- SwiGLU elementwise: u <- (u*s_u) * silu(g*s_v*rtD) ----------------
__global__ void swiglu_k(float* __restrict__ u, const float* __restrict__ g,
                         const float* __restrict__ su, const float* __restrict__ sv)
{
    long idx = (long)blockIdx.x * 256 + threadIdx.x;
    int f = (int)(idx & (DFF - 1));
    float uv = u[idx] * su[f];
    float gv = g[idx] * sv[f] * RTDM;
    u[idx] = uv * gv / (1.0f + __expf(-gv));
}

// ---------------- final row softmax over V=32000 ----------------
__global__ void softmax_full_k(float* __restrict__ out)
{
    int row = blockIdx.x;
    float* p = out + (long)row * NV;
    int t = threadIdx.x;                       // 256
    __shared__ float red[256];

    float m = -1e30f;
    for (int j = t; j < NV; j += 256) m = fmaxf(m, p[j]);
    red[t] = m; __syncthreads();
    for (int o = 128; o > 0; o >>= 1) { if (t < o) red[t] = fmaxf(red[t], red[t + o]); __syncthreads(); }
    m = red[0]; __syncthreads();

    float sum = 0.0f;
    for (int j = t; j < NV; j += 256) { float e = __expf(p[j] - m); p[j] = e; sum += e; }
    red[t] = sum; __syncthreads();
    for (int o = 128; o > 0; o >>= 1) { if (t < o) red[t] += red[t + o]; __syncthreads(); }
    float invs = 1.0f / red[0];

    for (int j = t; j < NV; j += 256) p[j] *= invs;
}

// ---------------- host-side launcher ----------------
static void run_gemm(bool transb, const float* A, const float* B, float* C,
                     int M, int N, int K, int lda, int ldb, int ldc,
                     long sA, long sB, long sC, int bdivB, int batch,
                     float alpha, const float* bias, const float* scalev, float beta)
{
    dim3 grid(N / BN, M / BM, batch);
    if (transb)
        gemm_k<true><<<grid, 256>>>(A, B, C, M, N, K, lda, ldb, ldc,
                                    sA, sB, sC, bdivB, alpha, bias, scalev, beta);
    else
        gemm_k<false><<<grid, 256>>>(A, B, C, M, N, K, lda, ldb, ldc,
                                     sA, sB, sC, bdivB, alpha, bias, scalev, beta);
}

extern "C" void kernel_launch(void* const* d_in, const int* in_sizes, int n_in,
                              void* d_out, int out_size)
{
    const int*   x      = (const int*)  d_in[0];
    const float* emb    = (const float*)d_in[1];
    const float* qw     = (const float*)d_in[2];
    const float* qb     = (const float*)d_in[3];
    const float* kw     = (const float*)d_in[4];
    const float* kb     = (const float*)d_in[5];
    const float* vw     = (const float*)d_in[6];
    const float* vb     = (const float*)d_in[7];
    const float* sqk    = (const float*)d_in[8];
    const float* ow     = (const float*)d_in[9];
    const float* ob     = (const float*)d_in[10];
    const float* w_in   = (const float*)d_in[11];
    const float* b_in   = (const float*)d_in[12];
    const float* w_gate = (const float*)d_in[13];
    const float* b_gate = (const float*)d_in[14];
    const float* w_out  = (const float*)d_in[15];
    const float* b_out  = (const float*)d_in[16];
    const float* s_u    = (const float*)d_in[17];
    const float* s_v    = (const float*)d_in[18];
    const float* eig_a  = (const float*)d_in[19];
    const float* eig_m  = (const float*)d_in[20];
    const float* out_w  = (const float*)d_in[21];
    const float* out_b  = (const float*)d_in[22];
    const float* s_z    = (const float*)d_in[23];
    float* out = (float*)d_out;

    float *h, *q, *k, *v, *sc, *attn, *t, *u, *g;
    cudaGetSymbolAddress((void**)&h,    g_h);
    cudaGetSymbolAddress((void**)&q,    g_q);
    cudaGetSymbolAddress((void**)&k,    g_k);
    cudaGetSymbolAddress((void**)&v,    g_v);
    cudaGetSymbolAddress((void**)&sc,   g_sc);
    cudaGetSymbolAddress((void**)&attn, g_attn);
    cudaGetSymbolAddress((void**)&t,    g_t);
    cudaGetSymbolAddress((void**)&u,    g_u);
    cudaGetSymbolAddress((void**)&g,    g_g);

    embed_k<<<SQ, 256>>>(x, emb, h);

    for (int i = 0; i < NL; i++) {
        const float* Qw = qw + (long)i * DM * DM;
        const float* Kw = kw + (long)i * GHD * DM;
        const float* Vw = vw + (long)i * GHD * DM;
        const float* Ow = ow + (long)i * DM * DM;

        // QKV projections
        run_gemm(true, h, Qw, q, SQ, DM,  DM, DM, DM, DM,  0, 0, 0, 1, 1, 1.0f, qb + (long)i * DM,  nullptr, 0.0f);
        run_gemm(true, h, Kw, k, SQ, GHD, DM, DM, DM, GHD, 0, 0, 0, 1, 1, 1.0f, kb + (long)i * GHD, nullptr, 0.0f);
        run_gemm(true, h, Vw, v, SQ, GHD, DM, DM, DM, GHD, 0, 0, 0, 1, 1, 1.0f, vb + (long)i * GHD, nullptr, 0.0f);

        // RoPE + cosine-norm
        rope_norm_q_k<<<dim3(SQ, NH), 32>>>(q, sqk + (long)i * NH * HDIM);
        rope_norm_kk <<<dim3(SQ, NG), 32>>>(k);

        // scores[h] = (Qh @ Kg^T) * rtd, batched over heads
        run_gemm(true, q, k, sc, SQ, SQ, HDIM, DM, GHD, SQ,
                 /*sA=*/HDIM, /*sB=*/HDIM, /*sC=*/(long)SQ * SQ, /*bdivB=*/HPG, /*batch=*/NH,
                 RTD, nullptr, nullptr, 0.0f);

        softmax_causal_k<<<dim3(SQ, NH), 256>>>(sc);

        // attn[h] = scores[h] @ Vg (NN), batched over heads
        run_gemm(false, sc, v, attn, SQ, HDIM, SQ, SQ, GHD, DM,
                 (long)SQ * SQ, HDIM, HDIM, HPG, NH,
                 1.0f, nullptr, nullptr, 0.0f);

        // output projection + residual/cos-norm
        run_gemm(true, attn, Ow, t, SQ, DM, DM, DM, DM, DM, 0, 0, 0, 1, 1,
                 1.0f, ob + (long)i * DM, nullptr, 0.0f);
        resid_norm_k<<<SQ, 256>>>(h, t, eig_a + (long)i * DM);

        // FFN
        run_gemm(true, h, w_in   + (long)i * DFF * DM, u, SQ, DFF, DM, DM, DM, DFF, 0, 0, 0, 1, 1,
                 1.0f, b_in   + (long)i * DFF, nullptr, 0.0f);
        run_gemm(true, h, w_gate + (long)i * DFF * DM, g, SQ, DFF, DM, DM, DM, DFF, 0, 0, 0, 1, 1,
                 1.0f, b_gate + (long)i * DFF, nullptr, 0.0f);
        swiglu_k<<<(SQ * DFF) / 256, 256>>>(u, g, s_u + (long)i * DFF, s_v + (long)i * DFF);
        run_gemm(true, u, w_out + (long)i * DM * DFF, t, SQ, DM, DFF, DFF, DFF, DM, 0, 0, 0, 1, 1,
                 1.0f, b_out + (long)i * DM, nullptr, 0.0f);
        resid_norm_k<<<SQ, 256>>>(h, t, eig_m + (long)i * DM);
    }

    // logits -> d_out, epilogue (acc + out_b) * (s_z * rtD), then softmax in place
    run_gemm(true, h, out_w, out, SQ, NV, DM, DM, DM, NV, 0, 0, 0, 1, 1,
             1.0f, out_b, s_z, RTDM);
    softmax_full_k<<<SQ, 256>>>(out);
}

// round 2
// speedup vs baseline: 1.9307x; 1.9307x over previous
#include <cuda_runtime.h>
#include <math.h>
#include <stdint.h>

// ---------------- problem dims (fixed) ----------------
#define SQ   1024
#define DM   1024
#define NH   16
#define NG   4
#define HDIM 64
#define HPG  4
#define GHD  256
#define NL   4
#define DFF  4096
#define NV   32000
#define RTD  8.0f
#define RTDM 32.0f

// ---------------- device scratch ----------------
__device__ float g_h   [SQ * DM];
__device__ float g_q   [SQ * DM];
__device__ float g_k   [SQ * GHD];
__device__ float g_v   [SQ * GHD];
__device__ float g_sc  [(long)NH * SQ * SQ];
__device__ float g_attn[SQ * DM];
__device__ float g_t   [SQ * DM];
__device__ float g_u   [SQ * DFF];
__device__ float g_g   [SQ * DFF];

__device__ __forceinline__ uint32_t f2tf(float f) {
    uint32_t u;
    asm("cvt.rna.tf32.f32 %0, %1;" : "=r"(u) : "f"(f));
    return u;
}

__device__ __forceinline__ void mma_tf32(float c[4], uint32_t a0, uint32_t a1,
                                         uint32_t a2, uint32_t a3,
                                         uint32_t b0, uint32_t b1) {
    asm volatile(
        "mma.sync.aligned.m16n8k8.row.col.f32.tf32.tf32.f32 "
        "{%0,%1,%2,%3}, {%4,%5,%6,%7}, {%8,%9}, {%0,%1,%2,%3};"
        : "+f"(c[0]), "+f"(c[1]), "+f"(c[2]), "+f"(c[3])
        : "r"(a0), "r"(a1), "r"(a2), "r"(a3), "r"(b0), "r"(b1));
}

// ================= tensor-core GEMM =================
// BM=128, BK=32, 256 threads (8 warps, 4m x 2n), warp tile 32 x (BN/2).
// TRANSB: B is [N,K] row-major (ldb) -> C = A @ B^T
// !TRANSB: B is [K,N] row-major (ldb) -> C = A @ B   (used with BN=64)
// batched over blockIdx.z: A += z*sA, B += (z/bdivB)*sB, C += z*sC
// epilogue: v = acc*alpha; if(bias) v += bias[col]; if(scalev) v *= scalev[col]*beta
#define BM 128
#define BK 32

template<bool TRANSB, int BN>
__global__ void __launch_bounds__(256)
mma_gemm_k(const float* __restrict__ A, const float* __restrict__ B, float* __restrict__ C,
           int K, int lda, int ldb, int ldc,
           long sA, long sB, long sC, int bdivB,
           float alpha, const float* __restrict__ bias,
           const float* __restrict__ scalev, float beta)
{
    // As: [BM][BK] stride 36  (row-major, k contiguous)
    // Bs TRANSB: [BN][BK] stride 36 ; !TRANSB: [BK][BN] stride BN+8
    __shared__ uint32_t As[BM * 36];
    __shared__ uint32_t Bs[TRANSB ? (BN * 36) : (BK * (BN + 8))];

    const int bz = blockIdx.z;
    A += (long)bz * sA;
    B += (long)(bz / bdivB) * sB;
    C += (long)bz * sC;

    const int bm = blockIdx.y * BM;
    const int bn = blockIdx.x * BN;
    const int tid  = threadIdx.x;
    const int wid  = tid >> 5;
    const int lane = tid & 31;
    const int g4   = lane >> 2;   // groupID
    const int t4   = lane & 3;    // threadID_in_group

    const int wm = (wid & 3) * 32;          // warp m offset in tile
    const int wn = (wid >> 2) * (BN / 2);   // warp n offset in tile
    constexpr int NF = BN / 16;             // n-frags per warp

    // ---- staging-register load mappings ----
    // A: 128 rows x 32 k -> 2 threads/row, 16 floats each (4 x float4)
    const int a_row = tid >> 1;
    const int a_ks  = (tid & 1) * 16;
    // B TRANSB (BN==128): same mapping over N rows
    const int b_row = tid >> 1;
    const int b_ks  = (tid & 1) * 16;
    // B NN: 32 k-rows x BN cols -> (256/32)=8 threads/row, BN/8 floats each
    const int c_row = tid >> 3;             // k-row 0..31
    const int c_ns  = (tid & 7) * (BN / 8); // col segment

    float4 ra[4], rb[4];

    auto loadA = [&](int k0) {
        const float* p = A + (long)(bm + a_row) * lda + k0 + a_ks;
#pragma unroll
        for (int i = 0; i < 4; i++) ra[i] = *(const float4*)(p + i * 4);
    };
    auto loadB = [&](int k0) {
        if (TRANSB) {
            const float* p = B + (long)(bn + b_row) * ldb + k0 + b_ks;
#pragma unroll
            for (int i = 0; i < 4; i++) rb[i] = *(const float4*)(p + i * 4);
        } else {
            const float* p = B + (long)(k0 + c_row) * ldb + bn + c_ns;
#pragma unroll
            for (int i = 0; i < BN / 32; i++) rb[i] = *(const float4*)(p + i * 4);
        }
    };
    auto storeS = [&]() {
        {
            uint32_t* d = As + a_row * 36 + a_ks;
#pragma unroll
            for (int i = 0; i < 4; i++) {
                d[i * 4 + 0] = f2tf(ra[i].x); d[i * 4 + 1] = f2tf(ra[i].y);
                d[i * 4 + 2] = f2tf(ra[i].z); d[i * 4 + 3] = f2tf(ra[i].w);
            }
        }
        if (TRANSB) {
            uint32_t* d = Bs + b_row * 36 + b_ks;
#pragma unroll
            for (int i = 0; i < 4; i++) {
                d[i * 4 + 0] = f2tf(rb[i].x); d[i * 4 + 1] = f2tf(rb[i].y);
                d[i * 4 + 2] = f2tf(rb[i].z); d[i * 4 + 3] = f2tf(rb[i].w);
            }
        } else {
            uint32_t* d = Bs + c_row * (BN + 8) + c_ns;
#pragma unroll
            for (int i = 0; i < BN / 32; i++) {
                d[i * 4 + 0] = f2tf(rb[i].x); d[i * 4 + 1] = f2tf(rb[i].y);
                d[i * 4 + 2] = f2tf(rb[i].z); d[i * 4 + 3] = f2tf(rb[i].w);
            }
        }
    };

    float acc[2][NF][4];
#pragma unroll
    for (int i = 0; i < 2; i++)
#pragma unroll
        for (int j = 0; j < NF; j++)
#pragma unroll
            for (int l = 0; l < 4; l++) acc[i][j][l] = 0.0f;

    loadA(0); loadB(0);

    for (int k0 = 0; k0 < K; k0 += BK) {
        __syncthreads();           // previous compute done reading smem
        storeS();
        __syncthreads();
        if (k0 + BK < K) { loadA(k0 + BK); loadB(k0 + BK); }   // overlap with mma

#pragma unroll
        for (int k8 = 0; k8 < BK / 8; k8++) {
            const int kk = k8 * 8;
            uint32_t af[2][4];
#pragma unroll
            for (int mf = 0; mf < 2; mf++) {
                const int r0 = wm + mf * 16 + g4;
                af[mf][0] = As[(r0    ) * 36 + kk + t4    ];
                af[mf][1] = As[(r0 + 8) * 36 + kk + t4    ];
                af[mf][2] = As[(r0    ) * 36 + kk + t4 + 4];
                af[mf][3] = As[(r0 + 8) * 36 + kk + t4 + 4];
            }
#pragma unroll
            for (int nf = 0; nf < NF; nf++) {
                uint32_t b0, b1;
                if (TRANSB) {
                    const int n0 = wn + nf * 8 + g4;
                    b0 = Bs[n0 * 36 + kk + t4];
                    b1 = Bs[n0 * 36 + kk + t4 + 4];
                } else {
                    b0 = Bs[(kk + t4    ) * (BN + 8) + wn + nf * 8 + g4];
                    b1 = Bs[(kk + t4 + 4) * (BN + 8) + wn + nf * 8 + g4];
                }
                mma_tf32(acc[0][nf], af[0][0], af[0][1], af[0][2], af[0][3], b0, b1);
                mma_tf32(acc[1][nf], af[1][0], af[1][1], af[1][2], af[1][3], b0, b1);
            }
        }
    }

    // ---- epilogue ----
#pragma unroll
    for (int mf = 0; mf < 2; mf++) {
#pragma unroll
        for (int nf = 0; nf < NF; nf++) {
            const int row = bm + wm + mf * 16 + g4;
            const int col = bn + wn + nf * 8 + t4 * 2;
            float v0 = acc[mf][nf][0] * alpha;
            float v1 = acc[mf][nf][1] * alpha;
            float v2 = acc[mf][nf][2] * alpha;
            float v3 = acc[mf][nf][3] * alpha;
            if (bias) {
                float b0 = bias[col], b1 = bias[col + 1];
                v0 += b0; v1 += b1; v2 += b0; v3 += b1;
            }
            if (scalev) {
                float s0 = scalev[col] * beta, s1 = scalev[col + 1] * beta;
                v0 *= s0; v1 *= s1; v2 *= s0; v3 *= s1;
            }
            *(float2*)(C + (long)row * ldc + col)       = make_float2(v0, v1);
            *(float2*)(C + (long)(row + 8) * ldc + col) = make_float2(v2, v3);
        }
    }
}

// ---------------- embedding gather ----------------
__global__ void embed_k(const int* __restrict__ x, const float* __restrict__ emb,
                        float* __restrict__ h)
{
    int s = blockIdx.x;
    int t = threadIdx.x;
    const float4* src = (const float4*)(emb + (long)x[s] * DM);
    ((float4*)(h + (long)s * DM))[t] = src[t];
}

// ---------------- RoPE + cosine-norm, Q (folds eff^2 into Q) ----------------
__global__ void rope_norm_q_k(float* __restrict__ q, const float* __restrict__ sqk)
{
    int s = blockIdx.x, hh = blockIdx.y;
    int j = threadIdx.x;
    float* base = q + (long)s * DM + hh * HDIM;
    float x1 = base[j], x2 = base[j + 32];

    float inv = powf(10000.0f, -(float)j / 32.0f);
    float ang = (float)s * inv;
    float sn, cs; sincosf(ang, &sn, &cs);
    float o1 = x1 * cs - x2 * sn;
    float o2 = x2 * cs + x1 * sn;

    float ss = o1 * o1 + o2 * o2;
#pragma unroll
    for (int off = 16; off > 0; off >>= 1)
        ss += __shfl_xor_sync(0xffffffffu, ss, off);
    float n = fmaxf(sqrtf(ss), 1e-6f);

    float e1 = sqk[hh * HDIM + j]      * RTD;
    float e2 = sqk[hh * HDIM + j + 32] * RTD;
    base[j]      = (o1 / n) * e1 * e1;
    base[j + 32] = (o2 / n) * e2 * e2;
}

// ---------------- RoPE + cosine-norm, K ----------------
__global__ void rope_norm_kk(float* __restrict__ k)
{
    int s = blockIdx.x, g = blockIdx.y;
    int j = threadIdx.x;
    float* base = k + (long)s * GHD + g * HDIM;
    float x1 = base[j], x2 = base[j + 32];

    float inv = powf(10000.0f, -(float)j / 32.0f);
    float ang = (float)s * inv;
    float sn, cs; sincosf(ang, &sn, &cs);
    float o1 = x1 * cs - x2 * sn;
    float o2 = x2 * cs + x1 * sn;

    float ss = o1 * o1 + o2 * o2;
#pragma unroll
    for (int off = 16; off > 0; off >>= 1)
        ss += __shfl_xor_sync(0xffffffffu, ss, off);
    float n = fmaxf(sqrtf(ss), 1e-6f);

    base[j]      = o1 / n;
    base[j + 32] = o2 / n;
}

// ---------------- causal row softmax ----------------
__global__ void softmax_causal_k(float* __restrict__ scores)
{
    int qr = blockIdx.x, hh = blockIdx.y;
    float* row = scores + (long)hh * SQ * SQ + (long)qr * SQ;
    int valid = qr + 1;
    int t = threadIdx.x;
    __shared__ float red[256];

    float m = -1e30f;
    for (int j = t; j < valid; j += 256) m = fmaxf(m, row[j]);
    red[t] = m; __syncthreads();
    for (int o = 128; o > 0; o >>= 1) { if (t < o) red[t] = fmaxf(red[t], red[t + o]); __syncthreads(); }
    m = red[0]; __syncthreads();

    float sum = 0.0f;
    for (int j = t; j < valid; j += 256) { float e = __expf(row[j] - m); row[j] = e; sum += e; }
    red[t] = sum; __syncthreads();
    for (int o = 128; o > 0; o >>= 1) { if (t < o) red[t] += red[t + o]; __syncthreads(); }
    float invs = 1.0f / red[0];

    for (int j = t; j < valid; j += 256) row[j] *= invs;
    for (int j = valid + t; j < SQ; j += 256) row[j] = 0.0f;
}

// ---------------- residual lerp + cosine norm ----------------
__global__ void resid_norm_k(float* __restrict__ h, const float* __restrict__ t,
                             const float* __restrict__ eig)
{
    int row = blockIdx.x;
    int tid = threadIdx.x;
    __shared__ float red[256];

    float4 tv = ((const float4*)(t + (long)row * DM))[tid];
    float ss = tv.x * tv.x + tv.y * tv.y + tv.z * tv.z + tv.w * tv.w;
    red[tid] = ss; __syncthreads();
    for (int o = 128; o > 0; o >>= 1) { if (tid < o) red[tid] += red[tid + o]; __syncthreads(); }
    float nt = fmaxf(sqrtf(red[0]), 1e-6f);
    __syncthreads();

    float4 hv = ((const float4*)(h + (long)row * DM))[tid];
    float4 ev = ((const float4*)eig)[tid];
    float4 r;
    r.x = hv.x + ev.x * RTDM * (tv.x / nt - hv.x);
    r.y = hv.y + ev.y * RTDM * (tv.y / nt - hv.y);
    r.z = hv.z + ev.z * RTDM * (tv.z / nt - hv.z);
    r.w = hv.w + ev.w * RTDM * (tv.w / nt - hv.w);

    float ss2 = r.x * r.x + r.y * r.y + r.z * r.z + r.w * r.w;
    red[tid] = ss2; __syncthreads();
    for (int o = 128; o > 0; o >>= 1) { if (tid < o) red[tid] += red[tid + o]; __syncthreads(); }
    float nr = fmaxf(sqrtf(red[0]), 1e-6f);

    r.x /= nr; r.y /= nr; r.z /= nr; r.w /= nr;
    ((float4*)(h + (long)row * DM))[tid] = r;
}

// ---------------- SwiGLU ----------------
__global__ void swiglu_k(float* __restrict__ u, const float* __restrict__ g,
                         const float* __restrict__ su, const float* __restrict__ sv)
{
    long idx = (long)blockIdx.x * 256 + threadIdx.x;
    int f = (int)(idx & (DFF - 1));
    float uv = u[idx] * su[f];
    float gv = g[idx] * sv[f] * RTDM;
    u[idx] = uv * gv / (1.0f + __expf(-gv));
}

// ---------------- final row softmax ----------------
__global__ void softmax_full_k(float* __restrict__ out)
{
    int row = blockIdx.x;
    float* p = out + (long)row * NV;
    int t = threadIdx.x;
    __shared__ float red[256];

    float m = -1e30f;
    for (int j = t; j < NV; j += 256) m = fmaxf(m, p[j]);
    red[t] = m; __syncthreads();
    for (int o = 128; o > 0; o >>= 1) { if (t < o) red[t] = fmaxf(red[t], red[t + o]); __syncthreads(); }
    m = red[0]; __syncthreads();

    float sum = 0.0f;
    for (int j = t; j < NV; j += 256) { float e = __expf(p[j] - m); p[j] = e; sum += e; }
    red[t] = sum; __syncthreads();
    for (int o = 128; o > 0; o >>= 1) { if (t < o) red[t] += red[t + o]; __syncthreads(); }
    float invs = 1.0f / red[0];

    for (int j = t; j < NV; j += 256) p[j] *= invs;
}

// ---------------- host-side launchers ----------------
static void gemm_tb(const float* A, const float* B, float* C,
                    int M, int N, int K, int lda, int ldb, int ldc,
                    long sA, long sB, long sC, int bdivB, int batch,
                    float alpha, const float* bias, const float* scalev, float beta)
{
    dim3 grid(N / 128, M / BM, batch);
    mma_gemm_k<true, 128><<<grid, 256>>>(A, B, C, K, lda, ldb, ldc,
                                         sA, sB, sC, bdivB, alpha, bias, scalev, beta);
}

static void gemm_nn64(const float* A, const float* B, float* C,
                      int M, int N, int K, int lda, int ldb, int ldc,
                      long sA, long sB, long sC, int bdivB, int batch,
                      float alpha)
{
    dim3 grid(N / 64, M / BM, batch);
    mma_gemm_k<false, 64><<<grid, 256>>>(A, B, C, K, lda, ldb, ldc,
                                         sA, sB, sC, bdivB, alpha, nullptr, nullptr, 0.0f);
}

extern "C" void kernel_launch(void* const* d_in, const int* in_sizes, int n_in,
                              void* d_out, int out_size)
{
    const int*   x      = (const int*)  d_in[0];
    const float* emb    = (const float*)d_in[1];
    const float* qw     = (const float*)d_in[2];
    const float* qb     = (const float*)d_in[3];
    const float* kw     = (const float*)d_in[4];
    const float* kb     = (const float*)d_in[5];
    const float* vw     = (const float*)d_in[6];
    const float* vb     = (const float*)d_in[7];
    const float* sqk    = (const float*)d_in[8];
    const float* ow     = (const float*)d_in[9];
    const float* ob     = (const float*)d_in[10];
    const float* w_in   = (const float*)d_in[11];
    const float* b_in   = (const float*)d_in[12];
    const float* w_gate = (const float*)d_in[13];
    const float* b_gate = (const float*)d_in[14];
    const float* w_out  = (const float*)d_in[15];
    const float* b_out  = (const float*)d_in[16];
    const float* s_u    = (const float*)d_in[17];
    const float* s_v    = (const float*)d_in[18];
    const float* eig_a  = (const float*)d_in[19];
    const float* eig_m  = (const float*)d_in[20];
    const float* out_w  = (const float*)d_in[21];
    const float* out_b  = (const float*)d_in[22];
    const float* s_z    = (const float*)d_in[23];
    float* out = (float*)d_out;

    float *h, *q, *k, *v, *sc, *attn, *t, *u, *g;
    cudaGetSymbolAddress((void**)&h,    g_h);
    cudaGetSymbolAddress((void**)&q,    g_q);
    cudaGetSymbolAddress((void**)&k,    g_k);
    cudaGetSymbolAddress((void**)&v,    g_v);
    cudaGetSymbolAddress((void**)&sc,   g_sc);
    cudaGetSymbolAddress((void**)&attn, g_attn);
    cudaGetSymbolAddress((void**)&t,    g_t);
    cudaGetSymbolAddress((void**)&u,    g_u);
    cudaGetSymbolAddress((void**)&g,    g_g);

    embed_k<<<SQ, 256>>>(x, emb, h);

    for (int i = 0; i < NL; i++) {
        const float* Qw = qw + (long)i * DM * DM;
        const float* Kw = kw + (long)i * GHD * DM;
        const float* Vw = vw + (long)i * GHD * DM;
        const float* Ow = ow + (long)i * DM * DM;

        // QKV projections (C = h @ W^T + b)
        gemm_tb(h, Qw, q, SQ, DM,  DM, DM, DM, DM,  0, 0, 0, 1, 1, 1.0f, qb + (long)i * DM,  nullptr, 0.0f);
        gemm_tb(h, Kw, k, SQ, GHD, DM, DM, DM, GHD, 0, 0, 0, 1, 1, 1.0f, kb + (long)i * GHD, nullptr, 0.0f);
        gemm_tb(h, Vw, v, SQ, GHD, DM, DM, DM, GHD, 0, 0, 0, 1, 1, 1.0f, vb + (long)i * GHD, nullptr, 0.0f);

        rope_norm_q_k<<<dim3(SQ, NH), 32>>>(q, sqk + (long)i * NH * HDIM);
        rope_norm_kk <<<dim3(SQ, NG), 32>>>(k);

        // scores[h] = (Qh @ Kg^T) * rtd, batched over heads
        gemm_tb(q, k, sc, SQ, SQ, HDIM, DM, GHD, SQ,
                HDIM, HDIM, (long)SQ * SQ, HPG, NH,
                RTD, nullptr, nullptr, 0.0f);

        softmax_causal_k<<<dim3(SQ, NH), 256>>>(sc);

        // attn[h] = scores[h] @ Vg  (NN, N=64)
        gemm_nn64(sc, v, attn, SQ, HDIM, SQ, SQ, GHD, DM,
                  (long)SQ * SQ, HDIM, HDIM, HPG, NH, 1.0f);

        // output projection + residual
        gemm_tb(attn, Ow, t, SQ, DM, DM, DM, DM, DM, 0, 0, 0, 1, 1,
                1.0f, ob + (long)i * DM, nullptr, 0.0f);
        resid_norm_k<<<SQ, 256>>>(h, t, eig_a + (long)i * DM);

        // FFN
        gemm_tb(h, w_in   + (long)i * DFF * DM, u, SQ, DFF, DM, DM, DM, DFF, 0, 0, 0, 1, 1,
                1.0f, b_in   + (long)i * DFF, nullptr, 0.0f);
        gemm_tb(h, w_gate + (long)i * DFF * DM, g, SQ, DFF, DM, DM, DM, DFF, 0, 0, 0, 1, 1,
                1.0f, b_gate + (long)i * DFF, nullptr, 0.0f);
        swiglu_k<<<(SQ * DFF) / 256, 256>>>(u, g, s_u + (long)i * DFF, s_v + (long)i * DFF);
        gemm_tb(u, w_out + (long)i * DM * DFF, t, SQ, DM, DFF, DFF, DFF, DM, 0, 0, 0, 1, 1,
                1.0f, b_out + (long)i * DM, nullptr, 0.0f);
        resid_norm_k<<<SQ, 256>>>(h, t, eig_m + (long)i * DM);
    }

    // logits -> d_out, epilogue (acc + out_b) * (s_z * rtD), softmax in place
    gemm_tb(h, out_w, out, SQ, NV, DM, DM, DM, NV, 0, 0, 0, 1, 1,
            1.0f, out_b, s_z, RTDM);
    softmax_full_k<<<SQ, 256>>>(out);
}

// round 4
// speedup vs baseline: 2.2878x; 1.1849x over previous
#include <cuda_runtime.h>
#include <cuda_bf16.h>
#include <math.h>
#include <stdint.h>

// ---------------- problem dims (fixed) ----------------
#define SQ   1024
#define DM   1024
#define NH   16
#define NG   4
#define HDIM 64
#define HPG  4
#define GHD  256
#define NL   4
#define DFF  4096
#define NV   32000
#define QKV  1536      // DM + 2*GHD
#define RTD  8.0f
#define RTDM 32.0f

// ---------------- device scratch ----------------
__device__ float g_h   [SQ * DM];
__device__ float g_qkv [SQ * QKV];
__device__ float g_sc  [(long)NH * SQ * SQ];
__device__ float g_attn[SQ * DM];
__device__ float g_t   [SQ * DM];
__device__ float g_u   [SQ * DFF];
__device__ float g_g   [SQ * DFF];
__device__ float g_qkvw[(long)NL * QKV * DM];
__device__ float g_qkvb[NL * QKV];

__device__ __forceinline__ uint32_t packbf(float x, float y) {
    __nv_bfloat162 t = __floats2bfloat162_rn(x, y);
    return *reinterpret_cast<uint32_t*>(&t);
}

__device__ __forceinline__ uint32_t f2tf(float f) {
    uint32_t u;
    asm("cvt.rna.tf32.f32 %0, %1;" : "=r"(u) : "f"(f));
    return u;
}

__device__ __forceinline__ void mma_bf16(float c[4], uint32_t a0, uint32_t a1,
                                         uint32_t a2, uint32_t a3,
                                         uint32_t b0, uint32_t b1) {
    asm volatile(
        "mma.sync.aligned.m16n8k16.row.col.f32.bf16.bf16.f32 "
        "{%0,%1,%2,%3}, {%4,%5,%6,%7}, {%8,%9}, {%0,%1,%2,%3};"
        : "+f"(c[0]), "+f"(c[1]), "+f"(c[2]), "+f"(c[3])
        : "r"(a0), "r"(a1), "r"(a2), "r"(a3), "r"(b0), "r"(b1));
}

__device__ __forceinline__ void mma_tf32(float c[4], uint32_t a0, uint32_t a1,
                                         uint32_t a2, uint32_t a3,
                                         uint32_t b0, uint32_t b1) {
    asm volatile(
        "mma.sync.aligned.m16n8k8.row.col.f32.tf32.tf32.f32 "
        "{%0,%1,%2,%3}, {%4,%5,%6,%7}, {%8,%9}, {%0,%1,%2,%3};"
        : "+f"(c[0]), "+f"(c[1]), "+f"(c[2]), "+f"(c[3])
        : "r"(a0), "r"(a1), "r"(a2), "r"(a3), "r"(b0), "r"(b1));
}

// ================= bf16 TB GEMM =================
// C[M,N] = epi(alpha * A[M,K] @ B[N,K]^T), tiles 128x128x32, 256 thr (8 warps 4x2),
// double-buffered static smem, bf16x2 words, stride 20 (conflict-free).
// batched: A += z*sA, B += (z/bdivB)*sB, C += z*sC
#define TASTR 20
#define TAW   (128 * TASTR)

__global__ void __launch_bounds__(256)
bf16_tb_k(const float* __restrict__ A, const float* __restrict__ B, float* __restrict__ C,
          int K, int lda, int ldb, int ldc,
          long sA, long sB, long sC, int bdivB,
          float alpha, const float* __restrict__ bias,
          const float* __restrict__ scalev, float beta)
{
    __shared__ uint32_t As[2 * TAW];   // 20480 B
    __shared__ uint32_t Bs[2 * TAW];   // 20480 B

    const int bz = blockIdx.z;
    A += (long)bz * sA;
    B += (long)(bz / bdivB) * sB;
    C += (long)bz * sC;

    const int bm = blockIdx.y * 128;
    const int bn = blockIdx.x * 128;
    const int tid  = threadIdx.x;
    const int wid  = tid >> 5;
    const int lane = tid & 31;
    const int g4   = lane >> 2;
    const int t4   = lane & 3;
    const int wm   = (wid & 3) * 32;
    const int wn   = (wid >> 2) * 64;

    const int r_  = tid >> 1;           // 0..127 (row of A/B tile)
    const int ks_ = (tid & 1) * 16;     // float offset within BK=32

    float4 ra[4], rb[4];

    auto ldg = [&](int k0) {
        const float* pa = A + (long)(bm + r_) * lda + k0 + ks_;
        const float* pb = B + (long)(bn + r_) * ldb + k0 + ks_;
#pragma unroll
        for (int i = 0; i < 4; i++) {
            ra[i] = *(const float4*)(pa + i * 4);
            rb[i] = *(const float4*)(pb + i * 4);
        }
    };
    auto sts = [&](int buf) {
        uint32_t* da = As + buf * TAW + r_ * TASTR + (tid & 1) * 8;
        uint32_t* db = Bs + buf * TAW + r_ * TASTR + (tid & 1) * 8;
#pragma unroll
        for (int i = 0; i < 4; i++) {
            da[2 * i]     = packbf(ra[i].x, ra[i].y);
            da[2 * i + 1] = packbf(ra[i].z, ra[i].w);
            db[2 * i]     = packbf(rb[i].x, rb[i].y);
            db[2 * i + 1] = packbf(rb[i].z, rb[i].w);
        }
    };

    float acc[2][8][4];
#pragma unroll
    for (int i = 0; i < 2; i++)
#pragma unroll
        for (int j = 0; j < 8; j++)
#pragma unroll
            for (int l = 0; l < 4; l++) acc[i][j][l] = 0.0f;

    ldg(0);
    const int nsteps = K / 32;
    for (int ks = 0; ks < nsteps; ks++) {
        sts(ks & 1);
        __syncthreads();
        if (ks + 1 < nsteps) ldg((ks + 1) * 32);

        const uint32_t* Ab = As + (ks & 1) * TAW;
        const uint32_t* Bb = Bs + (ks & 1) * TAW;

#pragma unroll
        for (int kh = 0; kh < 2; kh++) {
            const int kw = kh * 8;
            uint32_t af[2][4];
#pragma unroll
            for (int mf = 0; mf < 2; mf++) {
                const int r0 = wm + mf * 16 + g4;
                af[mf][0] = Ab[(r0    ) * TASTR + kw + t4    ];
                af[mf][1] = Ab[(r0 + 8) * TASTR + kw + t4    ];
                af[mf][2] = Ab[(r0    ) * TASTR + kw + t4 + 4];
                af[mf][3] = Ab[(r0 + 8) * TASTR + kw + t4 + 4];
            }
#pragma unroll
            for (int nf = 0; nf < 8; nf++) {
                const int n0 = wn + nf * 8 + g4;
                uint32_t b0 = Bb[n0 * TASTR + kw + t4];
                uint32_t b1 = Bb[n0 * TASTR + kw + t4 + 4];
                mma_bf16(acc[0][nf], af[0][0], af[0][1], af[0][2], af[0][3], b0, b1);
                mma_bf16(acc[1][nf], af[1][0], af[1][1], af[1][2], af[1][3], b0, b1);
            }
        }
        __syncthreads();   // reads done before next sts overwrites the other buffer's turn
    }

    // ---- epilogue ----
#pragma unroll
    for (int mf = 0; mf < 2; mf++) {
#pragma unroll
        for (int nf = 0; nf < 8; nf++) {
            const int row = bm + wm + mf * 16 + g4;
            const int col = bn + wn + nf * 8 + t4 * 2;
            float v0 = acc[mf][nf][0] * alpha;
            float v1 = acc[mf][nf][1] * alpha;
            float v2 = acc[mf][nf][2] * alpha;
            float v3 = acc[mf][nf][3] * alpha;
            if (bias) {
                float b0 = bias[col], b1 = bias[col + 1];
                v0 += b0; v1 += b1; v2 += b0; v3 += b1;
            }
            if (scalev) {
                float s0 = scalev[col] * beta, s1 = scalev[col + 1] * beta;
                v0 *= s0; v1 *= s1; v2 *= s0; v3 *= s1;
            }
            *(float2*)(C + (long)row * ldc + col)       = make_float2(v0, v1);
            *(float2*)(C + (long)(row + 8) * ldc + col) = make_float2(v2, v3);
        }
    }
}

// ================= TF32 NN GEMM (verbatim R2 logic, BN=64) =================
// C = alpha * A[M,K] @ B[K,N], used for attn = P @ V. Single-buffered, proven.
__global__ void __launch_bounds__(256)
tf32_nn_k(const float* __restrict__ A, const float* __restrict__ B, float* __restrict__ C,
          int K, int lda, int ldb, int ldc,
          long sA, long sB, long sC, int bdivB, float alpha)
{
    __shared__ uint32_t As[128 * 36];
    __shared__ uint32_t Bs[32 * 72];

    const int bz = blockIdx.z;
    A += (long)bz * sA;
    B += (long)(bz / bdivB) * sB;
    C += (long)bz * sC;

    const int bm = blockIdx.y * 128;
    const int bn = blockIdx.x * 64;
    const int tid  = threadIdx.x;
    const int wid  = tid >> 5;
    const int lane = tid & 31;
    const int g4   = lane >> 2;
    const int t4   = lane & 3;
    const int wm = (wid & 3) * 32;
    const int wn = (wid >> 2) * 32;

    const int a_row = tid >> 1;
    const int a_ks  = (tid & 1) * 16;
    const int c_row = tid >> 3;          // 0..31
    const int c_ns  = (tid & 7) * 8;     // 0..56

    float4 ra[4], rb[2];

    auto loadA = [&](int k0) {
        const float* p = A + (long)(bm + a_row) * lda + k0 + a_ks;
#pragma unroll
        for (int i = 0; i < 4; i++) ra[i] = *(const float4*)(p + i * 4);
    };
    auto loadB = [&](int k0) {
        const float* p = B + (long)(k0 + c_row) * ldb + bn + c_ns;
#pragma unroll
        for (int i = 0; i < 2; i++) rb[i] = *(const float4*)(p + i * 4);
    };
    auto storeS = [&]() {
        uint32_t* d = As + a_row * 36 + a_ks;
#pragma unroll
        for (int i = 0; i < 4; i++) {
            d[i * 4 + 0] = f2tf(ra[i].x); d[i * 4 + 1] = f2tf(ra[i].y);
            d[i * 4 + 2] = f2tf(ra[i].z); d[i * 4 + 3] = f2tf(ra[i].w);
        }
        uint32_t* e = Bs + c_row * 72 + c_ns;
#pragma unroll
        for (int i = 0; i < 2; i++) {
            e[i * 4 + 0] = f2tf(rb[i].x); e[i * 4 + 1] = f2tf(rb[i].y);
            e[i * 4 + 2] = f2tf(rb[i].z); e[i * 4 + 3] = f2tf(rb[i].w);
        }
    };

    float acc[2][4][4];
#pragma unroll
    for (int i = 0; i < 2; i++)
#pragma unroll
        for (int j = 0; j < 4; j++)
#pragma unroll
            for (int l = 0; l < 4; l++) acc[i][j][l] = 0.0f;

    loadA(0); loadB(0);

    for (int k0 = 0; k0 < K; k0 += 32) {
        __syncthreads();
        storeS();
        __syncthreads();
        if (k0 + 32 < K) { loadA(k0 + 32); loadB(k0 + 32); }

#pragma unroll
        for (int k8 = 0; k8 < 4; k8++) {
            const int kk = k8 * 8;
            uint32_t af[2][4];
#pragma unroll
            for (int mf = 0; mf < 2; mf++) {
                const int r0 = wm + mf * 16 + g4;
                af[mf][0] = As[(r0    ) * 36 + kk + t4    ];
                af[mf][1] = As[(r0 + 8) * 36 + kk + t4    ];
                af[mf][2] = As[(r0    ) * 36 + kk + t4 + 4];
                af[mf][3] = As[(r0 + 8) * 36 + kk + t4 + 4];
            }
#pragma unroll
            for (int nf = 0; nf < 4; nf++) {
                uint32_t b0 = Bs[(kk + t4    ) * 72 + wn + nf * 8 + g4];
                uint32_t b1 = Bs[(kk + t4 + 4) * 72 + wn + nf * 8 + g4];
                mma_tf32(acc[0][nf], af[0][0], af[0][1], af[0][2], af[0][3], b0, b1);
                mma_tf32(acc[1][nf], af[1][0], af[1][1], af[1][2], af[1][3], b0, b1);
            }
        }
    }

#pragma unroll
    for (int mf = 0; mf < 2; mf++) {
#pragma unroll
        for (int nf = 0; nf < 4; nf++) {
            const int row = bm + wm + mf * 16 + g4;
            const int col = bn + wn + nf * 8 + t4 * 2;
            float v0 = acc[mf][nf][0] * alpha;
            float v1 = acc[mf][nf][1] * alpha;
            float v2 = acc[mf][nf][2] * alpha;
            float v3 = acc[mf][nf][3] * alpha;
            *(float2*)(C + (long)row * ldc + col)       = make_float2(v0, v1);
            *(float2*)(C + (long)(row + 8) * ldc + col) = make_float2(v2, v3);
        }
    }
}

// ---------------- embedding gather ----------------
__global__ void embed_k(const int* __restrict__ x, const float* __restrict__ emb,
                        float* __restrict__ h)
{
    int s = blockIdx.x;
    int t = threadIdx.x;
    const float4* src = (const float4*)(emb + (long)x[s] * DM);
    ((float4*)(h + (long)s * DM))[t] = src[t];
}

// ---------------- RoPE + cosine-norm, Q (folds eff^2 into Q) ----------------
__global__ void rope_norm_q_k(float* __restrict__ q, const float* __restrict__ sqk, int ld)
{
    int s = blockIdx.x, hh = blockIdx.y;
    int j = threadIdx.x;
    float* base = q + (long)s * ld + hh * HDIM;
    float x1 = base[j], x2 = base[j + 32];

    float inv = powf(10000.0f, -(float)j / 32.0f);
    float ang = (float)s * inv;
    float sn, cs; sincosf(ang, &sn, &cs);
    float o1 = x1 * cs - x2 * sn;
    float o2 = x2 * cs + x1 * sn;

    float ss = o1 * o1 + o2 * o2;
#pragma unroll
    for (int off = 16; off > 0; off >>= 1)
        ss += __shfl_xor_sync(0xffffffffu, ss, off);
    float n = fmaxf(sqrtf(ss), 1e-6f);

    float e1 = sqk[hh * HDIM + j]      * RTD;
    float e2 = sqk[hh * HDIM + j + 32] * RTD;
    base[j]      = (o1 / n) * e1 * e1;
    base[j + 32] = (o2 / n) * e2 * e2;
}

// ---------------- RoPE + cosine-norm, K ----------------
__global__ void rope_norm_kk(float* __restrict__ k, int ld)
{
    int s = blockIdx.x, g = blockIdx.y;
    int j = threadIdx.x;
    float* base = k + (long)s * ld + g * HDIM;
    float x1 = base[j], x2 = base[j + 32];

    float inv = powf(10000.0f, -(float)j / 32.0f);
    float ang = (float)s * inv;
    float sn, cs; sincosf(ang, &sn, &cs);
    float o1 = x1 * cs - x2 * sn;
    float o2 = x2 * cs + x1 * sn;

    float ss = o1 * o1 + o2 * o2;
#pragma unroll
    for (int off = 16; off > 0; off >>= 1)
        ss += __shfl_xor_sync(0xffffffffu, ss, off);
    float n = fmaxf(sqrtf(ss), 1e-6f);

    base[j]      = o1 / n;
    base[j + 32] = o2 / n;
}

// ---------------- causal row softmax ----------------
__global__ void softmax_causal_k(float* __restrict__ scores)
{
    int qr = blockIdx.x, hh = blockIdx.y;
    float* row = scores + (long)hh * SQ * SQ + (long)qr * SQ;
    int valid = qr + 1;
    int t = threadIdx.x;
    __shared__ float red[256];

    float m = -1e30f;
    for (int j = t; j < valid; j += 256) m = fmaxf(m, row[j]);
    red[t] = m; __syncthreads();
    for (int o = 128; o > 0; o >>= 1) { if (t < o) red[t] = fmaxf(red[t], red[t + o]); __syncthreads(); }
    m = red[0]; __syncthreads();

    float sum = 0.0f;
    for (int j = t; j < valid; j += 256) { float e = __expf(row[j] - m); row[j] = e; sum += e; }
    red[t] = sum; __syncthreads();
    for (int o = 128; o > 0; o >>= 1) { if (t < o) red[t] += red[t + o]; __syncthreads(); }
    float invs = 1.0f / red[0];

    for (int j = t; j < valid; j += 256) row[j] *= invs;
    for (int j = valid + t; j < SQ; j += 256) row[j] = 0.0f;
}

// ---------------- residual lerp + cosine norm ----------------
__global__ void resid_norm_k(float* __restrict__ h, const float* __restrict__ t,
                             const float* __restrict__ eig)
{
    int row = blockIdx.x;
    int tid = threadIdx.x;
    __shared__ float red[256];

    float4 tv = ((const float4*)(t + (long)row * DM))[tid];
    float ss = tv.x * tv.x + tv.y * tv.y + tv.z * tv.z + tv.w * tv.w;
    red[tid] = ss; __syncthreads();
    for (int o = 128; o > 0; o >>= 1) { if (tid < o) red[tid] += red[tid + o]; __syncthreads(); }
    float nt = fmaxf(sqrtf(red[0]), 1e-6f);
    __syncthreads();

    float4 hv = ((const float4*)(h + (long)row * DM))[tid];
    float4 ev = ((const float4*)eig)[tid];
    float4 r;
    r.x = hv.x + ev.x * RTDM * (tv.x / nt - hv.x);
    r.y = hv.y + ev.y * RTDM * (tv.y / nt - hv.y);
    r.z = hv.z + ev.z * RTDM * (tv.z / nt - hv.z);
    r.w = hv.w + ev.w * RTDM * (tv.w / nt - hv.w);

    float ss2 = r.x * r.x + r.y * r.y + r.z * r.z + r.w * r.w;
    red[tid] = ss2; __syncthreads();
    for (int o = 128; o > 0; o >>= 1) { if (tid < o) red[tid] += red[tid + o]; __syncthreads(); }
    float nr = fmaxf(sqrtf(red[0]), 1e-6f);

    r.x /= nr; r.y /= nr; r.z /= nr; r.w /= nr;
    ((float4*)(h + (long)row * DM))[tid] = r;
}

// ---------------- SwiGLU ----------------
__global__ void swiglu_k(float* __restrict__ u, const float* __restrict__ g,
                         const float* __restrict__ su, const float* __restrict__ sv)
{
    long idx = (long)blockIdx.x * 256 + threadIdx.x;
    int f = (int)(idx & (DFF - 1));
    float uv = u[idx] * su[f];
    float gv = g[idx] * sv[f] * RTDM;
    u[idx] = uv * gv / (1.0f + __expf(-gv));
}

// ---------------- final row softmax ----------------
__global__ void softmax_full_k(float* __restrict__ out)
{
    int row = blockIdx.x;
    float* p = out + (long)row * NV;
    int t = threadIdx.x;
    __shared__ float red[256];

    float m = -1e30f;
    for (int j = t; j < NV; j += 256) m = fmaxf(m, p[j]);
    red[t] = m; __syncthreads();
    for (int o = 128; o > 0; o >>= 1) { if (t < o) red[t] = fmaxf(red[t], red[t + o]); __syncthreads(); }
    m = red[0]; __syncthreads();

    float sum = 0.0f;
    for (int j = t; j < NV; j += 256) { float e = __expf(p[j] - m); p[j] = e; sum += e; }
    red[t] = sum; __syncthreads();
    for (int o = 128; o > 0; o >>= 1) { if (t < o) red[t] += red[t + o]; __syncthreads(); }
    float invs = 1.0f / red[0];

    for (int j = t; j < NV; j += 256) p[j] *= invs;
}

// ---------------- host-side launchers ----------------
static void gemm_tb(const float* A, const float* B, float* C,
                    int M, int N, int K, int lda, int ldb, int ldc,
                    long sA, long sB, long sC, int bdivB, int batch,
                    float alpha, const float* bias, const float* scalev, float beta)
{
    dim3 grid(N / 128, M / 128, batch);
    bf16_tb_k<<<grid, 256>>>(A, B, C, K, lda, ldb, ldc,
                             sA, sB, sC, bdivB, alpha, bias, scalev, beta);
}

extern "C" void kernel_launch(void* const* d_in, const int* in_sizes, int n_in,
                              void* d_out, int out_size)
{
    const int*   x      = (const int*)  d_in[0];
    const float* emb    = (const float*)d_in[1];
    const float* qw     = (const float*)d_in[2];
    const float* qb     = (const float*)d_in[3];
    const float* kw     = (const float*)d_in[4];
    const float* kb     = (const float*)d_in[5];
    const float* vw     = (const float*)d_in[6];
    const float* vb     = (const float*)d_in[7];
    const float* sqk    = (const float*)d_in[8];
    const float* ow     = (const float*)d_in[9];
    const float* ob     = (const float*)d_in[10];
    const float* w_in   = (const float*)d_in[11];
    const float* b_in   = (const float*)d_in[12];
    const float* w_gate = (const float*)d_in[13];
    const float* b_gate = (const float*)d_in[14];
    const float* w_out  = (const float*)d_in[15];
    const float* b_out  = (const float*)d_in[16];
    const float* s_u    = (const float*)d_in[17];
    const float* s_v    = (const float*)d_in[18];
    const float* eig_a  = (const float*)d_in[19];
    const float* eig_m  = (const float*)d_in[20];
    const float* out_w  = (const float*)d_in[21];
    const float* out_b  = (const float*)d_in[22];
    const float* s_z    = (const float*)d_in[23];
    float* out = (float*)d_out;

    float *h, *qkv, *sc, *attn, *t, *u, *g, *qkvw, *qkvb;
    cudaGetSymbolAddress((void**)&h,    g_h);
    cudaGetSymbolAddress((void**)&qkv,  g_qkv);
    cudaGetSymbolAddress((void**)&sc,   g_sc);
    cudaGetSymbolAddress((void**)&attn, g_attn);
    cudaGetSymbolAddress((void**)&t,    g_t);
    cudaGetSymbolAddress((void**)&u,    g_u);
    cudaGetSymbolAddress((void**)&g,    g_g);
    cudaGetSymbolAddress((void**)&qkvw, g_qkvw);
    cudaGetSymbolAddress((void**)&qkvb, g_qkvb);

    // assemble fused QKV weights/biases (graph-capturable D2D copies)
    for (int i = 0; i < NL; i++) {
        float* w = qkvw + (long)i * QKV * DM;
        cudaMemcpyAsync(w,                     qw + (long)i * DM * DM,  sizeof(float) * DM * DM,  cudaMemcpyDeviceToDevice);
        cudaMemcpyAsync(w + (long)DM * DM,     kw + (long)i * GHD * DM, sizeof(float) * GHD * DM, cudaMemcpyDeviceToDevice);
        cudaMemcpyAsync(w + (long)(DM + GHD) * DM, vw + (long)i * GHD * DM, sizeof(float) * GHD * DM, cudaMemcpyDeviceToDevice);
        float* b = qkvb + i * QKV;
        cudaMemcpyAsync(b,            qb + (long)i * DM,  sizeof(float) * DM,  cudaMemcpyDeviceToDevice);
        cudaMemcpyAsync(b + DM,       kb + (long)i * GHD, sizeof(float) * GHD, cudaMemcpyDeviceToDevice);
        cudaMemcpyAsync(b + DM + GHD, vb + (long)i * GHD, sizeof(float) * GHD, cudaMemcpyDeviceToDevice);
    }

    embed_k<<<SQ, 256>>>(x, emb, h);

    for (int i = 0; i < NL; i++) {
        // fused QKV projection: qkv[s, 0:1024]=Q, [1024:1280]=K, [1280:1536]=V
        gemm_tb(h, qkvw + (long)i * QKV * DM, qkv, SQ, QKV, DM, DM, DM, QKV,
                0, 0, 0, 1, 1, 1.0f, qkvb + i * QKV, nullptr, 0.0f);

        rope_norm_q_k<<<dim3(SQ, NH), 32>>>(qkv, sqk + (long)i * NH * HDIM, QKV);
        rope_norm_kk <<<dim3(SQ, NG), 32>>>(qkv + DM, QKV);

        // scores[z] = (Q_z @ K_{z/4}^T) * rtd
        gemm_tb(qkv, qkv + DM, sc, SQ, SQ, HDIM, QKV, QKV, SQ,
                HDIM, HDIM, (long)SQ * SQ, HPG, NH,
                RTD, nullptr, nullptr, 0.0f);

        softmax_causal_k<<<dim3(SQ, NH), 256>>>(sc);

        // attn[z] = P_z @ V_{z/4}   (NN, N=64, TF32)
        {
            dim3 grid(1, SQ / 128, NH);
            tf32_nn_k<<<grid, 256>>>(sc, qkv + DM + GHD, attn, SQ, SQ, QKV, DM,
                                     (long)SQ * SQ, HDIM, HDIM, HPG, 1.0f);
        }

        gemm_tb(attn, ow + (long)i * DM * DM, t, SQ, DM, DM, DM, DM, DM,
                0, 0, 0, 1, 1, 1.0f, ob + (long)i * DM, nullptr, 0.0f);
        resid_norm_k<<<SQ, 256>>>(h, t, eig_a + (long)i * DM);

        gemm_tb(h, w_in   + (long)i * DFF * DM, u, SQ, DFF, DM, DM, DM, DFF,
                0, 0, 0, 1, 1, 1.0f, b_in   + (long)i * DFF, nullptr, 0.0f);
        gemm_tb(h, w_gate + (long)i * DFF * DM, g, SQ, DFF, DM, DM, DM, DFF,
                0, 0, 0, 1, 1, 1.0f, b_gate + (long)i * DFF, nullptr, 0.0f);
        swiglu_k<<<(SQ * DFF) / 256, 256>>>(u, g, s_u + (long)i * DFF, s_v + (long)i * DFF);
        gemm_tb(u, w_out + (long)i * DM * DFF, t, SQ, DM, DFF, DFF, DFF, DM,
                0, 0, 0, 1, 1, 1.0f, b_out + (long)i * DM, nullptr, 0.0f);
        resid_norm_k<<<SQ, 256>>>(h, t, eig_m + (long)i * DM);
    }

    gemm_tb(h, out_w, out, SQ, NV, DM, DM, DM, NV,
            0, 0, 0, 1, 1, 1.0f, out_b, s_z, RTDM);
    softmax_full_k<<<SQ, 256>>>(out);
}

// round 5
// speedup vs baseline: 2.4989x; 1.0923x over previous
#include <cuda_runtime.h>
#include <cuda_bf16.h>
#include <math.h>
#include <stdint.h>

// ---------------- problem dims (fixed) ----------------
#define SQ   1024
#define DM   1024
#define NH   16
#define NG   4
#define HDIM 64
#define HPG  4
#define GHD  256
#define NL   4
#define DFF  4096
#define NV   32000
#define QKV  1536      // DM + 2*GHD
#define RTD  8.0f
#define RTDM 32.0f

// ---------------- device scratch ----------------
__device__ float g_h   [SQ * DM];
__device__ float g_qkv [SQ * QKV];
__device__ float g_attn[SQ * DM];
__device__ float g_t   [SQ * DM];
__device__ float g_u   [SQ * DFF];
__device__ float g_g   [SQ * DFF];
__device__ float g_qkvw[(long)NL * QKV * DM];
__device__ float g_qkvb[NL * QKV];

__device__ __forceinline__ uint32_t packbf(float x, float y) {
    __nv_bfloat162 t = __floats2bfloat162_rn(x, y);
    return *reinterpret_cast<uint32_t*>(&t);
}
// residual of (x,y) after bf16 rounding given the rounded pair
__device__ __forceinline__ uint32_t packbf_res(float x, float y, uint32_t hi) {
    __nv_bfloat162 h = *reinterpret_cast<__nv_bfloat162*>(&hi);
    return packbf(x - __bfloat162float(h.x), y - __bfloat162float(h.y));
}

__device__ __forceinline__ void mma_bf16(float c[4], uint32_t a0, uint32_t a1,
                                         uint32_t a2, uint32_t a3,
                                         uint32_t b0, uint32_t b1) {
    asm volatile(
        "mma.sync.aligned.m16n8k16.row.col.f32.bf16.bf16.f32 "
        "{%0,%1,%2,%3}, {%4,%5,%6,%7}, {%8,%9}, {%0,%1,%2,%3};"
        : "+f"(c[0]), "+f"(c[1]), "+f"(c[2]), "+f"(c[3])
        : "r"(a0), "r"(a1), "r"(a2), "r"(a3), "r"(b0), "r"(b1));
}

// ================= bf16 TB GEMM (proven R4) =================
#define TASTR 20
#define TAW   (128 * TASTR)

__global__ void __launch_bounds__(256)
bf16_tb_k(const float* __restrict__ A, const float* __restrict__ B, float* __restrict__ C,
          int K, int lda, int ldb, int ldc,
          long sA, long sB, long sC, int bdivB,
          float alpha, const float* __restrict__ bias,
          const float* __restrict__ scalev, float beta)
{
    __shared__ uint32_t As[2 * TAW];
    __shared__ uint32_t Bs[2 * TAW];

    const int bz = blockIdx.z;
    A += (long)bz * sA;
    B += (long)(bz / bdivB) * sB;
    C += (long)bz * sC;

    const int bm = blockIdx.y * 128;
    const int bn = blockIdx.x * 128;
    const int tid  = threadIdx.x;
    const int wid  = tid >> 5;
    const int lane = tid & 31;
    const int g4   = lane >> 2;
    const int t4   = lane & 3;
    const int wm   = (wid & 3) * 32;
    const int wn   = (wid >> 2) * 64;

    const int r_  = tid >> 1;
    const int ks_ = (tid & 1) * 16;

    float4 ra[4], rb[4];

    auto ldg = [&](int k0) {
        const float* pa = A + (long)(bm + r_) * lda + k0 + ks_;
        const float* pb = B + (long)(bn + r_) * ldb + k0 + ks_;
#pragma unroll
        for (int i = 0; i < 4; i++) {
            ra[i] = *(const float4*)(pa + i * 4);
            rb[i] = *(const float4*)(pb + i * 4);
        }
    };
    auto sts = [&](int buf) {
        uint32_t* da = As + buf * TAW + r_ * TASTR + (tid & 1) * 8;
        uint32_t* db = Bs + buf * TAW + r_ * TASTR + (tid & 1) * 8;
#pragma unroll
        for (int i = 0; i < 4; i++) {
            da[2 * i]     = packbf(ra[i].x, ra[i].y);
            da[2 * i + 1] = packbf(ra[i].z, ra[i].w);
            db[2 * i]     = packbf(rb[i].x, rb[i].y);
            db[2 * i + 1] = packbf(rb[i].z, rb[i].w);
        }
    };

    float acc[2][8][4];
#pragma unroll
    for (int i = 0; i < 2; i++)
#pragma unroll
        for (int j = 0; j < 8; j++)
#pragma unroll
            for (int l = 0; l < 4; l++) acc[i][j][l] = 0.0f;

    ldg(0);
    const int nsteps = K / 32;
    for (int ks = 0; ks < nsteps; ks++) {
        sts(ks & 1);
        __syncthreads();
        if (ks + 1 < nsteps) ldg((ks + 1) * 32);

        const uint32_t* Ab = As + (ks & 1) * TAW;
        const uint32_t* Bb = Bs + (ks & 1) * TAW;

#pragma unroll
        for (int kh = 0; kh < 2; kh++) {
            const int kw = kh * 8;
            uint32_t af[2][4];
#pragma unroll
            for (int mf = 0; mf < 2; mf++) {
                const int r0 = wm + mf * 16 + g4;
                af[mf][0] = Ab[(r0    ) * TASTR + kw + t4    ];
                af[mf][1] = Ab[(r0 + 8) * TASTR + kw + t4    ];
                af[mf][2] = Ab[(r0    ) * TASTR + kw + t4 + 4];
                af[mf][3] = Ab[(r0 + 8) * TASTR + kw + t4 + 4];
            }
#pragma unroll
            for (int nf = 0; nf < 8; nf++) {
                const int n0 = wn + nf * 8 + g4;
                uint32_t b0 = Bb[n0 * TASTR + kw + t4];
                uint32_t b1 = Bb[n0 * TASTR + kw + t4 + 4];
                mma_bf16(acc[0][nf], af[0][0], af[0][1], af[0][2], af[0][3], b0, b1);
                mma_bf16(acc[1][nf], af[1][0], af[1][1], af[1][2], af[1][3], b0, b1);
            }
        }
        __syncthreads();
    }

#pragma unroll
    for (int mf = 0; mf < 2; mf++) {
#pragma unroll
        for (int nf = 0; nf < 8; nf++) {
            const int row = bm + wm + mf * 16 + g4;
            const int col = bn + wn + nf * 8 + t4 * 2;
            float v0 = acc[mf][nf][0] * alpha;
            float v1 = acc[mf][nf][1] * alpha;
            float v2 = acc[mf][nf][2] * alpha;
            float v3 = acc[mf][nf][3] * alpha;
            if (bias) {
                float b0 = bias[col], b1 = bias[col + 1];
                v0 += b0; v1 += b1; v2 += b0; v3 += b1;
            }
            if (scalev) {
                float s0 = scalev[col] * beta, s1 = scalev[col + 1] * beta;
                v0 *= s0; v1 *= s1; v2 *= s0; v3 *= s1;
            }
            *(float2*)(C + (long)row * ldc + col)       = make_float2(v0, v1);
            *(float2*)(C + (long)(row + 8) * ldc + col) = make_float2(v2, v3);
        }
    }
}

// ================= fused flash attention =================
// grid (qb=SQ/128, head=NH), 256 threads = 8 warps, warp owns 16 q-rows.
// Q has eff^2 * RTD folded in (rope kernel); K unit-norm. Online softmax in regs.
// P@V via bf16 hi/lo split (2 MMAs) for fp32-grade accuracy.
__global__ void __launch_bounds__(256)
flash_attn_k(const float* __restrict__ qkv, float* __restrict__ attn)
{
    __shared__ uint32_t Qs[128 * 36];   // [qrow][32 bf16x2 words + pad]
    __shared__ uint32_t Ks[64 * 36];    // [kvrow][d words]
    __shared__ uint32_t Vs[64 * 36];    // [d][kv words] (transposed)

    const int qb = blockIdx.x;
    const int hh = blockIdx.y;
    const int gg = hh >> 2;
    const int qcol = hh * HDIM;
    const int kcol = DM + gg * HDIM;
    const int vcol = DM + GHD + gg * HDIM;

    const int tid  = threadIdx.x;
    const int wid  = tid >> 5;
    const int lane = tid & 31;
    const int g4   = lane >> 2;
    const int t4   = lane & 3;
    const int wm   = wid * 16;
    const int s0q  = qb * 128;

    // load Q tile once (128 x 64)
    {
        int r = tid >> 1, half = tid & 1;
        const float* src = qkv + (long)(s0q + r) * QKV + qcol + half * 32;
        uint32_t* dst = Qs + r * 36 + half * 16;
#pragma unroll
        for (int i = 0; i < 8; i++) {
            float4 v = *(const float4*)(src + i * 4);
            dst[2 * i]     = packbf(v.x, v.y);
            dst[2 * i + 1] = packbf(v.z, v.w);
        }
    }

    float O[8][4];
#pragma unroll
    for (int j = 0; j < 8; j++)
#pragma unroll
        for (int l = 0; l < 4; l++) O[j][l] = 0.0f;
    float m0 = -1e30f, m1 = -1e30f, l0 = 0.0f, l1 = 0.0f;

    const int nblk = 2 * qb + 2;
    for (int jb = 0; jb < nblk; jb++) {
        const int s0 = jb * 64;
        __syncthreads();   // prev block's smem reads done (also covers Qs on jb=0)

        // K block (64 x 64)
        {
            int r = tid >> 2, q4 = tid & 3;
            const float* src = qkv + (long)(s0 + r) * QKV + kcol + q4 * 16;
            uint32_t* dst = Ks + r * 36 + q4 * 8;
#pragma unroll
            for (int i = 0; i < 4; i++) {
                float4 v = *(const float4*)(src + i * 4);
                dst[2 * i]     = packbf(v.x, v.y);
                dst[2 * i + 1] = packbf(v.z, v.w);
            }
        }
        // V block transposed (d major)
        {
            int d = tid & 63, sb = tid >> 6;
#pragma unroll
            for (int i = 0; i < 8; i++) {
                int sp = sb * 8 + i;
                const float* p0 = qkv + (long)(s0 + 2 * sp) * QKV + vcol + d;
                Vs[d * 36 + sp] = packbf(p0[0], p0[QKV]);
            }
        }
        __syncthreads();

        // S = Q @ K^T  (16 x 64 per warp)
        float S[8][4];
#pragma unroll
        for (int j = 0; j < 8; j++)
#pragma unroll
            for (int l = 0; l < 4; l++) S[j][l] = 0.0f;

#pragma unroll
        for (int kc = 0; kc < 4; kc++) {
            uint32_t a0 = Qs[(wm + g4    ) * 36 + kc * 8 + t4    ];
            uint32_t a1 = Qs[(wm + g4 + 8) * 36 + kc * 8 + t4    ];
            uint32_t a2 = Qs[(wm + g4    ) * 36 + kc * 8 + t4 + 4];
            uint32_t a3 = Qs[(wm + g4 + 8) * 36 + kc * 8 + t4 + 4];
#pragma unroll
            for (int nf = 0; nf < 8; nf++) {
                uint32_t b0 = Ks[(nf * 8 + g4) * 36 + kc * 8 + t4    ];
                uint32_t b1 = Ks[(nf * 8 + g4) * 36 + kc * 8 + t4 + 4];
                mma_bf16(S[nf], a0, a1, a2, a3, b0, b1);
            }
        }

        // causal mask (only blocks touching the diagonal)
        if (jb >= 2 * qb) {
            const int r0 = s0q + wm + g4, r1 = r0 + 8;
#pragma unroll
            for (int nf = 0; nf < 8; nf++) {
                const int c = s0 + nf * 8 + t4 * 2;
                if (c     > r0) S[nf][0] = -1e30f;
                if (c + 1 > r0) S[nf][1] = -1e30f;
                if (c     > r1) S[nf][2] = -1e30f;
                if (c + 1 > r1) S[nf][3] = -1e30f;
            }
        }

        // online softmax (rows live in lane quads: shfl over t4)
        float bm0 = -1e30f, bm1 = -1e30f;
#pragma unroll
        for (int nf = 0; nf < 8; nf++) {
            bm0 = fmaxf(bm0, fmaxf(S[nf][0], S[nf][1]));
            bm1 = fmaxf(bm1, fmaxf(S[nf][2], S[nf][3]));
        }
        bm0 = fmaxf(bm0, __shfl_xor_sync(0xffffffffu, bm0, 1));
        bm0 = fmaxf(bm0, __shfl_xor_sync(0xffffffffu, bm0, 2));
        bm1 = fmaxf(bm1, __shfl_xor_sync(0xffffffffu, bm1, 1));
        bm1 = fmaxf(bm1, __shfl_xor_sync(0xffffffffu, bm1, 2));

        float nm0 = fmaxf(m0, bm0), nm1 = fmaxf(m1, bm1);
        float sc0 = __expf(m0 - nm0), sc1 = __expf(m1 - nm1);
        m0 = nm0; m1 = nm1;

        float ps0 = 0.0f, ps1 = 0.0f;
#pragma unroll
        for (int nf = 0; nf < 8; nf++) {
            S[nf][0] = __expf(S[nf][0] - m0);
            S[nf][1] = __expf(S[nf][1] - m0);
            S[nf][2] = __expf(S[nf][2] - m1);
            S[nf][3] = __expf(S[nf][3] - m1);
            ps0 += S[nf][0] + S[nf][1];
            ps1 += S[nf][2] + S[nf][3];
        }
        ps0 += __shfl_xor_sync(0xffffffffu, ps0, 1);
        ps0 += __shfl_xor_sync(0xffffffffu, ps0, 2);
        ps1 += __shfl_xor_sync(0xffffffffu, ps1, 1);
        ps1 += __shfl_xor_sync(0xffffffffu, ps1, 2);
        l0 = l0 * sc0 + ps0;
        l1 = l1 * sc1 + ps1;

#pragma unroll
        for (int nf = 0; nf < 8; nf++) {
            O[nf][0] *= sc0; O[nf][1] *= sc0;
            O[nf][2] *= sc1; O[nf][3] *= sc1;
        }

        // O += P @ V   (bf16 hi/lo split)
#pragma unroll
        for (int kc = 0; kc < 4; kc++) {
            uint32_t ah0 = packbf(S[2*kc  ][0], S[2*kc  ][1]);
            uint32_t ah1 = packbf(S[2*kc  ][2], S[2*kc  ][3]);
            uint32_t ah2 = packbf(S[2*kc+1][0], S[2*kc+1][1]);
            uint32_t ah3 = packbf(S[2*kc+1][2], S[2*kc+1][3]);
            uint32_t al0 = packbf_res(S[2*kc  ][0], S[2*kc  ][1], ah0);
            uint32_t al1 = packbf_res(S[2*kc  ][2], S[2*kc  ][3], ah1);
            uint32_t al2 = packbf_res(S[2*kc+1][0], S[2*kc+1][1], ah2);
            uint32_t al3 = packbf_res(S[2*kc+1][2], S[2*kc+1][3], ah3);
#pragma unroll
            for (int nf = 0; nf < 8; nf++) {
                uint32_t b0 = Vs[(nf * 8 + g4) * 36 + kc * 8 + t4    ];
                uint32_t b1 = Vs[(nf * 8 + g4) * 36 + kc * 8 + t4 + 4];
                mma_bf16(O[nf], ah0, ah1, ah2, ah3, b0, b1);
                mma_bf16(O[nf], al0, al1, al2, al3, b0, b1);
            }
        }
    }

    // normalize + store
    const float inv0 = 1.0f / l0, inv1 = 1.0f / l1;
    const int row0 = s0q + wm + g4;
#pragma unroll
    for (int nf = 0; nf < 8; nf++) {
        const int col = hh * HDIM + nf * 8 + t4 * 2;
        *(float2*)(attn + (long)row0 * DM + col) =
            make_float2(O[nf][0] * inv0, O[nf][1] * inv0);
        *(float2*)(attn + (long)(row0 + 8) * DM + col) =
            make_float2(O[nf][2] * inv1, O[nf][3] * inv1);
    }
}

// ---------------- embedding gather ----------------
__global__ void embed_k(const int* __restrict__ x, const float* __restrict__ emb,
                        float* __restrict__ h)
{
    int s = blockIdx.x;
    int t = threadIdx.x;
    const float4* src = (const float4*)(emb + (long)x[s] * DM);
    ((float4*)(h + (long)s * DM))[t] = src[t];
}

// ---------------- RoPE + cosine-norm, Q (folds eff^2 * RTD into Q) ----------------
__global__ void rope_norm_q_k(float* __restrict__ q, const float* __restrict__ sqk, int ld)
{
    int s = blockIdx.x, hh = blockIdx.y;
    int j = threadIdx.x;
    float* base = q + (long)s * ld + hh * HDIM;
    float x1 = base[j], x2 = base[j + 32];

    float inv = powf(10000.0f, -(float)j / 32.0f);
    float ang = (float)s * inv;
    float sn, cs; sincosf(ang, &sn, &cs);
    float o1 = x1 * cs - x2 * sn;
    float o2 = x2 * cs + x1 * sn;

    float ss = o1 * o1 + o2 * o2;
#pragma unroll
    for (int off = 16; off > 0; off >>= 1)
        ss += __shfl_xor_sync(0xffffffffu, ss, off);
    float n = fmaxf(sqrtf(ss), 1e-6f);

    float e1 = sqk[hh * HDIM + j]      * RTD;
    float e2 = sqk[hh * HDIM + j + 32] * RTD;
    base[j]      = (o1 / n) * e1 * e1 * RTD;   // eff^2 and score scale folded in
    base[j + 32] = (o2 / n) * e2 * e2 * RTD;
}

// ---------------- RoPE + cosine-norm, K ----------------
__global__ void rope_norm_kk(float* __restrict__ k, int ld)
{
    int s = blockIdx.x, g = blockIdx.y;
    int j = threadIdx.x;
    float* base = k + (long)s * ld + g * HDIM;
    float x1 = base[j], x2 = base[j + 32];

    float inv = powf(10000.0f, -(float)j / 32.0f);
    float ang = (float)s * inv;
    float sn, cs; sincosf(ang, &sn, &cs);
    float o1 = x1 * cs - x2 * sn;
    float o2 = x2 * cs + x1 * sn;

    float ss = o1 * o1 + o2 * o2;
#pragma unroll
    for (int off = 16; off > 0; off >>= 1)
        ss += __shfl_xor_sync(0xffffffffu, ss, off);
    float n = fmaxf(sqrtf(ss), 1e-6f);

    base[j]      = o1 / n;
    base[j + 32] = o2 / n;
}

// ---------------- residual lerp + cosine norm ----------------
__global__ void resid_norm_k(float* __restrict__ h, const float* __restrict__ t,
                             const float* __restrict__ eig)
{
    int row = blockIdx.x;
    int tid = threadIdx.x;
    __shared__ float red[256];

    float4 tv = ((const float4*)(t + (long)row * DM))[tid];
    float ss = tv.x * tv.x + tv.y * tv.y + tv.z * tv.z + tv.w * tv.w;
    red[tid] = ss; __syncthreads();
    for (int o = 128; o > 0; o >>= 1) { if (tid < o) red[tid] += red[tid + o]; __syncthreads(); }
    float nt = fmaxf(sqrtf(red[0]), 1e-6f);
    __syncthreads();

    float4 hv = ((const float4*)(h + (long)row * DM))[tid];
    float4 ev = ((const float4*)eig)[tid];
    float4 r;
    r.x = hv.x + ev.x * RTDM * (tv.x / nt - hv.x);
    r.y = hv.y + ev.y * RTDM * (tv.y / nt - hv.y);
    r.z = hv.z + ev.z * RTDM * (tv.z / nt - hv.z);
    r.w = hv.w + ev.w * RTDM * (tv.w / nt - hv.w);

    float ss2 = r.x * r.x + r.y * r.y + r.z * r.z + r.w * r.w;
    red[tid] = ss2; __syncthreads();
    for (int o = 128; o > 0; o >>= 1) { if (tid < o) red[tid] += red[tid + o]; __syncthreads(); }
    float nr = fmaxf(sqrtf(red[0]), 1e-6f);

    r.x /= nr; r.y /= nr; r.z /= nr; r.w /= nr;
    ((float4*)(h + (long)row * DM))[tid] = r;
}

// ---------------- SwiGLU ----------------
__global__ void swiglu_k(float* __restrict__ u, const float* __restrict__ g,
                         const float* __restrict__ su, const float* __restrict__ sv)
{
    long idx = (long)blockIdx.x * 256 + threadIdx.x;
    int f = (int)(idx & (DFF - 1));
    float uv = u[idx] * su[f];
    float gv = g[idx] * sv[f] * RTDM;
    u[idx] = uv * gv / (1.0f + __expf(-gv));
}

// ---------------- final row softmax ----------------
__global__ void softmax_full_k(float* __restrict__ out)
{
    int row = blockIdx.x;
    float* p = out + (long)row * NV;
    int t = threadIdx.x;
    __shared__ float red[256];

    float m = -1e30f;
    for (int j = t; j < NV; j += 256) m = fmaxf(m, p[j]);
    red[t] = m; __syncthreads();
    for (int o = 128; o > 0; o >>= 1) { if (t < o) red[t] = fmaxf(red[t], red[t + o]); __syncthreads(); }
    m = red[0]; __syncthreads();

    float sum = 0.0f;
    for (int j = t; j < NV; j += 256) { float e = __expf(p[j] - m); p[j] = e; sum += e; }
    red[t] = sum; __syncthreads();
    for (int o = 128; o > 0; o >>= 1) { if (t < o) red[t] += red[t + o]; __syncthreads(); }
    float invs = 1.0f / red[0];

    for (int j = t; j < NV; j += 256) p[j] *= invs;
}

// ---------------- host-side launcher ----------------
static void gemm_tb(const float* A, const float* B, float* C,
                    int M, int N, int K, int lda, int ldb, int ldc,
                    float alpha, const float* bias, const float* scalev, float beta)
{
    dim3 grid(N / 128, M / 128, 1);
    bf16_tb_k<<<grid, 256>>>(A, B, C, K, lda, ldb, ldc,
                             0, 0, 0, 1, alpha, bias, scalev, beta);
}

extern "C" void kernel_launch(void* const* d_in, const int* in_sizes, int n_in,
                              void* d_out, int out_size)
{
    const int*   x      = (const int*)  d_in[0];
    const float* emb    = (const float*)d_in[1];
    const float* qw     = (const float*)d_in[2];
    const float* qb     = (const float*)d_in[3];
    const float* kw     = (const float*)d_in[4];
    const float* kb     = (const float*)d_in[5];
    const float* vw     = (const float*)d_in[6];
    const float* vb     = (const float*)d_in[7];
    const float* sqk    = (const float*)d_in[8];
    const float* ow     = (const float*)d_in[9];
    const float* ob     = (const float*)d_in[10];
    const float* w_in   = (const float*)d_in[11];
    const float* b_in   = (const float*)d_in[12];
    const float* w_gate = (const float*)d_in[13];
    const float* b_gate = (const float*)d_in[14];
    const float* w_out  = (const float*)d_in[15];
    const float* b_out  = (const float*)d_in[16];
    const float* s_u    = (const float*)d_in[17];
    const float* s_v    = (const float*)d_in[18];
    const float* eig_a  = (const float*)d_in[19];
    const float* eig_m  = (const float*)d_in[20];
    const float* out_w  = (const float*)d_in[21];
    const float* out_b  = (const float*)d_in[22];
    const float* s_z    = (const float*)d_in[23];
    float* out = (float*)d_out;

    float *h, *qkv, *attn, *t, *u, *g, *qkvw, *qkvb;
    cudaGetSymbolAddress((void**)&h,    g_h);
    cudaGetSymbolAddress((void**)&qkv,  g_qkv);
    cudaGetSymbolAddress((void**)&attn, g_attn);
    cudaGetSymbolAddress((void**)&t,    g_t);
    cudaGetSymbolAddress((void**)&u,    g_u);
    cudaGetSymbolAddress((void**)&g,    g_g);
    cudaGetSymbolAddress((void**)&qkvw, g_qkvw);
    cudaGetSymbolAddress((void**)&qkvb, g_qkvb);

    // assemble fused QKV weights/biases (graph-capturable D2D copies)
    for (int i = 0; i < NL; i++) {
        float* w = qkvw + (long)i * QKV * DM;
        cudaMemcpyAsync(w,                         qw + (long)i * DM * DM,  sizeof(float) * DM * DM,  cudaMemcpyDeviceToDevice);
        cudaMemcpyAsync(w + (long)DM * DM,         kw + (long)i * GHD * DM, sizeof(float) * GHD * DM, cudaMemcpyDeviceToDevice);
        cudaMemcpyAsync(w + (long)(DM + GHD) * DM, vw + (long)i * GHD * DM, sizeof(float) * GHD * DM, cudaMemcpyDeviceToDevice);
        float* b = qkvb + i * QKV;
        cudaMemcpyAsync(b,            qb + (long)i * DM,  sizeof(float) * DM,  cudaMemcpyDeviceToDevice);
        cudaMemcpyAsync(b + DM,       kb + (long)i * GHD, sizeof(float) * GHD, cudaMemcpyDeviceToDevice);
        cudaMemcpyAsync(b + DM + GHD, vb + (long)i * GHD, sizeof(float) * GHD, cudaMemcpyDeviceToDevice);
    }

    embed_k<<<SQ, 256>>>(x, emb, h);

    for (int i = 0; i < NL; i++) {
        // fused QKV projection
        gemm_tb(h, qkvw + (long)i * QKV * DM, qkv, SQ, QKV, DM, DM, DM, QKV,
                1.0f, qkvb + i * QKV, nullptr, 0.0f);

        rope_norm_q_k<<<dim3(SQ, NH), 32>>>(qkv, sqk + (long)i * NH * HDIM, QKV);
        rope_norm_kk <<<dim3(SQ, NG), 32>>>(qkv + DM, QKV);

        // fused attention (scores + causal softmax + P@V)
        flash_attn_k<<<dim3(SQ / 128, NH), 256>>>(qkv, attn);

        gemm_tb(attn, ow + (long)i * DM * DM, t, SQ, DM, DM, DM, DM, DM,
                1.0f, ob + (long)i * DM, nullptr, 0.0f);
        resid_norm_k<<<SQ, 256>>>(h, t, eig_a + (long)i * DM);

        gemm_tb(h, w_in   + (long)i * DFF * DM, u, SQ, DFF, DM, DM, DM, DFF,
                1.0f, b_in   + (long)i * DFF, nullptr, 0.0f);
        gemm_tb(h, w_gate + (long)i * DFF * DM, g, SQ, DFF, DM, DM, DM, DFF,
                1.0f, b_gate + (long)i * DFF, nullptr, 0.0f);
        swiglu_k<<<(SQ * DFF) / 256, 256>>>(u, g, s_u + (long)i * DFF, s_v + (long)i * DFF);
        gemm_tb(u, w_out + (long)i * DM * DFF, t, SQ, DM, DFF, DFF, DFF, DM,
                1.0f, b_out + (long)i * DM, nullptr, 0.0f);
        resid_norm_k<<<SQ, 256>>>(h, t, eig_m + (long)i * DM);
    }

    gemm_tb(h, out_w, out, SQ, NV, DM, DM, DM, NV,
            1.0f, out_b, s_z, RTDM);
    softmax_full_k<<<SQ, 256>>>(out);
}

// round 6
// speedup vs baseline: 3.4883x; 1.3959x over previous
#include <cuda_runtime.h>
#include <cuda_bf16.h>
#include <math.h>
#include <stdint.h>

// ---------------- problem dims (fixed) ----------------
#define SQ   1024
#define DM   1024
#define NH   16
#define NG   4
#define HDIM 64
#define HPG  4
#define GHD  256
#define NL   4
#define DFF  4096
#define NV   32000
#define QKV  1536      // DM + 2*GHD
#define RTD  8.0f
#define RTDM 32.0f

// ---------------- device scratch ----------------
__device__ float g_h   [SQ * DM];
__device__ float g_qkv [SQ * QKV];
__device__ float g_t   [SQ * DM];
__device__ float g_ug  [SQ * 2 * DFF];
__device__ float g_qkvb[NL * QKV];
__device__ float g_biog[NL * 2 * DFF];

__device__ __align__(16) __nv_bfloat16 g_hb   [SQ * DM];
__device__ __align__(16) __nv_bfloat16 g_attnb[SQ * DM];
__device__ __align__(16) __nv_bfloat16 g_ub   [SQ * DFF];
__device__ __align__(16) __nv_bfloat16 g_qkvw [(long)NL * QKV * DM];
__device__ __align__(16) __nv_bfloat16 g_wiog [(long)NL * 2 * DFF * DM];
__device__ __align__(16) __nv_bfloat16 g_wout [(long)NL * DM * DFF];
__device__ __align__(16) __nv_bfloat16 g_ow   [(long)NL * DM * DM];
__device__ __align__(16) __nv_bfloat16 g_outw [(long)NV * DM];

__device__ __forceinline__ uint32_t packbf(float x, float y) {
    __nv_bfloat162 t = __floats2bfloat162_rn(x, y);
    return *reinterpret_cast<uint32_t*>(&t);
}
__device__ __forceinline__ uint32_t packbf_res(float x, float y, uint32_t hi) {
    __nv_bfloat162 h = *reinterpret_cast<__nv_bfloat162*>(&hi);
    return packbf(x - __bfloat162float(h.x), y - __bfloat162float(h.y));
}

__device__ __forceinline__ void mma_bf16(float c[4], uint32_t a0, uint32_t a1,
                                         uint32_t a2, uint32_t a3,
                                         uint32_t b0, uint32_t b1) {
    asm volatile(
        "mma.sync.aligned.m16n8k16.row.col.f32.bf16.bf16.f32 "
        "{%0,%1,%2,%3}, {%4,%5,%6,%7}, {%8,%9}, {%0,%1,%2,%3};"
        : "+f"(c[0]), "+f"(c[1]), "+f"(c[2]), "+f"(c[3])
        : "r"(a0), "r"(a1), "r"(a2), "r"(a3), "r"(b0), "r"(b1));
}

// ---------------- fp32 -> bf16 conversion (vectorized x4) ----------------
__global__ void cvt_k(__nv_bfloat16* __restrict__ dst, const float* __restrict__ src, int n4)
{
    int i = blockIdx.x * 256 + threadIdx.x;
    if (i < n4) {
        float4 v = ((const float4*)src)[i];
        uint32_t* d = (uint32_t*)dst + i * 2;
        d[0] = packbf(v.x, v.y);
        d[1] = packbf(v.z, v.w);
    }
}
static void cvt(__nv_bfloat16* dst, const float* src, long n) {
    int n4 = (int)(n / 4);
    cvt_k<<<(n4 + 255) / 256, 256>>>(dst, src, n4);
}

// ================= pure-bf16 TB GEMM =================
// C[M,N] = epi(alpha * A[M,K] @ B[N,K]^T); A,B bf16 row-major; tiles 128x128x32.
// 256 threads, 8 warps (4m x 2n), warp tile 32x64. Double-buffered smem.
#define TASTR 20
#define TAW   (128 * TASTR)

__global__ void __launch_bounds__(256)
bf16_gemm_k(const __nv_bfloat16* __restrict__ A, const __nv_bfloat16* __restrict__ B,
            float* __restrict__ C, int K, int lda, int ldb, int ldc,
            float alpha, const float* __restrict__ bias,
            const float* __restrict__ scalev, float beta)
{
    __shared__ __align__(16) uint32_t As[2 * TAW];
    __shared__ __align__(16) uint32_t Bs[2 * TAW];

    const int bm = blockIdx.y * 128;
    const int bn = blockIdx.x * 128;
    const int tid  = threadIdx.x;
    const int wid  = tid >> 5;
    const int lane = tid & 31;
    const int g4   = lane >> 2;
    const int t4   = lane & 3;
    const int wm   = (wid & 3) * 32;
    const int wn   = (wid >> 2) * 64;

    const int r_ = tid >> 1;        // 0..127 (tile row)
    const int h_ = tid & 1;         // which 16-element half of the 32-k row

    uint4 ra[2], rb[2];

    auto ldg = [&](int k0) {
        const __nv_bfloat16* pa = A + (long)(bm + r_) * lda + k0 + h_ * 16;
        const __nv_bfloat16* pb = B + (long)(bn + r_) * ldb + k0 + h_ * 16;
        ra[0] = *(const uint4*)pa; ra[1] = *(const uint4*)(pa + 8);
        rb[0] = *(const uint4*)pb; rb[1] = *(const uint4*)(pb + 8);
    };
    auto sts = [&](int buf) {
        uint32_t* da = As + buf * TAW + r_ * TASTR + h_ * 8;
        uint32_t* db = Bs + buf * TAW + r_ * TASTR + h_ * 8;
        *(uint4*)da       = ra[0];
        *(uint4*)(da + 4) = ra[1];
        *(uint4*)db       = rb[0];
        *(uint4*)(db + 4) = rb[1];
    };

    float acc[2][8][4];
#pragma unroll
    for (int i = 0; i < 2; i++)
#pragma unroll
        for (int j = 0; j < 8; j++)
#pragma unroll
            for (int l = 0; l < 4; l++) acc[i][j][l] = 0.0f;

    ldg(0);
    const int nsteps = K / 32;
    for (int ks = 0; ks < nsteps; ks++) {
        sts(ks & 1);
        __syncthreads();
        if (ks + 1 < nsteps) ldg((ks + 1) * 32);

        const uint32_t* Ab = As + (ks & 1) * TAW;
        const uint32_t* Bb = Bs + (ks & 1) * TAW;

#pragma unroll
        for (int kh = 0; kh < 2; kh++) {
            const int kw = kh * 8;
            uint32_t af[2][4];
#pragma unroll
            for (int mf = 0; mf < 2; mf++) {
                const int r0 = wm + mf * 16 + g4;
                af[mf][0] = Ab[(r0    ) * TASTR + kw + t4    ];
                af[mf][1] = Ab[(r0 + 8) * TASTR + kw + t4    ];
                af[mf][2] = Ab[(r0    ) * TASTR + kw + t4 + 4];
                af[mf][3] = Ab[(r0 + 8) * TASTR + kw + t4 + 4];
            }
#pragma unroll
            for (int nf = 0; nf < 8; nf++) {
                const int n0 = wn + nf * 8 + g4;
                uint32_t b0 = Bb[n0 * TASTR + kw + t4];
                uint32_t b1 = Bb[n0 * TASTR + kw + t4 + 4];
                mma_bf16(acc[0][nf], af[0][0], af[0][1], af[0][2], af[0][3], b0, b1);
                mma_bf16(acc[1][nf], af[1][0], af[1][1], af[1][2], af[1][3], b0, b1);
            }
        }
        __syncthreads();
    }

#pragma unroll
    for (int mf = 0; mf < 2; mf++) {
#pragma unroll
        for (int nf = 0; nf < 8; nf++) {
            const int row = bm + wm + mf * 16 + g4;
            const int col = bn + wn + nf * 8 + t4 * 2;
            float v0 = acc[mf][nf][0] * alpha;
            float v1 = acc[mf][nf][1] * alpha;
            float v2 = acc[mf][nf][2] * alpha;
            float v3 = acc[mf][nf][3] * alpha;
            if (bias) {
                float b0 = bias[col], b1 = bias[col + 1];
                v0 += b0; v1 += b1; v2 += b0; v3 += b1;
            }
            if (scalev) {
                float s0 = scalev[col] * beta, s1 = scalev[col + 1] * beta;
                v0 *= s0; v1 *= s1; v2 *= s0; v3 *= s1;
            }
            *(float2*)(C + (long)row * ldc + col)       = make_float2(v0, v1);
            *(float2*)(C + (long)(row + 8) * ldc + col) = make_float2(v2, v3);
        }
    }
}

// ================= fused flash attention (bf16 output) =================
__global__ void __launch_bounds__(256)
flash_attn_k(const float* __restrict__ qkv, __nv_bfloat16* __restrict__ attnb)
{
    __shared__ uint32_t Qs[128 * 36];
    __shared__ uint32_t Ks[64 * 36];
    __shared__ uint32_t Vs[64 * 36];

    const int qb = blockIdx.x;
    const int hh = blockIdx.y;
    const int gg = hh >> 2;
    const int qcol = hh * HDIM;
    const int kcol = DM + gg * HDIM;
    const int vcol = DM + GHD + gg * HDIM;

    const int tid  = threadIdx.x;
    const int wid  = tid >> 5;
    const int lane = tid & 31;
    const int g4   = lane >> 2;
    const int t4   = lane & 3;
    const int wm   = wid * 16;
    const int s0q  = qb * 128;

    {
        int r = tid >> 1, half = tid & 1;
        const float* src = qkv + (long)(s0q + r) * QKV + qcol + half * 32;
        uint32_t* dst = Qs + r * 36 + half * 16;
#pragma unroll
        for (int i = 0; i < 8; i++) {
            float4 v = *(const float4*)(src + i * 4);
            dst[2 * i]     = packbf(v.x, v.y);
            dst[2 * i + 1] = packbf(v.z, v.w);
        }
    }

    float O[8][4];
#pragma unroll
    for (int j = 0; j < 8; j++)
#pragma unroll
        for (int l = 0; l < 4; l++) O[j][l] = 0.0f;
    float m0 = -1e30f, m1 = -1e30f, l0 = 0.0f, l1 = 0.0f;

    const int nblk = 2 * qb + 2;
    for (int jb = 0; jb < nblk; jb++) {
        const int s0 = jb * 64;
        __syncthreads();

        {
            int r = tid >> 2, q4 = tid & 3;
            const float* src = qkv + (long)(s0 + r) * QKV + kcol + q4 * 16;
            uint32_t* dst = Ks + r * 36 + q4 * 8;
#pragma unroll
            for (int i = 0; i < 4; i++) {
                float4 v = *(const float4*)(src + i * 4);
                dst[2 * i]     = packbf(v.x, v.y);
                dst[2 * i + 1] = packbf(v.z, v.w);
            }
        }
        {
            int d = tid & 63, sb = tid >> 6;
#pragma unroll
            for (int i = 0; i < 8; i++) {
                int sp = sb * 8 + i;
                const float* p0 = qkv + (long)(s0 + 2 * sp) * QKV + vcol + d;
                Vs[d * 36 + sp] = packbf(p0[0], p0[QKV]);
            }
        }
        __syncthreads();

        float S[8][4];
#pragma unroll
        for (int j = 0; j < 8; j++)
#pragma unroll
            for (int l = 0; l < 4; l++) S[j][l] = 0.0f;

#pragma unroll
        for (int kc = 0; kc < 4; kc++) {
            uint32_t a0 = Qs[(wm + g4    ) * 36 + kc * 8 + t4    ];
            uint32_t a1 = Qs[(wm + g4 + 8) * 36 + kc * 8 + t4    ];
            uint32_t a2 = Qs[(wm + g4    ) * 36 + kc * 8 + t4 + 4];
            uint32_t a3 = Qs[(wm + g4 + 8) * 36 + kc * 8 + t4 + 4];
#pragma unroll
            for (int nf = 0; nf < 8; nf++) {
                uint32_t b0 = Ks[(nf * 8 + g4) * 36 + kc * 8 + t4    ];
                uint32_t b1 = Ks[(nf * 8 + g4) * 36 + kc * 8 + t4 + 4];
                mma_bf16(S[nf], a0, a1, a2, a3, b0, b1);
            }
        }

        if (jb >= 2 * qb) {
            const int r0 = s0q + wm + g4, r1 = r0 + 8;
#pragma unroll
            for (int nf = 0; nf < 8; nf++) {
                const int c = s0 + nf * 8 + t4 * 2;
                if (c     > r0) S[nf][0] = -1e30f;
                if (c + 1 > r0) S[nf][1] = -1e30f;
                if (c     > r1) S[nf][2] = -1e30f;
                if (c + 1 > r1) S[nf][3] = -1e30f;
            }
        }

        float bm0 = -1e30f, bm1 = -1e30f;
#pragma unroll
        for (int nf = 0; nf < 8; nf++) {
            bm0 = fmaxf(bm0, fmaxf(S[nf][0], S[nf][1]));
            bm1 = fmaxf(bm1, fmaxf(S[nf][2], S[nf][3]));
        }
        bm0 = fmaxf(bm0, __shfl_xor_sync(0xffffffffu, bm0, 1));
        bm0 = fmaxf(bm0, __shfl_xor_sync(0xffffffffu, bm0, 2));
        bm1 = fmaxf(bm1, __shfl_xor_sync(0xffffffffu, bm1, 1));
        bm1 = fmaxf(bm1, __shfl_xor_sync(0xffffffffu, bm1, 2));

        float nm0 = fmaxf(m0, bm0), nm1 = fmaxf(m1, bm1);
        float sc0 = __expf(m0 - nm0), sc1 = __expf(m1 - nm1);
        m0 = nm0; m1 = nm1;

        float ps0 = 0.0f, ps1 = 0.0f;
#pragma unroll
        for (int nf = 0; nf < 8; nf++) {
            S[nf][0] = __expf(S[nf][0] - m0);
            S[nf][1] = __expf(S[nf][1] - m0);
            S[nf][2] = __expf(S[nf][2] - m1);
            S[nf][3] = __expf(S[nf][3] - m1);
            ps0 += S[nf][0] + S[nf][1];
            ps1 += S[nf][2] + S[nf][3];
        }
        ps0 += __shfl_xor_sync(0xffffffffu, ps0, 1);
        ps0 += __shfl_xor_sync(0xffffffffu, ps0, 2);
        ps1 += __shfl_xor_sync(0xffffffffu, ps1, 1);
        ps1 += __shfl_xor_sync(0xffffffffu, ps1, 2);
        l0 = l0 * sc0 + ps0;
        l1 = l1 * sc1 + ps1;

#pragma unroll
        for (int nf = 0; nf < 8; nf++) {
            O[nf][0] *= sc0; O[nf][1] *= sc0;
            O[nf][2] *= sc1; O[nf][3] *= sc1;
        }

#pragma unroll
        for (int kc = 0; kc < 4; kc++) {
            uint32_t ah0 = packbf(S[2*kc  ][0], S[2*kc  ][1]);
            uint32_t ah1 = packbf(S[2*kc  ][2], S[2*kc  ][3]);
            uint32_t ah2 = packbf(S[2*kc+1][0], S[2*kc+1][1]);
            uint32_t ah3 = packbf(S[2*kc+1][2], S[2*kc+1][3]);
            uint32_t al0 = packbf_res(S[2*kc  ][0], S[2*kc  ][1], ah0);
            uint32_t al1 = packbf_res(S[2*kc  ][2], S[2*kc  ][3], ah1);
            uint32_t al2 = packbf_res(S[2*kc+1][0], S[2*kc+1][1], ah2);
            uint32_t al3 = packbf_res(S[2*kc+1][2], S[2*kc+1][3], ah3);
#pragma unroll
            for (int nf = 0; nf < 8; nf++) {
                uint32_t b0 = Vs[(nf * 8 + g4) * 36 + kc * 8 + t4    ];
                uint32_t b1 = Vs[(nf * 8 + g4) * 36 + kc * 8 + t4 + 4];
                mma_bf16(O[nf], ah0, ah1, ah2, ah3, b0, b1);
                mma_bf16(O[nf], al0, al1, al2, al3, b0, b1);
            }
        }
    }

    const float inv0 = 1.0f / l0, inv1 = 1.0f / l1;
    const int row0 = s0q + wm + g4;
#pragma unroll
    for (int nf = 0; nf < 8; nf++) {
        const int col = hh * HDIM + nf * 8 + t4 * 2;
        *(uint32_t*)(attnb + (long)row0 * DM + col) =
            packbf(O[nf][0] * inv0, O[nf][1] * inv0);
        *(uint32_t*)(attnb + (long)(row0 + 8) * DM + col) =
            packbf(O[nf][2] * inv1, O[nf][3] * inv1);
    }
}

// ---------------- embedding gather (fp32 + bf16 copies) ----------------
__global__ void embed_k(const int* __restrict__ x, const float* __restrict__ emb,
                        float* __restrict__ h, __nv_bfloat16* __restrict__ hb)
{
    int s = blockIdx.x;
    int t = threadIdx.x;
    float4 v = ((const float4*)(emb + (long)x[s] * DM))[t];
    ((float4*)(h + (long)s * DM))[t] = v;
    uint32_t* d = (uint32_t*)(hb + (long)s * DM) + t * 2;
    d[0] = packbf(v.x, v.y);
    d[1] = packbf(v.z, v.w);
}

// ---------------- RoPE + cosine-norm, Q (folds eff^2 * RTD into Q) ----------------
__global__ void rope_norm_q_k(float* __restrict__ q, const float* __restrict__ sqk, int ld)
{
    int s = blockIdx.x, hh = blockIdx.y;
    int j = threadIdx.x;
    float* base = q + (long)s * ld + hh * HDIM;
    float x1 = base[j], x2 = base[j + 32];

    float inv = powf(10000.0f, -(float)j / 32.0f);
    float ang = (float)s * inv;
    float sn, cs; sincosf(ang, &sn, &cs);
    float o1 = x1 * cs - x2 * sn;
    float o2 = x2 * cs + x1 * sn;

    float ss = o1 * o1 + o2 * o2;
#pragma unroll
    for (int off = 16; off > 0; off >>= 1)
        ss += __shfl_xor_sync(0xffffffffu, ss, off);
    float n = fmaxf(sqrtf(ss), 1e-6f);

    float e1 = sqk[hh * HDIM + j]      * RTD;
    float e2 = sqk[hh * HDIM + j + 32] * RTD;
    base[j]      = (o1 / n) * e1 * e1 * RTD;
    base[j + 32] = (o2 / n) * e2 * e2 * RTD;
}

// ---------------- RoPE + cosine-norm, K ----------------
__global__ void rope_norm_kk(float* __restrict__ k, int ld)
{
    int s = blockIdx.x, g = blockIdx.y;
    int j = threadIdx.x;
    float* base = k + (long)s * ld + g * HDIM;
    float x1 = base[j], x2 = base[j + 32];

    float inv = powf(10000.0f, -(float)j / 32.0f);
    float ang = (float)s * inv;
    float sn, cs; sincosf(ang, &sn, &cs);
    float o1 = x1 * cs - x2 * sn;
    float o2 = x2 * cs + x1 * sn;

    float ss = o1 * o1 + o2 * o2;
#pragma unroll
    for (int off = 16; off > 0; off >>= 1)
        ss += __shfl_xor_sync(0xffffffffu, ss, off);
    float n = fmaxf(sqrtf(ss), 1e-6f);

    base[j]      = o1 / n;
    base[j + 32] = o2 / n;
}

// ---------------- residual lerp + cosine norm (writes fp32 + bf16) ----------------
__global__ void resid_norm_k(float* __restrict__ h, __nv_bfloat16* __restrict__ hb,
                             const float* __restrict__ t, const float* __restrict__ eig)
{
    int row = blockIdx.x;
    int tid = threadIdx.x;
    __shared__ float red[256];

    float4 tv = ((const float4*)(t + (long)row * DM))[tid];
    float ss = tv.x * tv.x + tv.y * tv.y + tv.z * tv.z + tv.w * tv.w;
    red[tid] = ss; __syncthreads();
    for (int o = 128; o > 0; o >>= 1) { if (tid < o) red[tid] += red[tid + o]; __syncthreads(); }
    float nt = fmaxf(sqrtf(red[0]), 1e-6f);
    __syncthreads();

    float4 hv = ((const float4*)(h + (long)row * DM))[tid];
    float4 ev = ((const float4*)eig)[tid];
    float4 r;
    r.x = hv.x + ev.x * RTDM * (tv.x / nt - hv.x);
    r.y = hv.y + ev.y * RTDM * (tv.y / nt - hv.y);
    r.z = hv.z + ev.z * RTDM * (tv.z / nt - hv.z);
    r.w = hv.w + ev.w * RTDM * (tv.w / nt - hv.w);

    float ss2 = r.x * r.x + r.y * r.y + r.z * r.z + r.w * r.w;
    red[tid] = ss2; __syncthreads();
    for (int o = 128; o > 0; o >>= 1) { if (tid < o) red[tid] += red[tid + o]; __syncthreads(); }
    float nr = fmaxf(sqrtf(red[0]), 1e-6f);

    r.x /= nr; r.y /= nr; r.z /= nr; r.w /= nr;
    ((float4*)(h + (long)row * DM))[tid] = r;
    uint32_t* d = (uint32_t*)(hb + (long)row * DM) + tid * 2;
    d[0] = packbf(r.x, r.y);
    d[1] = packbf(r.z, r.w);
}

// ---------------- SwiGLU on fused [u;g] buffer -> bf16 ----------------
__global__ void swiglu_k(const float* __restrict__ ug, __nv_bfloat16* __restrict__ ub,
                         const float* __restrict__ su, const float* __restrict__ sv)
{
    long idx = (long)blockIdx.x * 256 + threadIdx.x;
    int s = (int)(idx >> 12);
    int f = (int)(idx & (DFF - 1));
    float uv = ug[(long)s * 2 * DFF + f]       * su[f];
    float gv = ug[(long)s * 2 * DFF + DFF + f] * sv[f] * RTDM;
    ub[idx] = __float2bfloat16(uv * gv / (1.0f + __expf(-gv)));
}

// ---------------- final row softmax ----------------
__global__ void softmax_full_k(float* __restrict__ out)
{
    int row = blockIdx.x;
    float* p = out + (long)row * NV;
    int t = threadIdx.x;
    __shared__ float red[256];

    float m = -1e30f;
    for (int j = t; j < NV; j += 256) m = fmaxf(m, p[j]);
    red[t] = m; __syncthreads();
    for (int o = 128; o > 0; o >>= 1) { if (t < o) red[t] = fmaxf(red[t], red[t + o]); __syncthreads(); }
    m = red[0]; __syncthreads();

    float sum = 0.0f;
    for (int j = t; j < NV; j += 256) { float e = __expf(p[j] - m); p[j] = e; sum += e; }
    red[t] = sum; __syncthreads();
    for (int o = 128; o > 0; o >>= 1) { if (t < o) red[t] += red[t + o]; __syncthreads(); }
    float invs = 1.0f / red[0];

    for (int j = t; j < NV; j += 256) p[j] *= invs;
}

// ---------------- host-side launcher ----------------
static void gemm(const __nv_bfloat16* A, const __nv_bfloat16* B, float* C,
                 int M, int N, int K, int lda, int ldb, int ldc,
                 float alpha, const float* bias, const float* scalev, float beta)
{
    dim3 grid(N / 128, M / 128);
    bf16_gemm_k<<<grid, 256>>>(A, B, C, K, lda, ldb, ldc, alpha, bias, scalev, beta);
}

extern "C" void kernel_launch(void* const* d_in, const int* in_sizes, int n_in,
                              void* d_out, int out_size)
{
    const int*   x      = (const int*)  d_in[0];
    const float* emb    = (const float*)d_in[1];
    const float* qw     = (const float*)d_in[2];
    const float* qb     = (const float*)d_in[3];
    const float* kw     = (const float*)d_in[4];
    const float* kb     = (const float*)d_in[5];
    const float* vw     = (const float*)d_in[6];
    const float* vb     = (const float*)d_in[7];
    const float* sqk    = (const float*)d_in[8];
    const float* ow     = (const float*)d_in[9];
    const float* ob     = (const float*)d_in[10];
    const float* w_in   = (const float*)d_in[11];
    const float* b_in   = (const float*)d_in[12];
    const float* w_gate = (const float*)d_in[13];
    const float* b_gate = (const float*)d_in[14];
    const float* w_out  = (const float*)d_in[15];
    const float* b_out  = (const float*)d_in[16];
    const float* s_u    = (const float*)d_in[17];
    const float* s_v    = (const float*)d_in[18];
    const float* eig_a  = (const float*)d_in[19];
    const float* eig_m  = (const float*)d_in[20];
    const float* out_w  = (const float*)d_in[21];
    const float* out_b  = (const float*)d_in[22];
    const float* s_z    = (const float*)d_in[23];
    float* out = (float*)d_out;

    float *h, *qkv, *t, *ug, *qkvb, *biog;
    __nv_bfloat16 *hb, *attnb, *ub, *qkvw, *wiog, *wout, *owb, *outwb;
    cudaGetSymbolAddress((void**)&h,     g_h);
    cudaGetSymbolAddress((void**)&qkv,   g_qkv);
    cudaGetSymbolAddress((void**)&t,     g_t);
    cudaGetSymbolAddress((void**)&ug,    g_ug);
    cudaGetSymbolAddress((void**)&qkvb,  g_qkvb);
    cudaGetSymbolAddress((void**)&biog,  g_biog);
    cudaGetSymbolAddress((void**)&hb,    g_hb);
    cudaGetSymbolAddress((void**)&attnb, g_attnb);
    cudaGetSymbolAddress((void**)&ub,    g_ub);
    cudaGetSymbolAddress((void**)&qkvw,  g_qkvw);
    cudaGetSymbolAddress((void**)&wiog,  g_wiog);
    cudaGetSymbolAddress((void**)&wout,  g_wout);
    cudaGetSymbolAddress((void**)&owb,   g_ow);
    cudaGetSymbolAddress((void**)&outwb, g_outw);

    // ---- one-time weight conversion to bf16 (fused layouts) ----
    for (int i = 0; i < NL; i++) {
        __nv_bfloat16* w = qkvw + (long)i * QKV * DM;
        cvt(w,                         qw + (long)i * DM * DM,  (long)DM * DM);
        cvt(w + (long)DM * DM,         kw + (long)i * GHD * DM, (long)GHD * DM);
        cvt(w + (long)(DM + GHD) * DM, vw + (long)i * GHD * DM, (long)GHD * DM);

        __nv_bfloat16* wg = wiog + (long)i * 2 * DFF * DM;
        cvt(wg,                  w_in   + (long)i * DFF * DM, (long)DFF * DM);
        cvt(wg + (long)DFF * DM, w_gate + (long)i * DFF * DM, (long)DFF * DM);

        float* b = qkvb + i * QKV;
        cudaMemcpyAsync(b,            qb + (long)i * DM,  sizeof(float) * DM,  cudaMemcpyDeviceToDevice);
        cudaMemcpyAsync(b + DM,       kb + (long)i * GHD, sizeof(float) * GHD, cudaMemcpyDeviceToDevice);
        cudaMemcpyAsync(b + DM + GHD, vb + (long)i * GHD, sizeof(float) * GHD, cudaMemcpyDeviceToDevice);
        cudaMemcpyAsync(biog + (long)i * 2 * DFF,       b_in   + (long)i * DFF, sizeof(float) * DFF, cudaMemcpyDeviceToDevice);
        cudaMemcpyAsync(biog + (long)i * 2 * DFF + DFF, b_gate + (long)i * DFF, sizeof(float) * DFF, cudaMemcpyDeviceToDevice);
    }
    cvt(owb,   ow,    (long)NL * DM * DM);
    cvt(wout,  w_out, (long)NL * DM * DFF);
    cvt(outwb, out_w, (long)NV * DM);

    embed_k<<<SQ, 256>>>(x, emb, h, hb);

    for (int i = 0; i < NL; i++) {
        // fused QKV projection
        gemm(hb, qkvw + (long)i * QKV * DM, qkv, SQ, QKV, DM, DM, DM, QKV,
             1.0f, qkvb + i * QKV, nullptr, 0.0f);

        rope_norm_q_k<<<dim3(SQ, NH), 32>>>(qkv, sqk + (long)i * NH * HDIM, QKV);
        rope_norm_kk <<<dim3(SQ, NG), 32>>>(qkv + DM, QKV);

        flash_attn_k<<<dim3(SQ / 128, NH), 256>>>(qkv, attnb);

        gemm(attnb, owb + (long)i * DM * DM, t, SQ, DM, DM, DM, DM, DM,
             1.0f, ob + (long)i * DM, nullptr, 0.0f);
        resid_norm_k<<<SQ, 256>>>(h, hb, t, eig_a + (long)i * DM);

        // fused in+gate GEMM: ug[s, 0:4096]=u, [4096:8192]=g
        gemm(hb, wiog + (long)i * 2 * DFF * DM, ug, SQ, 2 * DFF, DM, DM, DM, 2 * DFF,
             1.0f, biog + (long)i * 2 * DFF, nullptr, 0.0f);
        swiglu_k<<<(SQ * DFF) / 256, 256>>>(ug, ub, s_u + (long)i * DFF, s_v + (long)i * DFF);
        gemm(ub, wout + (long)i * DM * DFF, t, SQ, DM, DFF, DFF, DFF, DM,
             1.0f, b_out + (long)i * DM, nullptr, 0.0f);
        resid_norm_k<<<SQ, 256>>>(h, hb, t, eig_m + (long)i * DM);
    }

    gemm(hb, outwb, out, SQ, NV, DM, DM, DM, NV,
         1.0f, out_b, s_z, RTDM);
    softmax_full_k<<<SQ, 256>>>(out);
}

// round 7
// speedup vs baseline: 3.8179x; 1.0945x over previous
#include <cuda_runtime.h>
#include <cuda_bf16.h>
#include <math.h>
#include <stdint.h>

// ---------------- problem dims (fixed) ----------------
#define SQ   1024
#define DM   1024
#define NH   16
#define NG   4
#define HDIM 64
#define HPG  4
#define GHD  256
#define NL   4
#define DFF  4096
#define NV   32000
#define QKV  1536      // DM + 2*GHD
#define RTD  8.0f
#define RTDM 32.0f

// ---------------- device scratch ----------------
__device__ float g_h   [SQ * DM];
__device__ float g_qkv [SQ * QKV];
__device__ float g_t   [SQ * DM];
__device__ float g_ug  [SQ * 2 * DFF];
__device__ float g_qkvb[NL * QKV];
__device__ float g_biog[NL * 2 * DFF];

__device__ __align__(16) __nv_bfloat16 g_hb   [SQ * DM];
__device__ __align__(16) __nv_bfloat16 g_attnb[SQ * DM];
__device__ __align__(16) __nv_bfloat16 g_ub   [SQ * DFF];
__device__ __align__(16) __nv_bfloat16 g_qkvw [(long)NL * QKV * DM];
__device__ __align__(16) __nv_bfloat16 g_wiog [(long)NL * 2 * DFF * DM];
__device__ __align__(16) __nv_bfloat16 g_wout [(long)NL * DM * DFF];
__device__ __align__(16) __nv_bfloat16 g_ow   [(long)NL * DM * DM];
__device__ __align__(16) __nv_bfloat16 g_outw [(long)NV * DM];

__device__ __forceinline__ uint32_t packbf(float x, float y) {
    __nv_bfloat162 t = __floats2bfloat162_rn(x, y);
    return *reinterpret_cast<uint32_t*>(&t);
}
__device__ __forceinline__ uint32_t packbf_res(float x, float y, uint32_t hi) {
    __nv_bfloat162 h = *reinterpret_cast<__nv_bfloat162*>(&hi);
    return packbf(x - __bfloat162float(h.x), y - __bfloat162float(h.y));
}

__device__ __forceinline__ void mma_bf16(float c[4], uint32_t a0, uint32_t a1,
                                         uint32_t a2, uint32_t a3,
                                         uint32_t b0, uint32_t b1) {
    asm volatile(
        "mma.sync.aligned.m16n8k16.row.col.f32.bf16.bf16.f32 "
        "{%0,%1,%2,%3}, {%4,%5,%6,%7}, {%8,%9}, {%0,%1,%2,%3};"
        : "+f"(c[0]), "+f"(c[1]), "+f"(c[2]), "+f"(c[3])
        : "r"(a0), "r"(a1), "r"(a2), "r"(a3), "r"(b0), "r"(b1));
}

__device__ __forceinline__ void ldsm4(uint32_t r[4], uint32_t addr) {
    asm volatile(
        "ldmatrix.sync.aligned.m8n8.x4.shared.b16 {%0,%1,%2,%3}, [%4];"
        : "=r"(r[0]), "=r"(r[1]), "=r"(r[2]), "=r"(r[3]) : "r"(addr));
}

// ---------------- fp32 -> bf16 conversion (x4 ILP) ----------------
__global__ void cvt_k(__nv_bfloat16* __restrict__ dst, const float* __restrict__ src, int n4)
{
    int i = blockIdx.x * 1024 + threadIdx.x;
#pragma unroll
    for (int j = 0; j < 4; j++) {
        int idx = i + j * 256;
        if (idx < n4) {
            float4 v = ((const float4*)src)[idx];
            uint32_t* d = (uint32_t*)dst + idx * 2;
            d[0] = packbf(v.x, v.y);
            d[1] = packbf(v.z, v.w);
        }
    }
}
static void cvt(__nv_bfloat16* dst, const float* src, long n) {
    int n4 = (int)(n / 4);
    cvt_k<<<(n4 + 1023) / 1024, 256>>>(dst, src, n4);
}

// ================= pure-bf16 TB GEMM with ldmatrix =================
// C[M,N] = epi(alpha * A[M,K] @ B[N,K]^T); tiles BMT x 128 x 32, 256 threads.
// BMT=128: warps 4m x 2n (warp 32x64, NF=8). BMT=64: warps 2m x 4n (32x32, NF=4).
#define TASTR 20
#define TBW   (128 * TASTR)

template<int BMT, int NF>
__global__ void __launch_bounds__(256)
bf16_gemm_k(const __nv_bfloat16* __restrict__ A, const __nv_bfloat16* __restrict__ B,
            float* __restrict__ C, int K, int lda, int ldb, int ldc,
            float alpha, const float* __restrict__ bias,
            const float* __restrict__ scalev, float beta)
{
    constexpr int TAW = BMT * TASTR;
    __shared__ __align__(16) uint32_t As[2 * TAW];
    __shared__ __align__(16) uint32_t Bs[2 * TBW];

    const int bm = blockIdx.y * BMT;
    const int bn = blockIdx.x * 128;
    const int tid  = threadIdx.x;
    const int wid  = tid >> 5;
    const int lane = tid & 31;
    const int g4   = lane >> 2;
    const int t4   = lane & 3;
    const int wm   = (BMT == 128) ? (wid & 3) * 32 : (wid & 1) * 32;
    const int wn   = (BMT == 128) ? (wid >> 2) * 64 : (wid >> 1) * 32;

    // ldmatrix per-lane base (words): row = lane&15, k-word block = (lane>>4)*4
    const uint32_t asb = (uint32_t)__cvta_generic_to_shared(As);
    const uint32_t bsb = (uint32_t)__cvta_generic_to_shared(Bs);
    const uint32_t aFrag = asb + 4u * ((wm + (lane & 15)) * TASTR + (lane >> 4) * 4);
    const uint32_t bFrag = bsb + 4u * ((wn + (lane & 15)) * TASTR + (lane >> 4) * 4);

    // global->smem staging
    const int rb_ = tid >> 1, hb_ = tid & 1;          // B: 2 thr/row, 16 elems each
    const int ra_ = (BMT == 128) ? (tid >> 1) : (tid >> 2);
    const int qa_ = (BMT == 128) ? (tid & 1)  : (tid & 3);   // A quarter/half

    uint4 ra[2], rb[2];

    auto ldg = [&](int k0) {
        if (BMT == 128) {
            const __nv_bfloat16* pa = A + (long)(bm + ra_) * lda + k0 + qa_ * 16;
            ra[0] = *(const uint4*)pa; ra[1] = *(const uint4*)(pa + 8);
        } else {
            const __nv_bfloat16* pa = A + (long)(bm + ra_) * lda + k0 + qa_ * 8;
            ra[0] = *(const uint4*)pa;
        }
        const __nv_bfloat16* pb = B + (long)(bn + rb_) * ldb + k0 + hb_ * 16;
        rb[0] = *(const uint4*)pb; rb[1] = *(const uint4*)(pb + 8);
    };
    auto sts = [&](int buf) {
        if (BMT == 128) {
            uint32_t* da = As + buf * TAW + ra_ * TASTR + qa_ * 8;
            *(uint4*)da = ra[0]; *(uint4*)(da + 4) = ra[1];
        } else {
            uint32_t* da = As + buf * TAW + ra_ * TASTR + qa_ * 4;
            *(uint4*)da = ra[0];
        }
        uint32_t* db = Bs + buf * TBW + rb_ * TASTR + hb_ * 8;
        *(uint4*)db = rb[0]; *(uint4*)(db + 4) = rb[1];
    };

    float acc[2][NF][4];
#pragma unroll
    for (int i = 0; i < 2; i++)
#pragma unroll
        for (int j = 0; j < NF; j++)
#pragma unroll
            for (int l = 0; l < 4; l++) acc[i][j][l] = 0.0f;

    ldg(0);
    const int nsteps = K / 32;
    for (int ks = 0; ks < nsteps; ks++) {
        sts(ks & 1);
        __syncthreads();
        if (ks + 1 < nsteps) ldg((ks + 1) * 32);

        const uint32_t aB = aFrag + (ks & 1) * TAW * 4;
        const uint32_t bB = bFrag + (ks & 1) * TBW * 4;

#pragma unroll
        for (int kh = 0; kh < 2; kh++) {
            uint32_t af[2][4];
            ldsm4(af[0], aB + 4u * (kh * 8));
            ldsm4(af[1], aB + 4u * (16 * TASTR + kh * 8));
#pragma unroll
            for (int bf = 0; bf < NF / 2; bf++) {
                uint32_t bb[4];   // {b0 even, b0 odd, b1 even, b1 odd}
                ldsm4(bb, bB + 4u * (bf * 16 * TASTR + kh * 8));
                mma_bf16(acc[0][2*bf  ], af[0][0], af[0][1], af[0][2], af[0][3], bb[0], bb[2]);
                mma_bf16(acc[1][2*bf  ], af[1][0], af[1][1], af[1][2], af[1][3], bb[0], bb[2]);
                mma_bf16(acc[0][2*bf+1], af[0][0], af[0][1], af[0][2], af[0][3], bb[1], bb[3]);
                mma_bf16(acc[1][2*bf+1], af[1][0], af[1][1], af[1][2], af[1][3], bb[1], bb[3]);
            }
        }
        __syncthreads();
    }

#pragma unroll
    for (int mf = 0; mf < 2; mf++) {
#pragma unroll
        for (int nf = 0; nf < NF; nf++) {
            const int row = bm + wm + mf * 16 + g4;
            const int col = bn + wn + nf * 8 + t4 * 2;
            float v0 = acc[mf][nf][0] * alpha;
            float v1 = acc[mf][nf][1] * alpha;
            float v2 = acc[mf][nf][2] * alpha;
            float v3 = acc[mf][nf][3] * alpha;
            if (bias) {
                float b0 = bias[col], b1 = bias[col + 1];
                v0 += b0; v1 += b1; v2 += b0; v3 += b1;
            }
            if (scalev) {
                float s0 = scalev[col] * beta, s1 = scalev[col + 1] * beta;
                v0 *= s0; v1 *= s1; v2 *= s0; v3 *= s1;
            }
            *(float2*)(C + (long)row * ldc + col)       = make_float2(v0, v1);
            *(float2*)(C + (long)(row + 8) * ldc + col) = make_float2(v2, v3);
        }
    }
}

// ================= fused flash attention (bf16 output) =================
__global__ void __launch_bounds__(256)
flash_attn_k(const float* __restrict__ qkv, __nv_bfloat16* __restrict__ attnb)
{
    __shared__ uint32_t Qs[128 * 36];
    __shared__ uint32_t Ks[64 * 36];
    __shared__ uint32_t Vs[64 * 36];

    const int qb = blockIdx.x;
    const int hh = blockIdx.y;
    const int gg = hh >> 2;
    const int qcol = hh * HDIM;
    const int kcol = DM + gg * HDIM;
    const int vcol = DM + GHD + gg * HDIM;

    const int tid  = threadIdx.x;
    const int wid  = tid >> 5;
    const int lane = tid & 31;
    const int g4   = lane >> 2;
    const int t4   = lane & 3;
    const int wm   = wid * 16;
    const int s0q  = qb * 128;

    {
        int r = tid >> 1, half = tid & 1;
        const float* src = qkv + (long)(s0q + r) * QKV + qcol + half * 32;
        uint32_t* dst = Qs + r * 36 + half * 16;
#pragma unroll
        for (int i = 0; i < 8; i++) {
            float4 v = *(const float4*)(src + i * 4);
            dst[2 * i]     = packbf(v.x, v.y);
            dst[2 * i + 1] = packbf(v.z, v.w);
        }
    }

    float O[8][4];
#pragma unroll
    for (int j = 0; j < 8; j++)
#pragma unroll
        for (int l = 0; l < 4; l++) O[j][l] = 0.0f;
    float m0 = -1e30f, m1 = -1e30f, l0 = 0.0f, l1 = 0.0f;

    const int nblk = 2 * qb + 2;
    for (int jb = 0; jb < nblk; jb++) {
        const int s0 = jb * 64;
        __syncthreads();

        {
            int r = tid >> 2, q4 = tid & 3;
            const float* src = qkv + (long)(s0 + r) * QKV + kcol + q4 * 16;
            uint32_t* dst = Ks + r * 36 + q4 * 8;
#pragma unroll
            for (int i = 0; i < 4; i++) {
                float4 v = *(const float4*)(src + i * 4);
                dst[2 * i]     = packbf(v.x, v.y);
                dst[2 * i + 1] = packbf(v.z, v.w);
            }
        }
        {
            int d = tid & 63, sb = tid >> 6;
#pragma unroll
            for (int i = 0; i < 8; i++) {
                int sp = sb * 8 + i;
                const float* p0 = qkv + (long)(s0 + 2 * sp) * QKV + vcol + d;
                Vs[d * 36 + sp] = packbf(p0[0], p0[QKV]);
            }
        }
        __syncthreads();

        float S[8][4];
#pragma unroll
        for (int j = 0; j < 8; j++)
#pragma unroll
            for (int l = 0; l < 4; l++) S[j][l] = 0.0f;

#pragma unroll
        for (int kc = 0; kc < 4; kc++) {
            uint32_t a0 = Qs[(wm + g4    ) * 36 + kc * 8 + t4    ];
            uint32_t a1 = Qs[(wm + g4 + 8) * 36 + kc * 8 + t4    ];
            uint32_t a2 = Qs[(wm + g4    ) * 36 + kc * 8 + t4 + 4];
            uint32_t a3 = Qs[(wm + g4 + 8) * 36 + kc * 8 + t4 + 4];
#pragma unroll
            for (int nf = 0; nf < 8; nf++) {
                uint32_t b0 = Ks[(nf * 8 + g4) * 36 + kc * 8 + t4    ];
                uint32_t b1 = Ks[(nf * 8 + g4) * 36 + kc * 8 + t4 + 4];
                mma_bf16(S[nf], a0, a1, a2, a3, b0, b1);
            }
        }

        if (jb >= 2 * qb) {
            const int r0 = s0q + wm + g4, r1 = r0 + 8;
#pragma unroll
            for (int nf = 0; nf < 8; nf++) {
                const int c = s0 + nf * 8 + t4 * 2;
                if (c     > r0) S[nf][0] = -1e30f;
                if (c + 1 > r0) S[nf][1] = -1e30f;
                if (c     > r1) S[nf][2] = -1e30f;
                if (c + 1 > r1) S[nf][3] = -1e30f;
            }
        }

        float bm0 = -1e30f, bm1 = -1e30f;
#pragma unroll
        for (int nf = 0; nf < 8; nf++) {
            bm0 = fmaxf(bm0, fmaxf(S[nf][0], S[nf][1]));
            bm1 = fmaxf(bm1, fmaxf(S[nf][2], S[nf][3]));
        }
        bm0 = fmaxf(bm0, __shfl_xor_sync(0xffffffffu, bm0, 1));
        bm0 = fmaxf(bm0, __shfl_xor_sync(0xffffffffu, bm0, 2));
        bm1 = fmaxf(bm1, __shfl_xor_sync(0xffffffffu, bm1, 1));
        bm1 = fmaxf(bm1, __shfl_xor_sync(0xffffffffu, bm1, 2));

        float nm0 = fmaxf(m0, bm0), nm1 = fmaxf(m1, bm1);
        float sc0 = __expf(m0 - nm0), sc1 = __expf(m1 - nm1);
        m0 = nm0; m1 = nm1;

        float ps0 = 0.0f, ps1 = 0.0f;
#pragma unroll
        for (int nf = 0; nf < 8; nf++) {
            S[nf][0] = __expf(S[nf][0] - m0);
            S[nf][1] = __expf(S[nf][1] - m0);
            S[nf][2] = __expf(S[nf][2] - m1);
            S[nf][3] = __expf(S[nf][3] - m1);
            ps0 += S[nf][0] + S[nf][1];
            ps1 += S[nf][2] + S[nf][3];
        }
        ps0 += __shfl_xor_sync(0xffffffffu, ps0, 1);
        ps0 += __shfl_xor_sync(0xffffffffu, ps0, 2);
        ps1 += __shfl_xor_sync(0xffffffffu, ps1, 1);
        ps1 += __shfl_xor_sync(0xffffffffu, ps1, 2);
        l0 = l0 * sc0 + ps0;
        l1 = l1 * sc1 + ps1;

#pragma unroll
        for (int nf = 0; nf < 8; nf++) {
            O[nf][0] *= sc0; O[nf][1] *= sc0;
            O[nf][2] *= sc1; O[nf][3] *= sc1;
        }

#pragma unroll
        for (int kc = 0; kc < 4; kc++) {
            uint32_t ah0 = packbf(S[2*kc  ][0], S[2*kc  ][1]);
            uint32_t ah1 = packbf(S[2*kc  ][2], S[2*kc  ][3]);
            uint32_t ah2 = packbf(S[2*kc+1][0], S[2*kc+1][1]);
            uint32_t ah3 = packbf(S[2*kc+1][2], S[2*kc+1][3]);
            uint32_t al0 = packbf_res(S[2*kc  ][0], S[2*kc  ][1], ah0);
            uint32_t al1 = packbf_res(S[2*kc  ][2], S[2*kc  ][3], ah1);
            uint32_t al2 = packbf_res(S[2*kc+1][0], S[2*kc+1][1], ah2);
            uint32_t al3 = packbf_res(S[2*kc+1][2], S[2*kc+1][3], ah3);
#pragma unroll
            for (int nf = 0; nf < 8; nf++) {
                uint32_t b0 = Vs[(nf * 8 + g4) * 36 + kc * 8 + t4    ];
                uint32_t b1 = Vs[(nf * 8 + g4) * 36 + kc * 8 + t4 + 4];
                mma_bf16(O[nf], ah0, ah1, ah2, ah3, b0, b1);
                mma_bf16(O[nf], al0, al1, al2, al3, b0, b1);
            }
        }
    }

    const float inv0 = 1.0f / l0, inv1 = 1.0f / l1;
    const int row0 = s0q + wm + g4;
#pragma unroll
    for (int nf = 0; nf < 8; nf++) {
        const int col = hh * HDIM + nf * 8 + t4 * 2;
        *(uint32_t*)(attnb + (long)row0 * DM + col) =
            packbf(O[nf][0] * inv0, O[nf][1] * inv0);
        *(uint32_t*)(attnb + (long)(row0 + 8) * DM + col) =
            packbf(O[nf][2] * inv1, O[nf][3] * inv1);
    }
}

// ---------------- embedding gather (fp32 + bf16 copies) ----------------
__global__ void embed_k(const int* __restrict__ x, const float* __restrict__ emb,
                        float* __restrict__ h, __nv_bfloat16* __restrict__ hb)
{
    int s = blockIdx.x;
    int t = threadIdx.x;
    float4 v = ((const float4*)(emb + (long)x[s] * DM))[t];
    ((float4*)(h + (long)s * DM))[t] = v;
    uint32_t* d = (uint32_t*)(hb + (long)s * DM) + t * 2;
    d[0] = packbf(v.x, v.y);
    d[1] = packbf(v.z, v.w);
}

// ---------------- RoPE + cosine-norm, Q (folds eff^2 * RTD into Q) ----------------
__global__ void rope_norm_q_k(float* __restrict__ q, const float* __restrict__ sqk, int ld)
{
    int s = blockIdx.x, hh = blockIdx.y;
    int j = threadIdx.x;
    float* base = q + (long)s * ld + hh * HDIM;
    float x1 = base[j], x2 = base[j + 32];

    float inv = powf(10000.0f, -(float)j / 32.0f);
    float ang = (float)s * inv;
    float sn, cs; sincosf(ang, &sn, &cs);
    float o1 = x1 * cs - x2 * sn;
    float o2 = x2 * cs + x1 * sn;

    float ss = o1 * o1 + o2 * o2;
#pragma unroll
    for (int off = 16; off > 0; off >>= 1)
        ss += __shfl_xor_sync(0xffffffffu, ss, off);
    float n = fmaxf(sqrtf(ss), 1e-6f);

    float e1 = sqk[hh * HDIM + j]      * RTD;
    float e2 = sqk[hh * HDIM + j + 32] * RTD;
    base[j]      = (o1 / n) * e1 * e1 * RTD;
    base[j + 32] = (o2 / n) * e2 * e2 * RTD;
}

// ---------------- RoPE + cosine-norm, K ----------------
__global__ void rope_norm_kk(float* __restrict__ k, int ld)
{
    int s = blockIdx.x, g = blockIdx.y;
    int j = threadIdx.x;
    float* base = k + (long)s * ld + g * HDIM;
    float x1 = base[j], x2 = base[j + 32];

    float inv = powf(10000.0f, -(float)j / 32.0f);
    float ang = (float)s * inv;
    float sn, cs; sincosf(ang, &sn, &cs);
    float o1 = x1 * cs - x2 * sn;
    float o2 = x2 * cs + x1 * sn;

    float ss = o1 * o1 + o2 * o2;
#pragma unroll
    for (int off = 16; off > 0; off >>= 1)
        ss += __shfl_xor_sync(0xffffffffu, ss, off);
    float n = fmaxf(sqrtf(ss), 1e-6f);

    base[j]      = o1 / n;
    base[j + 32] = o2 / n;
}

// ---------------- residual lerp + cosine norm (writes fp32 + bf16) ----------------
__global__ void resid_norm_k(float* __restrict__ h, __nv_bfloat16* __restrict__ hb,
                             const float* __restrict__ t, const float* __restrict__ eig)
{
    int row = blockIdx.x;
    int tid = threadIdx.x;
    __shared__ float red[256];

    float4 tv = ((const float4*)(t + (long)row * DM))[tid];
    float ss = tv.x * tv.x + tv.y * tv.y + tv.z * tv.z + tv.w * tv.w;
    red[tid] = ss; __syncthreads();
    for (int o = 128; o > 0; o >>= 1) { if (tid < o) red[tid] += red[tid + o]; __syncthreads(); }
    float nt = fmaxf(sqrtf(red[0]), 1e-6f);
    __syncthreads();

    float4 hv = ((const float4*)(h + (long)row * DM))[tid];
    float4 ev = ((const float4*)eig)[tid];
    float4 r;
    r.x = hv.x + ev.x * RTDM * (tv.x / nt - hv.x);
    r.y = hv.y + ev.y * RTDM * (tv.y / nt - hv.y);
    r.z = hv.z + ev.z * RTDM * (tv.z / nt - hv.z);
    r.w = hv.w + ev.w * RTDM * (tv.w / nt - hv.w);

    float ss2 = r.x * r.x + r.y * r.y + r.z * r.z + r.w * r.w;
    red[tid] = ss2; __syncthreads();
    for (int o = 128; o > 0; o >>= 1) { if (tid < o) red[tid] += red[tid + o]; __syncthreads(); }
    float nr = fmaxf(sqrtf(red[0]), 1e-6f);

    r.x /= nr; r.y /= nr; r.z /= nr; r.w /= nr;
    ((float4*)(h + (long)row * DM))[tid] = r;
    uint32_t* d = (uint32_t*)(hb + (long)row * DM) + tid * 2;
    d[0] = packbf(r.x, r.y);
    d[1] = packbf(r.z, r.w);
}

// ---------------- SwiGLU on fused [u;g] buffer -> bf16 ----------------
__global__ void swiglu_k(const float* __restrict__ ug, __nv_bfloat16* __restrict__ ub,
                         const float* __restrict__ su, const float* __restrict__ sv)
{
    long idx = (long)blockIdx.x * 256 + threadIdx.x;
    int s = (int)(idx >> 12);
    int f = (int)(idx & (DFF - 1));
    float uv = ug[(long)s * 2 * DFF + f]       * su[f];
    float gv = ug[(long)s * 2 * DFF + DFF + f] * sv[f] * RTDM;
    ub[idx] = __float2bfloat16(uv * gv / (1.0f + __expf(-gv)));
}

// ---------------- final row softmax ----------------
__global__ void softmax_full_k(float* __restrict__ out)
{
    int row = blockIdx.x;
    float* p = out + (long)row * NV;
    int t = threadIdx.x;
    __shared__ float red[256];

    float m = -1e30f;
    for (int j = t; j < NV; j += 256) m = fmaxf(m, p[j]);
    red[t] = m; __syncthreads();
    for (int o = 128; o > 0; o >>= 1) { if (t < o) red[t] = fmaxf(red[t], red[t + o]); __syncthreads(); }
    m = red[0]; __syncthreads();

    float sum = 0.0f;
    for (int j = t; j < NV; j += 256) { float e = __expf(p[j] - m); p[j] = e; sum += e; }
    red[t] = sum; __syncthreads();
    for (int o = 128; o > 0; o >>= 1) { if (t < o) red[t] += red[t + o]; __syncthreads(); }
    float invs = 1.0f / red[0];

    for (int j = t; j < NV; j += 256) p[j] *= invs;
}

// ---------------- host-side launchers ----------------
static void gemm128(const __nv_bfloat16* A, const __nv_bfloat16* B, float* C,
                    int M, int N, int K, int lda, int ldb, int ldc,
                    float alpha, const float* bias, const float* scalev, float beta)
{
    dim3 grid(N / 128, M / 128);
    bf16_gemm_k<128, 8><<<grid, 256>>>(A, B, C, K, lda, ldb, ldc, alpha, bias, scalev, beta);
}
static void gemm64(const __nv_bfloat16* A, const __nv_bfloat16* B, float* C,
                   int M, int N, int K, int lda, int ldb, int ldc,
                   float alpha, const float* bias, const float* scalev, float beta)
{
    dim3 grid(N / 128, M / 64);
    bf16_gemm_k<64, 4><<<grid, 256>>>(A, B, C, K, lda, ldb, ldc, alpha, bias, scalev, beta);
}

extern "C" void kernel_launch(void* const* d_in, const int* in_sizes, int n_in,
                              void* d_out, int out_size)
{
    const int*   x      = (const int*)  d_in[0];
    const float* emb    = (const float*)d_in[1];
    const float* qw     = (const float*)d_in[2];
    const float* qb     = (const float*)d_in[3];
    const float* kw     = (const float*)d_in[4];
    const float* kb     = (const float*)d_in[5];
    const float* vw     = (const float*)d_in[6];
    const float* vb     = (const float*)d_in[7];
    const float* sqk    = (const float*)d_in[8];
    const float* ow     = (const float*)d_in[9];
    const float* ob     = (const float*)d_in[10];
    const float* w_in   = (const float*)d_in[11];
    const float* b_in   = (const float*)d_in[12];
    const float* w_gate = (const float*)d_in[13];
    const float* b_gate = (const float*)d_in[14];
    const float* w_out  = (const float*)d_in[15];
    const float* b_out  = (const float*)d_in[16];
    const float* s_u    = (const float*)d_in[17];
    const float* s_v    = (const float*)d_in[18];
    const float* eig_a  = (const float*)d_in[19];
    const float* eig_m  = (const float*)d_in[20];
    const float* out_w  = (const float*)d_in[21];
    const float* out_b  = (const float*)d_in[22];
    const float* s_z    = (const float*)d_in[23];
    float* out = (float*)d_out;

    float *h, *qkv, *t, *ug, *qkvb, *biog;
    __nv_bfloat16 *hb, *attnb, *ub, *qkvw, *wiog, *wout, *owb, *outwb;
    cudaGetSymbolAddress((void**)&h,     g_h);
    cudaGetSymbolAddress((void**)&qkv,   g_qkv);
    cudaGetSymbolAddress((void**)&t,     g_t);
    cudaGetSymbolAddress((void**)&ug,    g_ug);
    cudaGetSymbolAddress((void**)&qkvb,  g_qkvb);
    cudaGetSymbolAddress((void**)&biog,  g_biog);
    cudaGetSymbolAddress((void**)&hb,    g_hb);
    cudaGetSymbolAddress((void**)&attnb, g_attnb);
    cudaGetSymbolAddress((void**)&ub,    g_ub);
    cudaGetSymbolAddress((void**)&qkvw,  g_qkvw);
    cudaGetSymbolAddress((void**)&wiog,  g_wiog);
    cudaGetSymbolAddress((void**)&wout,  g_wout);
    cudaGetSymbolAddress((void**)&owb,   g_ow);
    cudaGetSymbolAddress((void**)&outwb, g_outw);

    // ---- one-time weight conversion to bf16 (fused layouts) ----
    for (int i = 0; i < NL; i++) {
        __nv_bfloat16* w = qkvw + (long)i * QKV * DM;
        cvt(w,                         qw + (long)i * DM * DM,  (long)DM * DM);
        cvt(w + (long)DM * DM,         kw + (long)i * GHD * DM, (long)GHD * DM);
        cvt(w + (long)(DM + GHD) * DM, vw + (long)i * GHD * DM, (long)GHD * DM);

        __nv_bfloat16* wg = wiog + (long)i * 2 * DFF * DM;
        cvt(wg,                  w_in   + (long)i * DFF * DM, (long)DFF * DM);
        cvt(wg + (long)DFF * DM, w_gate + (long)i * DFF * DM, (long)DFF * DM);

        float* b = qkvb + i * QKV;
        cudaMemcpyAsync(b,            qb + (long)i * DM,  sizeof(float) * DM,  cudaMemcpyDeviceToDevice);
        cudaMemcpyAsync(b + DM,       kb + (long)i * GHD, sizeof(float) * GHD, cudaMemcpyDeviceToDevice);
        cudaMemcpyAsync(b + DM + GHD, vb + (long)i * GHD, sizeof(float) * GHD, cudaMemcpyDeviceToDevice);
        cudaMemcpyAsync(biog + (long)i * 2 * DFF,       b_in   + (long)i * DFF, sizeof(float) * DFF, cudaMemcpyDeviceToDevice);
        cudaMemcpyAsync(biog + (long)i * 2 * DFF + DFF, b_gate + (long)i * DFF, sizeof(float) * DFF, cudaMemcpyDeviceToDevice);
    }
    cvt(owb,   ow,    (long)NL * DM * DM);
    cvt(wout,  w_out, (long)NL * DM * DFF);
    cvt(outwb, out_w, (long)NV * DM);

    embed_k<<<SQ, 256>>>(x, emb, h, hb);

    for (int i = 0; i < NL; i++) {
        // fused QKV projection
        gemm128(hb, qkvw + (long)i * QKV * DM, qkv, SQ, QKV, DM, DM, DM, QKV,
                1.0f, qkvb + i * QKV, nullptr, 0.0f);

        rope_norm_q_k<<<dim3(SQ, NH), 32>>>(qkv, sqk + (long)i * NH * HDIM, QKV);
        rope_norm_kk <<<dim3(SQ, NG), 32>>>(qkv + DM, QKV);

        flash_attn_k<<<dim3(SQ / 128, NH), 256>>>(qkv, attnb);

        gemm64(attnb, owb + (long)i * DM * DM, t, SQ, DM, DM, DM, DM, DM,
               1.0f, ob + (long)i * DM, nullptr, 0.0f);
        resid_norm_k<<<SQ, 256>>>(h, hb, t, eig_a + (long)i * DM);

        // fused in+gate GEMM
        gemm128(hb, wiog + (long)i * 2 * DFF * DM, ug, SQ, 2 * DFF, DM, DM, DM, 2 * DFF,
                1.0f, biog + (long)i * 2 * DFF, nullptr, 0.0f);
        swiglu_k<<<(SQ * DFF) / 256, 256>>>(ug, ub, s_u + (long)i * DFF, s_v + (long)i * DFF);
        gemm64(ub, wout + (long)i * DM * DFF, t, SQ, DM, DFF, DFF, DFF, DM,
               1.0f, b_out + (long)i * DM, nullptr, 0.0f);
        resid_norm_k<<<SQ, 256>>>(h, hb, t, eig_m + (long)i * DM);
    }

    gemm128(hb, outwb, out, SQ, NV, DM, DM, DM, NV,
            1.0f, out_b, s_z, RTDM);
    softmax_full_k<<<SQ, 256>>>(out);
}

// round 8
// speedup vs baseline: 4.3120x; 1.1294x over previous
#include <cuda_runtime.h>
#include <cuda_bf16.h>
#include <math.h>
#include <stdint.h>

// ---------------- problem dims (fixed) ----------------
#define SQ   1024
#define DM   1024
#define NH   16
#define NG   4
#define HDIM 64
#define HPG  4
#define GHD  256
#define NL   4
#define DFF  4096
#define NV   32000
#define QKV  1536      // DM + 2*GHD
#define RTD  8.0f
#define RTDM 32.0f

// ---------------- device scratch ----------------
__device__ float g_h   [SQ * DM];
__device__ float g_qkv [SQ * QKV];
__device__ float g_t   [SQ * DM];
__device__ float g_qkvb[NL * QKV];
__device__ float g_biog[NL * 2 * DFF];
__device__ float g_siog[NL * 2 * DFF];

__device__ __align__(16) __nv_bfloat16 g_hb   [SQ * DM];
__device__ __align__(16) __nv_bfloat16 g_attnb[SQ * DM];
__device__ __align__(16) __nv_bfloat16 g_ub   [SQ * DFF];
__device__ __align__(16) __nv_bfloat16 g_qkvw [(long)NL * QKV * DM];
__device__ __align__(16) __nv_bfloat16 g_wiog [(long)NL * 2 * DFF * DM];
__device__ __align__(16) __nv_bfloat16 g_wout [(long)NL * DM * DFF];
__device__ __align__(16) __nv_bfloat16 g_ow   [(long)NL * DM * DM];
__device__ __align__(16) __nv_bfloat16 g_outw [(long)NV * DM];

__device__ __forceinline__ uint32_t packbf(float x, float y) {
    __nv_bfloat162 t = __floats2bfloat162_rn(x, y);
    return *reinterpret_cast<uint32_t*>(&t);
}
__device__ __forceinline__ uint32_t packbf_res(float x, float y, uint32_t hi) {
    __nv_bfloat162 h = *reinterpret_cast<__nv_bfloat162*>(&hi);
    return packbf(x - __bfloat162float(h.x), y - __bfloat162float(h.y));
}

__device__ __forceinline__ void mma_bf16(float c[4], uint32_t a0, uint32_t a1,
                                         uint32_t a2, uint32_t a3,
                                         uint32_t b0, uint32_t b1) {
    asm volatile(
        "mma.sync.aligned.m16n8k16.row.col.f32.bf16.bf16.f32 "
        "{%0,%1,%2,%3}, {%4,%5,%6,%7}, {%8,%9}, {%0,%1,%2,%3};"
        : "+f"(c[0]), "+f"(c[1]), "+f"(c[2]), "+f"(c[3])
        : "r"(a0), "r"(a1), "r"(a2), "r"(a3), "r"(b0), "r"(b1));
}

__device__ __forceinline__ void ldsm4(uint32_t r[4], uint32_t addr) {
    asm volatile(
        "ldmatrix.sync.aligned.m8n8.x4.shared.b16 {%0,%1,%2,%3}, [%4];"
        : "=r"(r[0]), "=r"(r[1]), "=r"(r[2]), "=r"(r[3]) : "r"(addr));
}

// ---------------- fp32 -> bf16 conversion (exact grid, MLP=4) ----------------
__global__ void cvt_k(__nv_bfloat16* __restrict__ dst, const float* __restrict__ src)
{
    int base = blockIdx.x * 1024 + threadIdx.x;
    float4 v0 = ((const float4*)src)[base];
    float4 v1 = ((const float4*)src)[base + 256];
    float4 v2 = ((const float4*)src)[base + 512];
    float4 v3 = ((const float4*)src)[base + 768];
    uint2* d = (uint2*)dst;
    d[base]       = make_uint2(packbf(v0.x, v0.y), packbf(v0.z, v0.w));
    d[base + 256] = make_uint2(packbf(v1.x, v1.y), packbf(v1.z, v1.w));
    d[base + 512] = make_uint2(packbf(v2.x, v2.y), packbf(v2.z, v2.w));
    d[base + 768] = make_uint2(packbf(v3.x, v3.y), packbf(v3.z, v3.w));
}
static void cvt(__nv_bfloat16* dst, const float* src, long n) {
    cvt_k<<<(int)(n / 4096), 256>>>(dst, src);
}

// ---------------- interleaved conversion for w_in/w_gate ----------------
// dst row 2f = w_in[f], row 2f+1 = w_gate[f]; layers stacked.
__global__ void cvt_inter_k(__nv_bfloat16* __restrict__ dst,
                            const float* __restrict__ w_in,
                            const float* __restrict__ w_gate)
{
    int base = blockIdx.x * 1024 + threadIdx.x;
#pragma unroll
    for (int j = 0; j < 4; j++) {
        int e = base + j * 256;                 // float4 index
        int c4 = e & 255;                       // DM/4 = 256
        int rest = e >> 8;
        int r = rest & (2 * DFF - 1);
        int l = rest >> 13;
        const float* src = (r & 1) ? w_gate : w_in;
        float4 v = *(const float4*)(src + ((long)l * DFF + (r >> 1)) * DM + c4 * 4);
        ((uint2*)dst)[e] = make_uint2(packbf(v.x, v.y), packbf(v.z, v.w));
    }
}

// ---------------- interleave biases/scales for fused swiglu ----------------
__global__ void inter_bs_k(float* __restrict__ biog, float* __restrict__ siog,
                           const float* __restrict__ b_in, const float* __restrict__ b_gate,
                           const float* __restrict__ s_u, const float* __restrict__ s_v)
{
    int idx = blockIdx.x * 256 + threadIdx.x;      // over NL*DFF
    int l = idx >> 12;
    int f = idx & (DFF - 1);
    biog[(long)l * 2 * DFF + 2 * f]     = b_in  [(long)l * DFF + f];
    biog[(long)l * 2 * DFF + 2 * f + 1] = b_gate[(long)l * DFF + f];
    siog[(long)l * 2 * DFF + 2 * f]     = s_u   [(long)l * DFF + f];
    siog[(long)l * 2 * DFF + 2 * f + 1] = s_v   [(long)l * DFF + f] * RTDM;
}

// ================= pure-bf16 TB GEMM with ldmatrix =================
// C[M,N] = epi(alpha * A[M,K] @ B[N,K]^T); tiles BMT x 128 x 32, 256 threads.
// EPI=0: C fp32, optional bias/scalev. EPI=1: fused swiglu on interleaved
// (u,g) column pairs, C bf16 with ldc cols, bias/scalev interleaved.
#define TASTR 20
#define TBW   (128 * TASTR)

template<int BMT, int NF, int EPI>
__global__ void __launch_bounds__(256, 2)
bf16_gemm_k(const __nv_bfloat16* __restrict__ A, const __nv_bfloat16* __restrict__ B,
            void* __restrict__ Cv, int K, int lda, int ldb, int ldc,
            float alpha, const float* __restrict__ bias,
            const float* __restrict__ scalev, float beta)
{
    constexpr int TAW = BMT * TASTR;
    __shared__ __align__(16) uint32_t As[2 * TAW];
    __shared__ __align__(16) uint32_t Bs[2 * TBW];

    const int bm = blockIdx.y * BMT;
    const int bn = blockIdx.x * 128;
    const int tid  = threadIdx.x;
    const int wid  = tid >> 5;
    const int lane = tid & 31;
    const int g4   = lane >> 2;
    const int t4   = lane & 3;
    const int wm   = (BMT == 128) ? (wid & 3) * 32 : (wid & 1) * 32;
    const int wn   = (BMT == 128) ? (wid >> 2) * 64 : (wid >> 1) * 32;

    const uint32_t asb = (uint32_t)__cvta_generic_to_shared(As);
    const uint32_t bsb = (uint32_t)__cvta_generic_to_shared(Bs);
    const uint32_t aFrag = asb + 4u * ((wm + (lane & 15)) * TASTR + (lane >> 4) * 4);
    const uint32_t bFrag = bsb + 4u * ((wn + (lane & 15)) * TASTR + (lane >> 4) * 4);

    const int rb_ = tid >> 1, hb_ = tid & 1;
    const int ra_ = (BMT == 128) ? (tid >> 1) : (tid >> 2);
    const int qa_ = (BMT == 128) ? (tid & 1)  : (tid & 3);

    uint4 ra[2], rb[2];

    auto ldg = [&](int k0) {
        if (BMT == 128) {
            const __nv_bfloat16* pa = A + (long)(bm + ra_) * lda + k0 + qa_ * 16;
            ra[0] = *(const uint4*)pa; ra[1] = *(const uint4*)(pa + 8);
        } else {
            const __nv_bfloat16* pa = A + (long)(bm + ra_) * lda + k0 + qa_ * 8;
            ra[0] = *(const uint4*)pa;
        }
        const __nv_bfloat16* pb = B + (long)(bn + rb_) * ldb + k0 + hb_ * 16;
        rb[0] = *(const uint4*)pb; rb[1] = *(const uint4*)(pb + 8);
    };
    auto sts = [&](int buf) {
        if (BMT == 128) {
            uint32_t* da = As + buf * TAW + ra_ * TASTR + qa_ * 8;
            *(uint4*)da = ra[0]; *(uint4*)(da + 4) = ra[1];
        } else {
            uint32_t* da = As + buf * TAW + ra_ * TASTR + qa_ * 4;
            *(uint4*)da = ra[0];
        }
        uint32_t* db = Bs + buf * TBW + rb_ * TASTR + hb_ * 8;
        *(uint4*)db = rb[0]; *(uint4*)(db + 4) = rb[1];
    };

    float acc[2][NF][4];
#pragma unroll
    for (int i = 0; i < 2; i++)
#pragma unroll
        for (int j = 0; j < NF; j++)
#pragma unroll
            for (int l = 0; l < 4; l++) acc[i][j][l] = 0.0f;

    ldg(0);
    const int nsteps = K / 32;
    for (int ks = 0; ks < nsteps; ks++) {
        sts(ks & 1);
        __syncthreads();
        if (ks + 1 < nsteps) ldg((ks + 1) * 32);

        const uint32_t aB = aFrag + (ks & 1) * TAW * 4;
        const uint32_t bB = bFrag + (ks & 1) * TBW * 4;

#pragma unroll
        for (int kh = 0; kh < 2; kh++) {
            uint32_t af[2][4];
            ldsm4(af[0], aB + 4u * (kh * 8));
            ldsm4(af[1], aB + 4u * (16 * TASTR + kh * 8));
#pragma unroll
            for (int bf = 0; bf < NF / 2; bf++) {
                uint32_t bb[4];
                ldsm4(bb, bB + 4u * (bf * 16 * TASTR + kh * 8));
                mma_bf16(acc[0][2*bf  ], af[0][0], af[0][1], af[0][2], af[0][3], bb[0], bb[2]);
                mma_bf16(acc[1][2*bf  ], af[1][0], af[1][1], af[1][2], af[1][3], bb[0], bb[2]);
                mma_bf16(acc[0][2*bf+1], af[0][0], af[0][1], af[0][2], af[0][3], bb[1], bb[3]);
                mma_bf16(acc[1][2*bf+1], af[1][0], af[1][1], af[1][2], af[1][3], bb[1], bb[3]);
            }
        }
        __syncthreads();
    }

#pragma unroll
    for (int mf = 0; mf < 2; mf++) {
#pragma unroll
        for (int nf = 0; nf < NF; nf++) {
            const int row = bm + wm + mf * 16 + g4;
            const int col = bn + wn + nf * 8 + t4 * 2;
            if (EPI == 0) {
                float* C = (float*)Cv;
                float v0 = acc[mf][nf][0] * alpha;
                float v1 = acc[mf][nf][1] * alpha;
                float v2 = acc[mf][nf][2] * alpha;
                float v3 = acc[mf][nf][3] * alpha;
                if (bias) {
                    float b0 = bias[col], b1 = bias[col + 1];
                    v0 += b0; v1 += b1; v2 += b0; v3 += b1;
                }
                if (scalev) {
                    float s0 = scalev[col] * beta, s1 = scalev[col + 1] * beta;
                    v0 *= s0; v1 *= s1; v2 *= s0; v3 *= s1;
                }
                *(float2*)(C + (long)row * ldc + col)       = make_float2(v0, v1);
                *(float2*)(C + (long)(row + 8) * ldc + col) = make_float2(v2, v3);
            } else {
                // fused swiglu: (col, col+1) = (u_f, g_f), f = col/2
                __nv_bfloat16* C = (__nv_bfloat16*)Cv;
                const float b0 = bias[col], b1 = bias[col + 1];
                const float s0 = scalev[col], s1 = scalev[col + 1];
                const int f = col >> 1;
                {
                    float u = (acc[mf][nf][0] + b0) * s0;
                    float g = (acc[mf][nf][1] + b1) * s1;
                    C[(long)row * ldc + f] = __float2bfloat16(u * g / (1.0f + __expf(-g)));
                }
                {
                    float u = (acc[mf][nf][2] + b0) * s0;
                    float g = (acc[mf][nf][3] + b1) * s1;
                    C[(long)(row + 8) * ldc + f] = __float2bfloat16(u * g / (1.0f + __expf(-g)));
                }
            }
        }
    }
}

// ================= fused flash attention (bf16 output) =================
__global__ void __launch_bounds__(256)
flash_attn_k(const float* __restrict__ qkv, __nv_bfloat16* __restrict__ attnb)
{
    __shared__ uint32_t Qs[128 * 36];
    __shared__ uint32_t Ks[64 * 36];
    __shared__ uint32_t Vs[64 * 36];

    const int qb = blockIdx.x;
    const int hh = blockIdx.y;
    const int gg = hh >> 2;
    const int qcol = hh * HDIM;
    const int kcol = DM + gg * HDIM;
    const int vcol = DM + GHD + gg * HDIM;

    const int tid  = threadIdx.x;
    const int wid  = tid >> 5;
    const int lane = tid & 31;
    const int g4   = lane >> 2;
    const int t4   = lane & 3;
    const int wm   = wid * 16;
    const int s0q  = qb * 128;

    {
        int r = tid >> 1, half = tid & 1;
        const float* src = qkv + (long)(s0q + r) * QKV + qcol + half * 32;
        uint32_t* dst = Qs + r * 36 + half * 16;
#pragma unroll
        for (int i = 0; i < 8; i++) {
            float4 v = *(const float4*)(src + i * 4);
            dst[2 * i]     = packbf(v.x, v.y);
            dst[2 * i + 1] = packbf(v.z, v.w);
        }
    }

    float O[8][4];
#pragma unroll
    for (int j = 0; j < 8; j++)
#pragma unroll
        for (int l = 0; l < 4; l++) O[j][l] = 0.0f;
    float m0 = -1e30f, m1 = -1e30f, l0 = 0.0f, l1 = 0.0f;

    const int nblk = 2 * qb + 2;
    for (int jb = 0; jb < nblk; jb++) {
        const int s0 = jb * 64;
        __syncthreads();

        {
            int r = tid >> 2, q4 = tid & 3;
            const float* src = qkv + (long)(s0 + r) * QKV + kcol + q4 * 16;
            uint32_t* dst = Ks + r * 36 + q4 * 8;
#pragma unroll
            for (int i = 0; i < 4; i++) {
                float4 v = *(const float4*)(src + i * 4);
                dst[2 * i]     = packbf(v.x, v.y);
                dst[2 * i + 1] = packbf(v.z, v.w);
            }
        }
        {
            int d = tid & 63, sb = tid >> 6;
#pragma unroll
            for (int i = 0; i < 8; i++) {
                int sp = sb * 8 + i;
                const float* p0 = qkv + (long)(s0 + 2 * sp) * QKV + vcol + d;
                Vs[d * 36 + sp] = packbf(p0[0], p0[QKV]);
            }
        }
        __syncthreads();

        float S[8][4];
#pragma unroll
        for (int j = 0; j < 8; j++)
#pragma unroll
            for (int l = 0; l < 4; l++) S[j][l] = 0.0f;

#pragma unroll
        for (int kc = 0; kc < 4; kc++) {
            uint32_t a0 = Qs[(wm + g4    ) * 36 + kc * 8 + t4    ];
            uint32_t a1 = Qs[(wm + g4 + 8) * 36 + kc * 8 + t4    ];
            uint32_t a2 = Qs[(wm + g4    ) * 36 + kc * 8 + t4 + 4];
            uint32_t a3 = Qs[(wm + g4 + 8) * 36 + kc * 8 + t4 + 4];
#pragma unroll
            for (int nf = 0; nf < 8; nf++) {
                uint32_t b0 = Ks[(nf * 8 + g4) * 36 + kc * 8 + t4    ];
                uint32_t b1 = Ks[(nf * 8 + g4) * 36 + kc * 8 + t4 + 4];
                mma_bf16(S[nf], a0, a1, a2, a3, b0, b1);
            }
        }

        if (jb >= 2 * qb) {
            const int r0 = s0q + wm + g4, r1 = r0 + 8;
#pragma unroll
            for (int nf = 0; nf < 8; nf++) {
                const int c = s0 + nf * 8 + t4 * 2;
                if (c     > r0) S[nf][0] = -1e30f;
                if (c + 1 > r0) S[nf][1] = -1e30f;
                if (c     > r1) S[nf][2] = -1e30f;
                if (c + 1 > r1) S[nf][3] = -1e30f;
            }
        }

        float bm0 = -1e30f, bm1 = -1e30f;
#pragma unroll
        for (int nf = 0; nf < 8; nf++) {
            bm0 = fmaxf(bm0, fmaxf(S[nf][0], S[nf][1]));
            bm1 = fmaxf(bm1, fmaxf(S[nf][2], S[nf][3]));
        }
        bm0 = fmaxf(bm0, __shfl_xor_sync(0xffffffffu, bm0, 1));
        bm0 = fmaxf(bm0, __shfl_xor_sync(0xffffffffu, bm0, 2));
        bm1 = fmaxf(bm1, __shfl_xor_sync(0xffffffffu, bm1, 1));
        bm1 = fmaxf(bm1, __shfl_xor_sync(0xffffffffu, bm1, 2));

        float nm0 = fmaxf(m0, bm0), nm1 = fmaxf(m1, bm1);
        float sc0 = __expf(m0 - nm0), sc1 = __expf(m1 - nm1);
        m0 = nm0; m1 = nm1;

        float ps0 = 0.0f, ps1 = 0.0f;
#pragma unroll
        for (int nf = 0; nf < 8; nf++) {
            S[nf][0] = __expf(S[nf][0] - m0);
            S[nf][1] = __expf(S[nf][1] - m0);
            S[nf][2] = __expf(S[nf][2] - m1);
            S[nf][3] = __expf(S[nf][3] - m1);
            ps0 += S[nf][0] + S[nf][1];
            ps1 += S[nf][2] + S[nf][3];
        }
        ps0 += __shfl_xor_sync(0xffffffffu, ps0, 1);
        ps0 += __shfl_xor_sync(0xffffffffu, ps0, 2);
        ps1 += __shfl_xor_sync(0xffffffffu, ps1, 1);
        ps1 += __shfl_xor_sync(0xffffffffu, ps1, 2);
        l0 = l0 * sc0 + ps0;
        l1 = l1 * sc1 + ps1;

#pragma unroll
        for (int nf = 0; nf < 8; nf++) {
            O[nf][0] *= sc0; O[nf][1] *= sc0;
            O[nf][2] *= sc1; O[nf][3] *= sc1;
        }

#pragma unroll
        for (int kc = 0; kc < 4; kc++) {
            uint32_t ah0 = packbf(S[2*kc  ][0], S[2*kc  ][1]);
            uint32_t ah1 = packbf(S[2*kc  ][2], S[2*kc  ][3]);
            uint32_t ah2 = packbf(S[2*kc+1][0], S[2*kc+1][1]);
            uint32_t ah3 = packbf(S[2*kc+1][2], S[2*kc+1][3]);
            uint32_t al0 = packbf_res(S[2*kc  ][0], S[2*kc  ][1], ah0);
            uint32_t al1 = packbf_res(S[2*kc  ][2], S[2*kc  ][3], ah1);
            uint32_t al2 = packbf_res(S[2*kc+1][0], S[2*kc+1][1], ah2);
            uint32_t al3 = packbf_res(S[2*kc+1][2], S[2*kc+1][3], ah3);
#pragma unroll
            for (int nf = 0; nf < 8; nf++) {
                uint32_t b0 = Vs[(nf * 8 + g4) * 36 + kc * 8 + t4    ];
                uint32_t b1 = Vs[(nf * 8 + g4) * 36 + kc * 8 + t4 + 4];
                mma_bf16(O[nf], ah0, ah1, ah2, ah3, b0, b1);
                mma_bf16(O[nf], al0, al1, al2, al3, b0, b1);
            }
        }
    }

    const float inv0 = 1.0f / l0, inv1 = 1.0f / l1;
    const int row0 = s0q + wm + g4;
#pragma unroll
    for (int nf = 0; nf < 8; nf++) {
        const int col = hh * HDIM + nf * 8 + t4 * 2;
        *(uint32_t*)(attnb + (long)row0 * DM + col) =
            packbf(O[nf][0] * inv0, O[nf][1] * inv0);
        *(uint32_t*)(attnb + (long)(row0 + 8) * DM + col) =
            packbf(O[nf][2] * inv1, O[nf][3] * inv1);
    }
}

// ---------------- embedding gather (fp32 + bf16 copies) ----------------
__global__ void embed_k(const int* __restrict__ x, const float* __restrict__ emb,
                        float* __restrict__ h, __nv_bfloat16* __restrict__ hb)
{
    int s = blockIdx.x;
    int t = threadIdx.x;
    float4 v = ((const float4*)(emb + (long)x[s] * DM))[t];
    ((float4*)(h + (long)s * DM))[t] = v;
    uint32_t* d = (uint32_t*)(hb + (long)s * DM) + t * 2;
    d[0] = packbf(v.x, v.y);
    d[1] = packbf(v.z, v.w);
}

// ---------------- merged RoPE + cosine-norm (Q and K) ----------------
__global__ void rope_norm_k(float* __restrict__ qkv, const float* __restrict__ sqk)
{
    int s = blockIdx.x, z = blockIdx.y;
    int j = threadIdx.x;
    float* base = qkv + (long)s * QKV + ((z < NH) ? z * HDIM : DM + (z - NH) * HDIM);
    float x1 = base[j], x2 = base[j + 32];

    float inv = powf(10000.0f, -(float)j / 32.0f);
    float ang = (float)s * inv;
    float sn, cs; sincosf(ang, &sn, &cs);
    float o1 = x1 * cs - x2 * sn;
    float o2 = x2 * cs + x1 * sn;

    float ss = o1 * o1 + o2 * o2;
#pragma unroll
    for (int off = 16; off > 0; off >>= 1)
        ss += __shfl_xor_sync(0xffffffffu, ss, off);
    float n = fmaxf(sqrtf(ss), 1e-6f);

    if (z < NH) {
        float e1 = sqk[z * HDIM + j]      * RTD;
        float e2 = sqk[z * HDIM + j + 32] * RTD;
        base[j]      = (o1 / n) * e1 * e1 * RTD;
        base[j + 32] = (o2 / n) * e2 * e2 * RTD;
    } else {
        base[j]      = o1 / n;
        base[j + 32] = o2 / n;
    }
}

// ---------------- residual lerp + cosine norm (writes fp32 + bf16) ----------------
__global__ void resid_norm_k(float* __restrict__ h, __nv_bfloat16* __restrict__ hb,
                             const float* __restrict__ t, const float* __restrict__ eig)
{
    int row = blockIdx.x;
    int tid = threadIdx.x;
    __shared__ float red[256];

    float4 tv = ((const float4*)(t + (long)row * DM))[tid];
    float ss = tv.x * tv.x + tv.y * tv.y + tv.z * tv.z + tv.w * tv.w;
    red[tid] = ss; __syncthreads();
    for (int o = 128; o > 0; o >>= 1) { if (tid < o) red[tid] += red[tid + o]; __syncthreads(); }
    float nt = fmaxf(sqrtf(red[0]), 1e-6f);
    __syncthreads();

    float4 hv = ((const float4*)(h + (long)row * DM))[tid];
    float4 ev = ((const float4*)eig)[tid];
    float4 r;
    r.x = hv.x + ev.x * RTDM * (tv.x / nt - hv.x);
    r.y = hv.y + ev.y * RTDM * (tv.y / nt - hv.y);
    r.z = hv.z + ev.z * RTDM * (tv.z / nt - hv.z);
    r.w = hv.w + ev.w * RTDM * (tv.w / nt - hv.w);

    float ss2 = r.x * r.x + r.y * r.y + r.z * r.z + r.w * r.w;
    red[tid] = ss2; __syncthreads();
    for (int o = 128; o > 0; o >>= 1) { if (tid < o) red[tid] += red[tid + o]; __syncthreads(); }
    float nr = fmaxf(sqrtf(red[0]), 1e-6f);

    r.x /= nr; r.y /= nr; r.z /= nr; r.w /= nr;
    ((float4*)(h + (long)row * DM))[tid] = r;
    uint32_t* d = (uint32_t*)(hb + (long)row * DM) + tid * 2;
    d[0] = packbf(r.x, r.y);
    d[1] = packbf(r.z, r.w);
}

// ---------------- final row softmax ----------------
__global__ void softmax_full_k(float* __restrict__ out)
{
    int row = blockIdx.x;
    float* p = out + (long)row * NV;
    int t = threadIdx.x;
    __shared__ float red[256];

    float m = -1e30f;
    for (int j = t; j < NV; j += 256) m = fmaxf(m, p[j]);
    red[t] = m; __syncthreads();
    for (int o = 128; o > 0; o >>= 1) { if (t < o) red[t] = fmaxf(red[t], red[t + o]); __syncthreads(); }
    m = red[0]; __syncthreads();

    float sum = 0.0f;
    for (int j = t; j < NV; j += 256) { float e = __expf(p[j] - m); p[j] = e; sum += e; }
    red[t] = sum; __syncthreads();
    for (int o = 128; o > 0; o >>= 1) { if (t < o) red[t] += red[t + o]; __syncthreads(); }
    float invs = 1.0f / red[0];

    for (int j = t; j < NV; j += 256) p[j] *= invs;
}

// ---------------- host-side launchers ----------------
static void gemm128(const __nv_bfloat16* A, const __nv_bfloat16* B, float* C,
                    int M, int N, int K, int lda, int ldb, int ldc,
                    float alpha, const float* bias, const float* scalev, float beta)
{
    dim3 grid(N / 128, M / 128);
    bf16_gemm_k<128, 8, 0><<<grid, 256>>>(A, B, C, K, lda, ldb, ldc, alpha, bias, scalev, beta);
}
static void gemm64(const __nv_bfloat16* A, const __nv_bfloat16* B, float* C,
                   int M, int N, int K, int lda, int ldb, int ldc,
                   float alpha, const float* bias, const float* scalev, float beta)
{
    dim3 grid(N / 128, M / 64);
    bf16_gemm_k<64, 4, 0><<<grid, 256>>>(A, B, C, K, lda, ldb, ldc, alpha, bias, scalev, beta);
}
static void gemm_swiglu(const __nv_bfloat16* A, const __nv_bfloat16* B, __nv_bfloat16* C,
                        int M, int N, int K, int lda, int ldb, int ldc,
                        const float* bias, const float* scalev)
{
    dim3 grid(N / 128, M / 128);
    bf16_gemm_k<128, 8, 1><<<grid, 256>>>(A, B, C, K, lda, ldb, ldc, 1.0f, bias, scalev, 1.0f);
}

extern "C" void kernel_launch(void* const* d_in, const int* in_sizes, int n_in,
                              void* d_out, int out_size)
{
    const int*   x      = (const int*)  d_in[0];
    const float* emb    = (const float*)d_in[1];
    const float* qw     = (const float*)d_in[2];
    const float* qb     = (const float*)d_in[3];
    const float* kw     = (const float*)d_in[4];
    const float* kb     = (const float*)d_in[5];
    const float* vw     = (const float*)d_in[6];
    const float* vb     = (const float*)d_in[7];
    const float* sqk    = (const float*)d_in[8];
    const float* ow     = (const float*)d_in[9];
    const float* ob     = (const float*)d_in[10];
    const float* w_in   = (const float*)d_in[11];
    const float* b_in   = (const float*)d_in[12];
    const float* w_gate = (const float*)d_in[13];
    const float* b_gate = (const float*)d_in[14];
    const float* w_out  = (const float*)d_in[15];
    const float* b_out  = (const float*)d_in[16];
    const float* s_u    = (const float*)d_in[17];
    const float* s_v    = (const float*)d_in[18];
    const float* eig_a  = (const float*)d_in[19];
    const float* eig_m  = (const float*)d_in[20];
    const float* out_w  = (const float*)d_in[21];
    const float* out_b  = (const float*)d_in[22];
    const float* s_z    = (const float*)d_in[23];
    float* out = (float*)d_out;

    float *h, *qkv, *t, *qkvb, *biog, *siog;
    __nv_bfloat16 *hb, *attnb, *ub, *qkvw, *wiog, *wout, *owb, *outwb;
    cudaGetSymbolAddress((void**)&h,     g_h);
    cudaGetSymbolAddress((void**)&qkv,   g_qkv);
    cudaGetSymbolAddress((void**)&t,     g_t);
    cudaGetSymbolAddress((void**)&qkvb,  g_qkvb);
    cudaGetSymbolAddress((void**)&biog,  g_biog);
    cudaGetSymbolAddress((void**)&siog,  g_siog);
    cudaGetSymbolAddress((void**)&hb,    g_hb);
    cudaGetSymbolAddress((void**)&attnb, g_attnb);
    cudaGetSymbolAddress((void**)&ub,    g_ub);
    cudaGetSymbolAddress((void**)&qkvw,  g_qkvw);
    cudaGetSymbolAddress((void**)&wiog,  g_wiog);
    cudaGetSymbolAddress((void**)&wout,  g_wout);
    cudaGetSymbolAddress((void**)&owb,   g_ow);
    cudaGetSymbolAddress((void**)&outwb, g_outw);

    // ---- one-time weight conversion to bf16 (fused / interleaved layouts) ----
    for (int i = 0; i < NL; i++) {
        __nv_bfloat16* w = qkvw + (long)i * QKV * DM;
        cvt(w,                         qw + (long)i * DM * DM,  (long)DM * DM);
        cvt(w + (long)DM * DM,         kw + (long)i * GHD * DM, (long)GHD * DM);
        cvt(w + (long)(DM + GHD) * DM, vw + (long)i * GHD * DM, (long)GHD * DM);

        float* b = qkvb + i * QKV;
        cudaMemcpyAsync(b,            qb + (long)i * DM,  sizeof(float) * DM,  cudaMemcpyDeviceToDevice);
        cudaMemcpyAsync(b + DM,       kb + (long)i * GHD, sizeof(float) * GHD, cudaMemcpyDeviceToDevice);
        cudaMemcpyAsync(b + DM + GHD, vb + (long)i * GHD, sizeof(float) * GHD, cudaMemcpyDeviceToDevice);
    }
    cvt_inter_k<<<(int)((long)NL * 2 * DFF * DM / 4096), 256>>>(wiog, w_in, w_gate);
    inter_bs_k<<<NL * DFF / 256, 256>>>(biog, siog, b_in, b_gate, s_u, s_v);
    cvt(owb,   ow,    (long)NL * DM * DM);
    cvt(wout,  w_out, (long)NL * DM * DFF);
    cvt(outwb, out_w, (long)NV * DM);

    embed_k<<<SQ, 256>>>(x, emb, h, hb);

    for (int i = 0; i < NL; i++) {
        // fused QKV projection
        gemm128(hb, qkvw + (long)i * QKV * DM, qkv, SQ, QKV, DM, DM, DM, QKV,
                1.0f, qkvb + i * QKV, nullptr, 0.0f);

        rope_norm_k<<<dim3(SQ, NH + NG), 32>>>(qkv, sqk + (long)i * NH * HDIM);

        flash_attn_k<<<dim3(SQ / 128, NH), 256>>>(qkv, attnb);

        gemm64(attnb, owb + (long)i * DM * DM, t, SQ, DM, DM, DM, DM, DM,
               1.0f, ob + (long)i * DM, nullptr, 0.0f);
        resid_norm_k<<<SQ, 256>>>(h, hb, t, eig_a + (long)i * DM);

        // fused in+gate GEMM with swiglu epilogue -> ub (bf16)
        gemm_swiglu(hb, wiog + (long)i * 2 * DFF * DM, ub, SQ, 2 * DFF, DM, DM, DM, DFF,
                    biog + (long)i * 2 * DFF, siog + (long)i * 2 * DFF);
        gemm64(ub, wout + (long)i * DM * DFF, t, SQ, DM, DFF, DFF, DFF, DM,
               1.0f, b_out + (long)i * DM, nullptr, 0.0f);
        resid_norm_k<<<SQ, 256>>>(h, hb, t, eig_m + (long)i * DM);
    }

    gemm128(hb, outwb, out, SQ, NV, DM, DM, DM, NV,
            1.0f, out_b, s_z, RTDM);
    softmax_full_k<<<SQ, 256>>>(out);
}

// round 9
// speedup vs baseline: 4.5136x; 1.0468x over previous
#include <cuda_runtime.h>
#include <cuda_bf16.h>
#include <math.h>
#include <stdint.h>

// ---------------- problem dims (fixed) ----------------
#define SQ   1024
#define DM   1024
#define NH   16
#define NG   4
#define HDIM 64
#define HPG  4
#define GHD  256
#define NL   4
#define DFF  4096
#define NV   32000
#define QKV  1536      // DM + 2*GHD
#define RTD  8.0f
#define RTDM 32.0f

// ---------------- device scratch ----------------
__device__ float g_h   [SQ * DM];
__device__ float g_qkv [SQ * QKV];
__device__ float g_t   [SQ * DM];
__device__ float g_qkvb[NL * QKV];
__device__ float g_biog[NL * 2 * DFF];
__device__ float g_siog[NL * 2 * DFF];

__device__ __align__(16) __nv_bfloat16 g_hb   [SQ * DM];
__device__ __align__(16) __nv_bfloat16 g_attnb[SQ * DM];
__device__ __align__(16) __nv_bfloat16 g_ub   [SQ * DFF];
__device__ __align__(16) __nv_bfloat16 g_qkvw [(long)NL * QKV * DM];
__device__ __align__(16) __nv_bfloat16 g_wiog [(long)NL * 2 * DFF * DM];
__device__ __align__(16) __nv_bfloat16 g_wout [(long)NL * DM * DFF];
__device__ __align__(16) __nv_bfloat16 g_ow   [(long)NL * DM * DM];
__device__ __align__(16) __nv_bfloat16 g_outw [(long)NV * DM];

__device__ __forceinline__ uint32_t packbf(float x, float y) {
    __nv_bfloat162 t = __floats2bfloat162_rn(x, y);
    return *reinterpret_cast<uint32_t*>(&t);
}
__device__ __forceinline__ uint32_t packbf_res(float x, float y, uint32_t hi) {
    __nv_bfloat162 h = *reinterpret_cast<__nv_bfloat162*>(&hi);
    return packbf(x - __bfloat162float(h.x), y - __bfloat162float(h.y));
}

__device__ __forceinline__ void mma_bf16(float c[4], uint32_t a0, uint32_t a1,
                                         uint32_t a2, uint32_t a3,
                                         uint32_t b0, uint32_t b1) {
    asm volatile(
        "mma.sync.aligned.m16n8k16.row.col.f32.bf16.bf16.f32 "
        "{%0,%1,%2,%3}, {%4,%5,%6,%7}, {%8,%9}, {%0,%1,%2,%3};"
        : "+f"(c[0]), "+f"(c[1]), "+f"(c[2]), "+f"(c[3])
        : "r"(a0), "r"(a1), "r"(a2), "r"(a3), "r"(b0), "r"(b1));
}

__device__ __forceinline__ void ldsm4(uint32_t r[4], uint32_t addr) {
    asm volatile(
        "ldmatrix.sync.aligned.m8n8.x4.shared.b16 {%0,%1,%2,%3}, [%4];"
        : "=r"(r[0]), "=r"(r[1]), "=r"(r[2]), "=r"(r[3]) : "r"(addr));
}

// ================= mega weight-conversion kernel (single launch) =================
// Linear index space over uint2 (4 bf16) outputs + fp32 bias tails.
#define E_QKVW  1572864L                       // NL*QKV*DM/4
#define E_WIOG  8388608L                       // NL*2*DFF*DM/4
#define E_WOUT  4194304L                       // NL*DM*DFF/4
#define E_OW    1048576L                       // NL*DM*DM/4
#define E_OUTW  8192000L                       // NV*DM/4
#define CB0 (E_QKVW)
#define CB1 (CB0 + E_WIOG)
#define CB2 (CB1 + E_WOUT)
#define CB3 (CB2 + E_OW)
#define CB4 (CB3 + E_OUTW)
#define CB5 (CB4 + 1536L)                      // qkvb float4 units
#define CB6 (CB5 + 16384L)                     // bias/scale interleave units

__global__ void cvt_all_k(const float* __restrict__ qw, const float* __restrict__ kw,
                          const float* __restrict__ vw, const float* __restrict__ w_in,
                          const float* __restrict__ w_gate, const float* __restrict__ w_out,
                          const float* __restrict__ ow, const float* __restrict__ out_w,
                          const float* __restrict__ qb, const float* __restrict__ kb,
                          const float* __restrict__ vb, const float* __restrict__ b_in,
                          const float* __restrict__ b_gate, const float* __restrict__ s_u,
                          const float* __restrict__ s_v)
{
    for (long e = (long)blockIdx.x * 256 + threadIdx.x; e < CB6;
         e += (long)gridDim.x * 256) {
        if (e < CB0) {
            long t = e;
            int l = (int)(t / 393216L);                   // QKV*DM/4
            int rem = (int)(t - (long)l * 393216L);
            int row = rem >> 8, c4 = rem & 255;
            const float* src;
            if (row < DM)            src = qw + ((long)l * DM  + row)              * DM + c4 * 4;
            else if (row < DM + GHD) src = kw + ((long)l * GHD + row - DM)         * DM + c4 * 4;
            else                     src = vw + ((long)l * GHD + row - DM - GHD)   * DM + c4 * 4;
            float4 v = *(const float4*)src;
            ((uint2*)g_qkvw)[t] = make_uint2(packbf(v.x, v.y), packbf(v.z, v.w));
        } else if (e < CB1) {
            long t = e - CB0;
            int l = (int)(t >> 21);                       // 2*DFF*DM/4 = 2^21
            int rem = (int)(t & 2097151L);
            int r = rem >> 8, c4 = rem & 255;
            const float* src = ((r & 1) ? w_gate : w_in)
                             + ((long)l * DFF + (r >> 1)) * DM + c4 * 4;
            float4 v = *(const float4*)src;
            ((uint2*)g_wiog)[t] = make_uint2(packbf(v.x, v.y), packbf(v.z, v.w));
        } else if (e < CB2) {
            long t = e - CB1;
            float4 v = ((const float4*)w_out)[t];
            ((uint2*)g_wout)[t] = make_uint2(packbf(v.x, v.y), packbf(v.z, v.w));
        } else if (e < CB3) {
            long t = e - CB2;
            float4 v = ((const float4*)ow)[t];
            ((uint2*)g_ow)[t] = make_uint2(packbf(v.x, v.y), packbf(v.z, v.w));
        } else if (e < CB4) {
            long t = e - CB3;
            float4 v = ((const float4*)out_w)[t];
            ((uint2*)g_outw)[t] = make_uint2(packbf(v.x, v.y), packbf(v.z, v.w));
        } else if (e < CB5) {
            int t = (int)(e - CB4);                       // float4 units over NL*QKV
            int l = t / 384, f4 = (t % 384) * 4;
            float4 v;
            if (f4 < DM)            v = *(const float4*)(qb + (long)l * DM  + f4);
            else if (f4 < DM + GHD) v = *(const float4*)(kb + (long)l * GHD + f4 - DM);
            else                    v = *(const float4*)(vb + (long)l * GHD + f4 - DM - GHD);
            *(float4*)(g_qkvb + (long)l * QKV + f4) = v;
        } else {
            int t = (int)(e - CB5);                       // NL*DFF entries
            int l = t >> 12, f = t & (DFF - 1);
            g_biog[(long)l * 2 * DFF + 2 * f]     = b_in  [(long)l * DFF + f];
            g_biog[(long)l * 2 * DFF + 2 * f + 1] = b_gate[(long)l * DFF + f];
            g_siog[(long)l * 2 * DFF + 2 * f]     = s_u   [(long)l * DFF + f];
            g_siog[(long)l * 2 * DFF + 2 * f + 1] = s_v   [(long)l * DFF + f] * RTDM;
        }
    }
}

// ================= pure-bf16 TB GEMM, ldmatrix, single-sync mainloop =================
#define TASTR 20
#define TBW   (128 * TASTR)

template<int BMT, int NF, int EPI>
__global__ void __launch_bounds__(256, 2)
bf16_gemm_k(const __nv_bfloat16* __restrict__ A, const __nv_bfloat16* __restrict__ B,
            void* __restrict__ Cv, int K, int lda, int ldb, int ldc,
            float alpha, const float* __restrict__ bias,
            const float* __restrict__ scalev, float beta)
{
    constexpr int TAW = BMT * TASTR;
    __shared__ __align__(16) uint32_t As[2 * TAW];
    __shared__ __align__(16) uint32_t Bs[2 * TBW];

    const int bm = blockIdx.y * BMT;
    const int bn = blockIdx.x * 128;
    const int tid  = threadIdx.x;
    const int wid  = tid >> 5;
    const int lane = tid & 31;
    const int g4   = lane >> 2;
    const int t4   = lane & 3;
    const int wm   = (BMT == 128) ? (wid & 3) * 32 : (wid & 1) * 32;
    const int wn   = (BMT == 128) ? (wid >> 2) * 64 : (wid >> 1) * 32;

    const uint32_t asb = (uint32_t)__cvta_generic_to_shared(As);
    const uint32_t bsb = (uint32_t)__cvta_generic_to_shared(Bs);
    const uint32_t aFrag = asb + 4u * ((wm + (lane & 15)) * TASTR + (lane >> 4) * 4);
    const uint32_t bFrag = bsb + 4u * ((wn + (lane & 15)) * TASTR + (lane >> 4) * 4);

    const int rb_ = tid >> 1, hb_ = tid & 1;
    const int ra_ = (BMT == 128) ? (tid >> 1) : (tid >> 2);
    const int qa_ = (BMT == 128) ? (tid & 1)  : (tid & 3);

    uint4 ra[2], rb[2];

    auto ldg = [&](int k0) {
        if (BMT == 128) {
            const __nv_bfloat16* pa = A + (long)(bm + ra_) * lda + k0 + qa_ * 16;
            ra[0] = *(const uint4*)pa; ra[1] = *(const uint4*)(pa + 8);
        } else {
            const __nv_bfloat16* pa = A + (long)(bm + ra_) * lda + k0 + qa_ * 8;
            ra[0] = *(const uint4*)pa;
        }
        const __nv_bfloat16* pb = B + (long)(bn + rb_) * ldb + k0 + hb_ * 16;
        rb[0] = *(const uint4*)pb; rb[1] = *(const uint4*)(pb + 8);
    };
    auto sts = [&](int buf) {
        if (BMT == 128) {
            uint32_t* da = As + buf * TAW + ra_ * TASTR + qa_ * 8;
            *(uint4*)da = ra[0]; *(uint4*)(da + 4) = ra[1];
        } else {
            uint32_t* da = As + buf * TAW + ra_ * TASTR + qa_ * 4;
            *(uint4*)da = ra[0];
        }
        uint32_t* db = Bs + buf * TBW + rb_ * TASTR + hb_ * 8;
        *(uint4*)db = rb[0]; *(uint4*)(db + 4) = rb[1];
    };

    float acc[2][NF][4];
#pragma unroll
    for (int i = 0; i < 2; i++)
#pragma unroll
        for (int j = 0; j < NF; j++)
#pragma unroll
            for (int l = 0; l < 4; l++) acc[i][j][l] = 0.0f;

    // prologue: stage 0 resident before loop
    ldg(0);
    sts(0);
    __syncthreads();

    const int nsteps = K / 32;
    for (int ks = 0; ks < nsteps; ks++) {
        const bool more = (ks + 1 < nsteps);
        if (more) ldg((ks + 1) * 32);          // issue early; covered by MMAs

        const uint32_t aB = aFrag + (ks & 1) * TAW * 4;
        const uint32_t bB = bFrag + (ks & 1) * TBW * 4;

#pragma unroll
        for (int kh = 0; kh < 2; kh++) {
            uint32_t af[2][4];
            ldsm4(af[0], aB + 4u * (kh * 8));
            ldsm4(af[1], aB + 4u * (16 * TASTR + kh * 8));
#pragma unroll
            for (int bf = 0; bf < NF / 2; bf++) {
                uint32_t bb[4];
                ldsm4(bb, bB + 4u * (bf * 16 * TASTR + kh * 8));
                mma_bf16(acc[0][2*bf  ], af[0][0], af[0][1], af[0][2], af[0][3], bb[0], bb[2]);
                mma_bf16(acc[1][2*bf  ], af[1][0], af[1][1], af[1][2], af[1][3], bb[0], bb[2]);
                mma_bf16(acc[0][2*bf+1], af[0][0], af[0][1], af[0][2], af[0][3], bb[1], bb[3]);
                mma_bf16(acc[1][2*bf+1], af[1][0], af[1][1], af[1][2], af[1][3], bb[1], bb[3]);
            }
        }

        if (more) sts((ks + 1) & 1);           // writes the OTHER buffer — no hazard
        __syncthreads();                       // single barrier per step
    }

#pragma unroll
    for (int mf = 0; mf < 2; mf++) {
#pragma unroll
        for (int nf = 0; nf < NF; nf++) {
            const int row = bm + wm + mf * 16 + g4;
            const int col = bn + wn + nf * 8 + t4 * 2;
            if (EPI == 0) {
                float* C = (float*)Cv;
                float v0 = acc[mf][nf][0] * alpha;
                float v1 = acc[mf][nf][1] * alpha;
                float v2 = acc[mf][nf][2] * alpha;
                float v3 = acc[mf][nf][3] * alpha;
                if (bias) {
                    float b0 = bias[col], b1 = bias[col + 1];
                    v0 += b0; v1 += b1; v2 += b0; v3 += b1;
                }
                if (scalev) {
                    float s0 = scalev[col] * beta, s1 = scalev[col + 1] * beta;
                    v0 *= s0; v1 *= s1; v2 *= s0; v3 *= s1;
                }
                *(float2*)(C + (long)row * ldc + col)       = make_float2(v0, v1);
                *(float2*)(C + (long)(row + 8) * ldc + col) = make_float2(v2, v3);
            } else {
                __nv_bfloat16* C = (__nv_bfloat16*)Cv;
                const float b0 = bias[col], b1 = bias[col + 1];
                const float s0 = scalev[col], s1 = scalev[col + 1];
                const int f = col >> 1;
                {
                    float u = (acc[mf][nf][0] + b0) * s0;
                    float g = (acc[mf][nf][1] + b1) * s1;
                    C[(long)row * ldc + f] = __float2bfloat16(u * g / (1.0f + __expf(-g)));
                }
                {
                    float u = (acc[mf][nf][2] + b0) * s0;
                    float g = (acc[mf][nf][3] + b1) * s1;
                    C[(long)(row + 8) * ldc + f] = __float2bfloat16(u * g / (1.0f + __expf(-g)));
                }
            }
        }
    }
}

// ================= fused flash attention (bf16 output) =================
__global__ void __launch_bounds__(256)
flash_attn_k(const float* __restrict__ qkv, __nv_bfloat16* __restrict__ attnb)
{
    __shared__ uint32_t Qs[128 * 36];
    __shared__ uint32_t Ks[64 * 36];
    __shared__ uint32_t Vs[64 * 36];

    const int qb = blockIdx.x;
    const int hh = blockIdx.y;
    const int gg = hh >> 2;
    const int qcol = hh * HDIM;
    const int kcol = DM + gg * HDIM;
    const int vcol = DM + GHD + gg * HDIM;

    const int tid  = threadIdx.x;
    const int wid  = tid >> 5;
    const int lane = tid & 31;
    const int g4   = lane >> 2;
    const int t4   = lane & 3;
    const int wm   = wid * 16;
    const int s0q  = qb * 128;

    {
        int r = tid >> 1, half = tid & 1;
        const float* src = qkv + (long)(s0q + r) * QKV + qcol + half * 32;
        uint32_t* dst = Qs + r * 36 + half * 16;
#pragma unroll
        for (int i = 0; i < 8; i++) {
            float4 v = *(const float4*)(src + i * 4);
            dst[2 * i]     = packbf(v.x, v.y);
            dst[2 * i + 1] = packbf(v.z, v.w);
        }
    }

    float O[8][4];
#pragma unroll
    for (int j = 0; j < 8; j++)
#pragma unroll
        for (int l = 0; l < 4; l++) O[j][l] = 0.0f;
    float m0 = -1e30f, m1 = -1e30f, l0 = 0.0f, l1 = 0.0f;

    const int nblk = 2 * qb + 2;
    for (int jb = 0; jb < nblk; jb++) {
        const int s0 = jb * 64;
        __syncthreads();

        {
            int r = tid >> 2, q4 = tid & 3;
            const float* src = qkv + (long)(s0 + r) * QKV + kcol + q4 * 16;
            uint32_t* dst = Ks + r * 36 + q4 * 8;
#pragma unroll
            for (int i = 0; i < 4; i++) {
                float4 v = *(const float4*)(src + i * 4);
                dst[2 * i]     = packbf(v.x, v.y);
                dst[2 * i + 1] = packbf(v.z, v.w);
            }
        }
        {
            int d = tid & 63, sb = tid >> 6;
#pragma unroll
            for (int i = 0; i < 8; i++) {
                int sp = sb * 8 + i;
                const float* p0 = qkv + (long)(s0 + 2 * sp) * QKV + vcol + d;
                Vs[d * 36 + sp] = packbf(p0[0], p0[QKV]);
            }
        }
        __syncthreads();

        float S[8][4];
#pragma unroll
        for (int j = 0; j < 8; j++)
#pragma unroll
            for (int l = 0; l < 4; l++) S[j][l] = 0.0f;

#pragma unroll
        for (int kc = 0; kc < 4; kc++) {
            uint32_t a0 = Qs[(wm + g4    ) * 36 + kc * 8 + t4    ];
            uint32_t a1 = Qs[(wm + g4 + 8) * 36 + kc * 8 + t4    ];
            uint32_t a2 = Qs[(wm + g4    ) * 36 + kc * 8 + t4 + 4];
            uint32_t a3 = Qs[(wm + g4 + 8) * 36 + kc * 8 + t4 + 4];
#pragma unroll
            for (int nf = 0; nf < 8; nf++) {
                uint32_t b0 = Ks[(nf * 8 + g4) * 36 + kc * 8 + t4    ];
                uint32_t b1 = Ks[(nf * 8 + g4) * 36 + kc * 8 + t4 + 4];
                mma_bf16(S[nf], a0, a1, a2, a3, b0, b1);
            }
        }

        if (jb >= 2 * qb) {
            const int r0 = s0q + wm + g4, r1 = r0 + 8;
#pragma unroll
            for (int nf = 0; nf < 8; nf++) {
                const int c = s0 + nf * 8 + t4 * 2;
                if (c     > r0) S[nf][0] = -1e30f;
                if (c + 1 > r0) S[nf][1] = -1e30f;
                if (c     > r1) S[nf][2] = -1e30f;
                if (c + 1 > r1) S[nf][3] = -1e30f;
            }
        }

        float bm0 = -1e30f, bm1 = -1e30f;
#pragma unroll
        for (int nf = 0; nf < 8; nf++) {
            bm0 = fmaxf(bm0, fmaxf(S[nf][0], S[nf][1]));
            bm1 = fmaxf(bm1, fmaxf(S[nf][2], S[nf][3]));
        }
        bm0 = fmaxf(bm0, __shfl_xor_sync(0xffffffffu, bm0, 1));
        bm0 = fmaxf(bm0, __shfl_xor_sync(0xffffffffu, bm0, 2));
        bm1 = fmaxf(bm1, __shfl_xor_sync(0xffffffffu, bm1, 1));
        bm1 = fmaxf(bm1, __shfl_xor_sync(0xffffffffu, bm1, 2));

        float nm0 = fmaxf(m0, bm0), nm1 = fmaxf(m1, bm1);
        float sc0 = __expf(m0 - nm0), sc1 = __expf(m1 - nm1);
        m0 = nm0; m1 = nm1;

        float ps0 = 0.0f, ps1 = 0.0f;
#pragma unroll
        for (int nf = 0; nf < 8; nf++) {
            S[nf][0] = __expf(S[nf][0] - m0);
            S[nf][1] = __expf(S[nf][1] - m0);
            S[nf][2] = __expf(S[nf][2] - m1);
            S[nf][3] = __expf(S[nf][3] - m1);
            ps0 += S[nf][0] + S[nf][1];
            ps1 += S[nf][2] + S[nf][3];
        }
        ps0 += __shfl_xor_sync(0xffffffffu, ps0, 1);
        ps0 += __shfl_xor_sync(0xffffffffu, ps0, 2);
        ps1 += __shfl_xor_sync(0xffffffffu, ps1, 1);
        ps1 += __shfl_xor_sync(0xffffffffu, ps1, 2);
        l0 = l0 * sc0 + ps0;
        l1 = l1 * sc1 + ps1;

#pragma unroll
        for (int nf = 0; nf < 8; nf++) {
            O[nf][0] *= sc0; O[nf][1] *= sc0;
            O[nf][2] *= sc1; O[nf][3] *= sc1;
        }

#pragma unroll
        for (int kc = 0; kc < 4; kc++) {
            uint32_t ah0 = packbf(S[2*kc  ][0], S[2*kc  ][1]);
            uint32_t ah1 = packbf(S[2*kc  ][2], S[2*kc  ][3]);
            uint32_t ah2 = packbf(S[2*kc+1][0], S[2*kc+1][1]);
            uint32_t ah3 = packbf(S[2*kc+1][2], S[2*kc+1][3]);
            uint32_t al0 = packbf_res(S[2*kc  ][0], S[2*kc  ][1], ah0);
            uint32_t al1 = packbf_res(S[2*kc  ][2], S[2*kc  ][3], ah1);
            uint32_t al2 = packbf_res(S[2*kc+1][0], S[2*kc+1][1], ah2);
            uint32_t al3 = packbf_res(S[2*kc+1][2], S[2*kc+1][3], ah3);
#pragma unroll
            for (int nf = 0; nf < 8; nf++) {
                uint32_t b0 = Vs[(nf * 8 + g4) * 36 + kc * 8 + t4    ];
                uint32_t b1 = Vs[(nf * 8 + g4) * 36 + kc * 8 + t4 + 4];
                mma_bf16(O[nf], ah0, ah1, ah2, ah3, b0, b1);
                mma_bf16(O[nf], al0, al1, al2, al3, b0, b1);
            }
        }
    }

    const float inv0 = 1.0f / l0, inv1 = 1.0f / l1;
    const int row0 = s0q + wm + g4;
#pragma unroll
    for (int nf = 0; nf < 8; nf++) {
        const int col = hh * HDIM + nf * 8 + t4 * 2;
        *(uint32_t*)(attnb + (long)row0 * DM + col) =
            packbf(O[nf][0] * inv0, O[nf][1] * inv0);
        *(uint32_t*)(attnb + (long)(row0 + 8) * DM + col) =
            packbf(O[nf][2] * inv1, O[nf][3] * inv1);
    }
}

// ---------------- embedding gather (fp32 + bf16 copies) ----------------
__global__ void embed_k(const int* __restrict__ x, const float* __restrict__ emb,
                        float* __restrict__ h, __nv_bfloat16* __restrict__ hb)
{
    int s = blockIdx.x;
    int t = threadIdx.x;
    float4 v = ((const float4*)(emb + (long)x[s] * DM))[t];
    ((float4*)(h + (long)s * DM))[t] = v;
    uint32_t* d = (uint32_t*)(hb + (long)s * DM) + t * 2;
    d[0] = packbf(v.x, v.y);
    d[1] = packbf(v.z, v.w);
}

// ---------------- merged RoPE + cosine-norm (Q and K) ----------------
__global__ void rope_norm_k(float* __restrict__ qkv, const float* __restrict__ sqk)
{
    int s = blockIdx.x, z = blockIdx.y;
    int j = threadIdx.x;
    float* base = qkv + (long)s * QKV + ((z < NH) ? z * HDIM : DM + (z - NH) * HDIM);
    float x1 = base[j], x2 = base[j + 32];

    float inv = powf(10000.0f, -(float)j / 32.0f);
    float ang = (float)s * inv;
    float sn, cs; sincosf(ang, &sn, &cs);
    float o1 = x1 * cs - x2 * sn;
    float o2 = x2 * cs + x1 * sn;

    float ss = o1 * o1 + o2 * o2;
#pragma unroll
    for (int off = 16; off > 0; off >>= 1)
        ss += __shfl_xor_sync(0xffffffffu, ss, off);
    float n = fmaxf(sqrtf(ss), 1e-6f);

    if (z < NH) {
        float e1 = sqk[z * HDIM + j]      * RTD;
        float e2 = sqk[z * HDIM + j + 32] * RTD;
        base[j]      = (o1 / n) * e1 * e1 * RTD;
        base[j + 32] = (o2 / n) * e2 * e2 * RTD;
    } else {
        base[j]      = o1 / n;
        base[j + 32] = o2 / n;
    }
}

// ---------------- residual lerp + cosine norm (writes fp32 + bf16) ----------------
__global__ void resid_norm_k(float* __restrict__ h, __nv_bfloat16* __restrict__ hb,
                             const float* __restrict__ t, const float* __restrict__ eig)
{
    int row = blockIdx.x;
    int tid = threadIdx.x;
    __shared__ float red[256];

    float4 tv = ((const float4*)(t + (long)row * DM))[tid];
    float ss = tv.x * tv.x + tv.y * tv.y + tv.z * tv.z + tv.w * tv.w;
    red[tid] = ss; __syncthreads();
    for (int o = 128; o > 0; o >>= 1) { if (tid < o) red[tid] += red[tid + o]; __syncthreads(); }
    float nt = fmaxf(sqrtf(red[0]), 1e-6f);
    __syncthreads();

    float4 hv = ((const float4*)(h + (long)row * DM))[tid];
    float4 ev = ((const float4*)eig)[tid];
    float4 r;
    r.x = hv.x + ev.x * RTDM * (tv.x / nt - hv.x);
    r.y = hv.y + ev.y * RTDM * (tv.y / nt - hv.y);
    r.z = hv.z + ev.z * RTDM * (tv.z / nt - hv.z);
    r.w = hv.w + ev.w * RTDM * (tv.w / nt - hv.w);

    float ss2 = r.x * r.x + r.y * r.y + r.z * r.z + r.w * r.w;
    red[tid] = ss2; __syncthreads();
    for (int o = 128; o > 0; o >>= 1) { if (tid < o) red[tid] += red[tid + o]; __syncthreads(); }
    float nr = fmaxf(sqrtf(red[0]), 1e-6f);

    r.x /= nr; r.y /= nr; r.z /= nr; r.w /= nr;
    ((float4*)(h + (long)row * DM))[tid] = r;
    uint32_t* d = (uint32_t*)(hb + (long)row * DM) + tid * 2;
    d[0] = packbf(r.x, r.y);
    d[1] = packbf(r.z, r.w);
}

// ---------------- final row softmax ----------------
__global__ void softmax_full_k(float* __restrict__ out)
{
    int row = blockIdx.x;
    float* p = out + (long)row * NV;
    int t = threadIdx.x;
    __shared__ float red[256];

    float m = -1e30f;
    for (int j = t; j < NV; j += 256) m = fmaxf(m, p[j]);
    red[t] = m; __syncthreads();
    for (int o = 128; o > 0; o >>= 1) { if (t < o) red[t] = fmaxf(red[t], red[t + o]); __syncthreads(); }
    m = red[0]; __syncthreads();

    float sum = 0.0f;
    for (int j = t; j < NV; j += 256) { float e = __expf(p[j] - m); p[j] = e; sum += e; }
    red[t] = sum; __syncthreads();
    for (int o = 128; o > 0; o >>= 1) { if (t < o) red[t] += red[t + o]; __syncthreads(); }
    float invs = 1.0f / red[0];

    for (int j = t; j < NV; j += 256) p[j] *= invs;
}

// ---------------- host-side launchers ----------------
static void gemm128(const __nv_bfloat16* A, const __nv_bfloat16* B, float* C,
                    int M, int N, int K, int lda, int ldb, int ldc,
                    float alpha, const float* bias, const float* scalev, float beta)
{
    dim3 grid(N / 128, M / 128);
    bf16_gemm_k<128, 8, 0><<<grid, 256>>>(A, B, C, K, lda, ldb, ldc, alpha, bias, scalev, beta);
}
static void gemm64(const __nv_bfloat16* A, const __nv_bfloat16* B, float* C,
                   int M, int N, int K, int lda, int ldb, int ldc,
                   float alpha, const float* bias, const float* scalev, float beta)
{
    dim3 grid(N / 128, M / 64);
    bf16_gemm_k<64, 4, 0><<<grid, 256>>>(A, B, C, K, lda, ldb, ldc, alpha, bias, scalev, beta);
}
static void gemm_swiglu(const __nv_bfloat16* A, const __nv_bfloat16* B, __nv_bfloat16* C,
                        int M, int N, int K, int lda, int ldb, int ldc,
                        const float* bias, const float* scalev)
{
    dim3 grid(N / 128, M / 128);
    bf16_gemm_k<128, 8, 1><<<grid, 256>>>(A, B, C, K, lda, ldb, ldc, 1.0f, bias, scalev, 1.0f);
}

extern "C" void kernel_launch(void* const* d_in, const int* in_sizes, int n_in,
                              void* d_out, int out_size)
{
    const int*   x      = (const int*)  d_in[0];
    const float* emb    = (const float*)d_in[1];
    const float* qw     = (const float*)d_in[2];
    const float* qb     = (const float*)d_in[3];
    const float* kw     = (const float*)d_in[4];
    const float* kb     = (const float*)d_in[5];
    const float* vw     = (const float*)d_in[6];
    const float* vb     = (const float*)d_in[7];
    const float* sqk    = (const float*)d_in[8];
    const float* ow     = (const float*)d_in[9];
    const float* ob     = (const float*)d_in[10];
    const float* w_in   = (const float*)d_in[11];
    const float* b_in   = (const float*)d_in[12];
    const float* w_gate = (const float*)d_in[13];
    const float* b_gate = (const float*)d_in[14];
    const float* w_out  = (const float*)d_in[15];
    const float* b_out  = (const float*)d_in[16];
    const float* s_u    = (const float*)d_in[17];
    const float* s_v    = (const float*)d_in[18];
    const float* eig_a  = (const float*)d_in[19];
    const float* eig_m  = (const float*)d_in[20];
    const float* out_w  = (const float*)d_in[21];
    const float* out_b  = (const float*)d_in[22];
    const float* s_z    = (const float*)d_in[23];
    float* out = (float*)d_out;

    float *h, *qkv, *t, *qkvb, *biog, *siog;
    __nv_bfloat16 *hb, *attnb, *ub, *qkvw, *wiog, *wout, *owb, *outwb;
    cudaGetSymbolAddress((void**)&h,     g_h);
    cudaGetSymbolAddress((void**)&qkv,   g_qkv);
    cudaGetSymbolAddress((void**)&t,     g_t);
    cudaGetSymbolAddress((void**)&qkvb,  g_qkvb);
    cudaGetSymbolAddress((void**)&biog,  g_biog);
    cudaGetSymbolAddress((void**)&siog,  g_siog);
    cudaGetSymbolAddress((void**)&hb,    g_hb);
    cudaGetSymbolAddress((void**)&attnb, g_attnb);
    cudaGetSymbolAddress((void**)&ub,    g_ub);
    cudaGetSymbolAddress((void**)&qkvw,  g_qkvw);
    cudaGetSymbolAddress((void**)&wiog,  g_wiog);
    cudaGetSymbolAddress((void**)&wout,  g_wout);
    cudaGetSymbolAddress((void**)&owb,   g_ow);
    cudaGetSymbolAddress((void**)&outwb, g_outw);

    // ---- single-launch weight conversion + layout assembly ----
    cvt_all_k<<<8192, 256>>>(qw, kw, vw, w_in, w_gate, w_out, ow, out_w,
                             qb, kb, vb, b_in, b_gate, s_u, s_v);

    embed_k<<<SQ, 256>>>(x, emb, h, hb);

    for (int i = 0; i < NL; i++) {
        gemm128(hb, qkvw + (long)i * QKV * DM, qkv, SQ, QKV, DM, DM, DM, QKV,
                1.0f, qkvb + i * QKV, nullptr, 0.0f);

        rope_norm_k<<<dim3(SQ, NH + NG), 32>>>(qkv, sqk + (long)i * NH * HDIM);

        flash_attn_k<<<dim3(SQ / 128, NH), 256>>>(qkv, attnb);

        gemm64(attnb, owb + (long)i * DM * DM, t, SQ, DM, DM, DM, DM, DM,
               1.0f, ob + (long)i * DM, nullptr, 0.0f);
        resid_norm_k<<<SQ, 256>>>(h, hb, t, eig_a + (long)i * DM);

        gemm_swiglu(hb, wiog + (long)i * 2 * DFF * DM, ub, SQ, 2 * DFF, DM, DM, DM, DFF,
                    biog + (long)i * 2 * DFF, siog + (long)i * 2 * DFF);
        gemm64(ub, wout + (long)i * DM * DFF, t, SQ, DM, DFF, DFF, DFF, DM,
               1.0f, b_out + (long)i * DM, nullptr, 0.0f);
        resid_norm_k<<<SQ, 256>>>(h, hb, t, eig_m + (long)i * DM);
    }

    gemm128(hb, outwb, out, SQ, NV, DM, DM, DM, NV,
            1.0f, out_b, s_z, RTDM);
    softmax_full_k<<<SQ, 256>>>(out);
}

// round 10
// speedup vs baseline: 4.8023x; 1.0639x over previous
#include <cuda_runtime.h>
#include <cuda_bf16.h>
#include <math.h>
#include <stdint.h>

// ---------------- problem dims (fixed) ----------------
#define SQ   1024
#define DM   1024
#define NH   16
#define NG   4
#define HDIM 64
#define HPG  4
#define GHD  256
#define NL   4
#define DFF  4096
#define NV   32000
#define QKV  1536      // DM + 2*GHD
#define RTD  8.0f
#define RTDM 32.0f

// ---------------- device scratch ----------------
__device__ float g_h   [SQ * DM];
__device__ float g_qkv [SQ * QKV];
__device__ float g_t   [SQ * DM];
__device__ float g_qkvb[NL * QKV];
__device__ float g_biog[NL * 2 * DFF];
__device__ float g_siog[NL * 2 * DFF];

__device__ __align__(16) __nv_bfloat16 g_hb   [SQ * DM];
__device__ __align__(16) __nv_bfloat16 g_attnb[SQ * DM];
__device__ __align__(16) __nv_bfloat16 g_ub   [SQ * DFF];
__device__ __align__(16) __nv_bfloat16 g_qkvw [(long)NL * QKV * DM];
__device__ __align__(16) __nv_bfloat16 g_wiog [(long)NL * 2 * DFF * DM];
__device__ __align__(16) __nv_bfloat16 g_wout [(long)NL * DM * DFF];
__device__ __align__(16) __nv_bfloat16 g_ow   [(long)NL * DM * DM];
__device__ __align__(16) __nv_bfloat16 g_outw [(long)NV * DM];

__device__ __forceinline__ uint32_t packbf(float x, float y) {
    __nv_bfloat162 t = __floats2bfloat162_rn(x, y);
    return *reinterpret_cast<uint32_t*>(&t);
}
__device__ __forceinline__ uint32_t packbf_res(float x, float y, uint32_t hi) {
    __nv_bfloat162 h = *reinterpret_cast<__nv_bfloat162*>(&hi);
    return packbf(x - __bfloat162float(h.x), y - __bfloat162float(h.y));
}

__device__ __forceinline__ void mma_bf16(float c[4], uint32_t a0, uint32_t a1,
                                         uint32_t a2, uint32_t a3,
                                         uint32_t b0, uint32_t b1) {
    asm volatile(
        "mma.sync.aligned.m16n8k16.row.col.f32.bf16.bf16.f32 "
        "{%0,%1,%2,%3}, {%4,%5,%6,%7}, {%8,%9}, {%0,%1,%2,%3};"
        : "+f"(c[0]), "+f"(c[1]), "+f"(c[2]), "+f"(c[3])
        : "r"(a0), "r"(a1), "r"(a2), "r"(a3), "r"(b0), "r"(b1));
}

__device__ __forceinline__ void ldsm4(uint32_t r[4], uint32_t addr) {
    asm volatile(
        "ldmatrix.sync.aligned.m8n8.x4.shared.b16 {%0,%1,%2,%3}, [%4];"
        : "=r"(r[0]), "=r"(r[1]), "=r"(r[2]), "=r"(r[3]) : "r"(addr));
}

// ================= mega weight-conversion kernel (single launch) =================
#define E_QKVW  1572864L
#define E_WIOG  8388608L
#define E_WOUT  4194304L
#define E_OW    1048576L
#define E_OUTW  8192000L
#define CB0 (E_QKVW)
#define CB1 (CB0 + E_WIOG)
#define CB2 (CB1 + E_WOUT)
#define CB3 (CB2 + E_OW)
#define CB4 (CB3 + E_OUTW)
#define CB5 (CB4 + 1536L)
#define CB6 (CB5 + 16384L)

__global__ void cvt_all_k(const float* __restrict__ qw, const float* __restrict__ kw,
                          const float* __restrict__ vw, const float* __restrict__ w_in,
                          const float* __restrict__ w_gate, const float* __restrict__ w_out,
                          const float* __restrict__ ow, const float* __restrict__ out_w,
                          const float* __restrict__ qb, const float* __restrict__ kb,
                          const float* __restrict__ vb, const float* __restrict__ b_in,
                          const float* __restrict__ b_gate, const float* __restrict__ s_u,
                          const float* __restrict__ s_v)
{
    for (long e = (long)blockIdx.x * 256 + threadIdx.x; e < CB6;
         e += (long)gridDim.x * 256) {
        if (e < CB0) {
            long t = e;
            int l = (int)(t / 393216L);
            int rem = (int)(t - (long)l * 393216L);
            int row = rem >> 8, c4 = rem & 255;
            const float* src;
            if (row < DM)            src = qw + ((long)l * DM  + row)            * DM + c4 * 4;
            else if (row < DM + GHD) src = kw + ((long)l * GHD + row - DM)       * DM + c4 * 4;
            else                     src = vw + ((long)l * GHD + row - DM - GHD) * DM + c4 * 4;
            float4 v = *(const float4*)src;
            ((uint2*)g_qkvw)[t] = make_uint2(packbf(v.x, v.y), packbf(v.z, v.w));
        } else if (e < CB1) {
            long t = e - CB0;
            int l = (int)(t >> 21);
            int rem = (int)(t & 2097151L);
            int r = rem >> 8, c4 = rem & 255;
            const float* src = ((r & 1) ? w_gate : w_in)
                             + ((long)l * DFF + (r >> 1)) * DM + c4 * 4;
            float4 v = *(const float4*)src;
            ((uint2*)g_wiog)[t] = make_uint2(packbf(v.x, v.y), packbf(v.z, v.w));
        } else if (e < CB2) {
            long t = e - CB1;
            float4 v = ((const float4*)w_out)[t];
            ((uint2*)g_wout)[t] = make_uint2(packbf(v.x, v.y), packbf(v.z, v.w));
        } else if (e < CB3) {
            long t = e - CB2;
            float4 v = ((const float4*)ow)[t];
            ((uint2*)g_ow)[t] = make_uint2(packbf(v.x, v.y), packbf(v.z, v.w));
        } else if (e < CB4) {
            long t = e - CB3;
            float4 v = ((const float4*)out_w)[t];
            ((uint2*)g_outw)[t] = make_uint2(packbf(v.x, v.y), packbf(v.z, v.w));
        } else if (e < CB5) {
            int t = (int)(e - CB4);
            int l = t / 384, f4 = (t % 384) * 4;
            float4 v;
            if (f4 < DM)            v = *(const float4*)(qb + (long)l * DM  + f4);
            else if (f4 < DM + GHD) v = *(const float4*)(kb + (long)l * GHD + f4 - DM);
            else                    v = *(const float4*)(vb + (long)l * GHD + f4 - DM - GHD);
            *(float4*)(g_qkvb + (long)l * QKV + f4) = v;
        } else {
            int t = (int)(e - CB5);
            int l = t >> 12, f = t & (DFF - 1);
            g_biog[(long)l * 2 * DFF + 2 * f]     = b_in  [(long)l * DFF + f];
            g_biog[(long)l * 2 * DFF + 2 * f + 1] = b_gate[(long)l * DFF + f];
            g_siog[(long)l * 2 * DFF + 2 * f]     = s_u   [(long)l * DFF + f];
            g_siog[(long)l * 2 * DFF + 2 * f + 1] = s_v   [(long)l * DFF + f] * RTDM;
        }
    }
}

// ================= pure-bf16 TB GEMM, ldmatrix, single-sync mainloop =================
// Tiles BMT x BN x 32, 256 threads.
// BMT=128 (BN=128): warps 4m x 2n. BMT=64: warps 2m x 4n, wn step BN/4.
#define TASTR 20

template<int BMT, int BN, int EPI>
__global__ void __launch_bounds__(256, 2)
bf16_gemm_k(const __nv_bfloat16* __restrict__ A, const __nv_bfloat16* __restrict__ B,
            void* __restrict__ Cv, int K, int lda, int ldb, int ldc,
            float alpha, const float* __restrict__ bias,
            const float* __restrict__ scalev, float beta)
{
    constexpr int NF  = (BMT == 128) ? (BN / 16) : (BN / 32);
    constexpr int TAW = BMT * TASTR;
    constexpr int TBW = BN * TASTR;
    __shared__ __align__(16) uint32_t As[2 * TAW];
    __shared__ __align__(16) uint32_t Bs[2 * TBW];

    const int bm = blockIdx.y * BMT;
    const int bn = blockIdx.x * BN;
    const int tid  = threadIdx.x;
    const int wid  = tid >> 5;
    const int lane = tid & 31;
    const int g4   = lane >> 2;
    const int t4   = lane & 3;
    const int wm   = (BMT == 128) ? (wid & 3) * 32 : (wid & 1) * 32;
    const int wn   = (BMT == 128) ? (wid >> 2) * 64 : (wid >> 1) * (BN / 4);

    const uint32_t asb = (uint32_t)__cvta_generic_to_shared(As);
    const uint32_t bsb = (uint32_t)__cvta_generic_to_shared(Bs);
    const uint32_t aFrag = asb + 4u * ((wm + (lane & 15)) * TASTR + (lane >> 4) * 4);
    const uint32_t bFrag = bsb + 4u * ((wn + (lane & 15)) * TASTR + (lane >> 4) * 4);

    const int ra_ = (BMT == 128) ? (tid >> 1) : (tid >> 2);
    const int qa_ = (BMT == 128) ? (tid & 1)  : (tid & 3);
    const int rb_ = (BN  == 128) ? (tid >> 1) : (tid >> 2);
    const int hb_ = (BN  == 128) ? (tid & 1)  : (tid & 3);

    uint4 ra[2], rb[2];

    auto ldg = [&](int k0) {
        if (BMT == 128) {
            const __nv_bfloat16* pa = A + (long)(bm + ra_) * lda + k0 + qa_ * 16;
            ra[0] = *(const uint4*)pa; ra[1] = *(const uint4*)(pa + 8);
        } else {
            const __nv_bfloat16* pa = A + (long)(bm + ra_) * lda + k0 + qa_ * 8;
            ra[0] = *(const uint4*)pa;
        }
        if (BN == 128) {
            const __nv_bfloat16* pb = B + (long)(bn + rb_) * ldb + k0 + hb_ * 16;
            rb[0] = *(const uint4*)pb; rb[1] = *(const uint4*)(pb + 8);
        } else {
            const __nv_bfloat16* pb = B + (long)(bn + rb_) * ldb + k0 + hb_ * 8;
            rb[0] = *(const uint4*)pb;
        }
    };
    auto sts = [&](int buf) {
        if (BMT == 128) {
            uint32_t* da = As + buf * TAW + ra_ * TASTR + qa_ * 8;
            *(uint4*)da = ra[0]; *(uint4*)(da + 4) = ra[1];
        } else {
            uint32_t* da = As + buf * TAW + ra_ * TASTR + qa_ * 4;
            *(uint4*)da = ra[0];
        }
        if (BN == 128) {
            uint32_t* db = Bs + buf * TBW + rb_ * TASTR + hb_ * 8;
            *(uint4*)db = rb[0]; *(uint4*)(db + 4) = rb[1];
        } else {
            uint32_t* db = Bs + buf * TBW + rb_ * TASTR + hb_ * 4;
            *(uint4*)db = rb[0];
        }
    };

    float acc[2][NF][4];
#pragma unroll
    for (int i = 0; i < 2; i++)
#pragma unroll
        for (int j = 0; j < NF; j++)
#pragma unroll
            for (int l = 0; l < 4; l++) acc[i][j][l] = 0.0f;

    ldg(0);
    sts(0);
    __syncthreads();

    const int nsteps = K / 32;
    for (int ks = 0; ks < nsteps; ks++) {
        const bool more = (ks + 1 < nsteps);
        if (more) ldg((ks + 1) * 32);

        const uint32_t aB = aFrag + (ks & 1) * TAW * 4;
        const uint32_t bB = bFrag + (ks & 1) * TBW * 4;

#pragma unroll
        for (int kh = 0; kh < 2; kh++) {
            uint32_t af[2][4];
            ldsm4(af[0], aB + 4u * (kh * 8));
            ldsm4(af[1], aB + 4u * (16 * TASTR + kh * 8));
#pragma unroll
            for (int bf = 0; bf < NF / 2; bf++) {
                uint32_t bb[4];
                ldsm4(bb, bB + 4u * (bf * 16 * TASTR + kh * 8));
                mma_bf16(acc[0][2*bf  ], af[0][0], af[0][1], af[0][2], af[0][3], bb[0], bb[2]);
                mma_bf16(acc[1][2*bf  ], af[1][0], af[1][1], af[1][2], af[1][3], bb[0], bb[2]);
                mma_bf16(acc[0][2*bf+1], af[0][0], af[0][1], af[0][2], af[0][3], bb[1], bb[3]);
                mma_bf16(acc[1][2*bf+1], af[1][0], af[1][1], af[1][2], af[1][3], bb[1], bb[3]);
            }
        }

        if (more) sts((ks + 1) & 1);
        __syncthreads();
    }

#pragma unroll
    for (int mf = 0; mf < 2; mf++) {
#pragma unroll
        for (int nf = 0; nf < NF; nf++) {
            const int row = bm + wm + mf * 16 + g4;
            const int col = bn + wn + nf * 8 + t4 * 2;
            if (EPI == 0) {
                float* C = (float*)Cv;
                float v0 = acc[mf][nf][0] * alpha;
                float v1 = acc[mf][nf][1] * alpha;
                float v2 = acc[mf][nf][2] * alpha;
                float v3 = acc[mf][nf][3] * alpha;
                if (bias) {
                    float b0 = bias[col], b1 = bias[col + 1];
                    v0 += b0; v1 += b1; v2 += b0; v3 += b1;
                }
                if (scalev) {
                    float s0 = scalev[col] * beta, s1 = scalev[col + 1] * beta;
                    v0 *= s0; v1 *= s1; v2 *= s0; v3 *= s1;
                }
                *(float2*)(C + (long)row * ldc + col)       = make_float2(v0, v1);
                *(float2*)(C + (long)(row + 8) * ldc + col) = make_float2(v2, v3);
            } else {
                __nv_bfloat16* C = (__nv_bfloat16*)Cv;
                const float b0 = bias[col], b1 = bias[col + 1];
                const float s0 = scalev[col], s1 = scalev[col + 1];
                const int f = col >> 1;
                {
                    float u = (acc[mf][nf][0] + b0) * s0;
                    float g = (acc[mf][nf][1] + b1) * s1;
                    C[(long)row * ldc + f] = __float2bfloat16(u * g / (1.0f + __expf(-g)));
                }
                {
                    float u = (acc[mf][nf][2] + b0) * s0;
                    float g = (acc[mf][nf][3] + b1) * s1;
                    C[(long)(row + 8) * ldc + f] = __float2bfloat16(u * g / (1.0f + __expf(-g)));
                }
            }
        }
    }
}

// ================= fused flash attention (bf16 output) =================
__global__ void __launch_bounds__(256)
flash_attn_k(const float* __restrict__ qkv, __nv_bfloat16* __restrict__ attnb)
{
    __shared__ uint32_t Qs[128 * 36];
    __shared__ uint32_t Ks[64 * 36];
    __shared__ uint32_t Vs[64 * 36];

    const int qb = blockIdx.x;
    const int hh = blockIdx.y;
    const int gg = hh >> 2;
    const int qcol = hh * HDIM;
    const int kcol = DM + gg * HDIM;
    const int vcol = DM + GHD + gg * HDIM;

    const int tid  = threadIdx.x;
    const int wid  = tid >> 5;
    const int lane = tid & 31;
    const int g4   = lane >> 2;
    const int t4   = lane & 3;
    const int wm   = wid * 16;
    const int s0q  = qb * 128;

    {
        int r = tid >> 1, half = tid & 1;
        const float* src = qkv + (long)(s0q + r) * QKV + qcol + half * 32;
        uint32_t* dst = Qs + r * 36 + half * 16;
#pragma unroll
        for (int i = 0; i < 8; i++) {
            float4 v = *(const float4*)(src + i * 4);
            dst[2 * i]     = packbf(v.x, v.y);
            dst[2 * i + 1] = packbf(v.z, v.w);
        }
    }

    float O[8][4];
#pragma unroll
    for (int j = 0; j < 8; j++)
#pragma unroll
        for (int l = 0; l < 4; l++) O[j][l] = 0.0f;
    float m0 = -1e30f, m1 = -1e30f, l0 = 0.0f, l1 = 0.0f;

    const int nblk = 2 * qb + 2;
    for (int jb = 0; jb < nblk; jb++) {
        const int s0 = jb * 64;
        __syncthreads();

        {
            int r = tid >> 2, q4 = tid & 3;
            const float* src = qkv + (long)(s0 + r) * QKV + kcol + q4 * 16;
            uint32_t* dst = Ks + r * 36 + q4 * 8;
#pragma unroll
            for (int i = 0; i < 4; i++) {
                float4 v = *(const float4*)(src + i * 4);
                dst[2 * i]     = packbf(v.x, v.y);
                dst[2 * i + 1] = packbf(v.z, v.w);
            }
        }
        {
            int d = tid & 63, sb = tid >> 6;
#pragma unroll
            for (int i = 0; i < 8; i++) {
                int sp = sb * 8 + i;
                const float* p0 = qkv + (long)(s0 + 2 * sp) * QKV + vcol + d;
                Vs[d * 36 + sp] = packbf(p0[0], p0[QKV]);
            }
        }
        __syncthreads();

        float S[8][4];
#pragma unroll
        for (int j = 0; j < 8; j++)
#pragma unroll
            for (int l = 0; l < 4; l++) S[j][l] = 0.0f;

#pragma unroll
        for (int kc = 0; kc < 4; kc++) {
            uint32_t a0 = Qs[(wm + g4    ) * 36 + kc * 8 + t4    ];
            uint32_t a1 = Qs[(wm + g4 + 8) * 36 + kc * 8 + t4    ];
            uint32_t a2 = Qs[(wm + g4    ) * 36 + kc * 8 + t4 + 4];
            uint32_t a3 = Qs[(wm + g4 + 8) * 36 + kc * 8 + t4 + 4];
#pragma unroll
            for (int nf = 0; nf < 8; nf++) {
                uint32_t b0 = Ks[(nf * 8 + g4) * 36 + kc * 8 + t4    ];
                uint32_t b1 = Ks[(nf * 8 + g4) * 36 + kc * 8 + t4 + 4];
                mma_bf16(S[nf], a0, a1, a2, a3, b0, b1);
            }
        }

        if (jb >= 2 * qb) {
            const int r0 = s0q + wm + g4, r1 = r0 + 8;
#pragma unroll
            for (int nf = 0; nf < 8; nf++) {
                const int c = s0 + nf * 8 + t4 * 2;
                if (c     > r0) S[nf][0] = -1e30f;
                if (c + 1 > r0) S[nf][1] = -1e30f;
                if (c     > r1) S[nf][2] = -1e30f;
                if (c + 1 > r1) S[nf][3] = -1e30f;
            }
        }

        float bm0 = -1e30f, bm1 = -1e30f;
#pragma unroll
        for (int nf = 0; nf < 8; nf++) {
            bm0 = fmaxf(bm0, fmaxf(S[nf][0], S[nf][1]));
            bm1 = fmaxf(bm1, fmaxf(S[nf][2], S[nf][3]));
        }
        bm0 = fmaxf(bm0, __shfl_xor_sync(0xffffffffu, bm0, 1));
        bm0 = fmaxf(bm0, __shfl_xor_sync(0xffffffffu, bm0, 2));
        bm1 = fmaxf(bm1, __shfl_xor_sync(0xffffffffu, bm1, 1));
        bm1 = fmaxf(bm1, __shfl_xor_sync(0xffffffffu, bm1, 2));

        float nm0 = fmaxf(m0, bm0), nm1 = fmaxf(m1, bm1);
        float sc0 = __expf(m0 - nm0), sc1 = __expf(m1 - nm1);
        m0 = nm0; m1 = nm1;

        float ps0 = 0.0f, ps1 = 0.0f;
#pragma unroll
        for (int nf = 0; nf < 8; nf++) {
            S[nf][0] = __expf(S[nf][0] - m0);
            S[nf][1] = __expf(S[nf][1] - m0);
            S[nf][2] = __expf(S[nf][2] - m1);
            S[nf][3] = __expf(S[nf][3] - m1);
            ps0 += S[nf][0] + S[nf][1];
            ps1 += S[nf][2] + S[nf][3];
        }
        ps0 += __shfl_xor_sync(0xffffffffu, ps0, 1);
        ps0 += __shfl_xor_sync(0xffffffffu, ps0, 2);
        ps1 += __shfl_xor_sync(0xffffffffu, ps1, 1);
        ps1 += __shfl_xor_sync(0xffffffffu, ps1, 2);
        l0 = l0 * sc0 + ps0;
        l1 = l1 * sc1 + ps1;

#pragma unroll
        for (int nf = 0; nf < 8; nf++) {
            O[nf][0] *= sc0; O[nf][1] *= sc0;
            O[nf][2] *= sc1; O[nf][3] *= sc1;
        }

#pragma unroll
        for (int kc = 0; kc < 4; kc++) {
            uint32_t ah0 = packbf(S[2*kc  ][0], S[2*kc  ][1]);
            uint32_t ah1 = packbf(S[2*kc  ][2], S[2*kc  ][3]);
            uint32_t ah2 = packbf(S[2*kc+1][0], S[2*kc+1][1]);
            uint32_t ah3 = packbf(S[2*kc+1][2], S[2*kc+1][3]);
            uint32_t al0 = packbf_res(S[2*kc  ][0], S[2*kc  ][1], ah0);
            uint32_t al1 = packbf_res(S[2*kc  ][2], S[2*kc  ][3], ah1);
            uint32_t al2 = packbf_res(S[2*kc+1][0], S[2*kc+1][1], ah2);
            uint32_t al3 = packbf_res(S[2*kc+1][2], S[2*kc+1][3], ah3);
#pragma unroll
            for (int nf = 0; nf < 8; nf++) {
                uint32_t b0 = Vs[(nf * 8 + g4) * 36 + kc * 8 + t4    ];
                uint32_t b1 = Vs[(nf * 8 + g4) * 36 + kc * 8 + t4 + 4];
                mma_bf16(O[nf], ah0, ah1, ah2, ah3, b0, b1);
                mma_bf16(O[nf], al0, al1, al2, al3, b0, b1);
            }
        }
    }

    const float inv0 = 1.0f / l0, inv1 = 1.0f / l1;
    const int row0 = s0q + wm + g4;
#pragma unroll
    for (int nf = 0; nf < 8; nf++) {
        const int col = hh * HDIM + nf * 8 + t4 * 2;
        *(uint32_t*)(attnb + (long)row0 * DM + col) =
            packbf(O[nf][0] * inv0, O[nf][1] * inv0);
        *(uint32_t*)(attnb + (long)(row0 + 8) * DM + col) =
            packbf(O[nf][2] * inv1, O[nf][3] * inv1);
    }
}

// ---------------- embedding gather (fp32 + bf16 copies) ----------------
__global__ void embed_k(const int* __restrict__ x, const float* __restrict__ emb,
                        float* __restrict__ h, __nv_bfloat16* __restrict__ hb)
{
    int s = blockIdx.x;
    int t = threadIdx.x;
    float4 v = ((const float4*)(emb + (long)x[s] * DM))[t];
    ((float4*)(h + (long)s * DM))[t] = v;
    uint32_t* d = (uint32_t*)(hb + (long)s * DM) + t * 2;
    d[0] = packbf(v.x, v.y);
    d[1] = packbf(v.z, v.w);
}

// ---------------- merged RoPE + cosine-norm (Q and K), 8 units/block ----------------
__global__ void rope_norm_k(float* __restrict__ qkv, const float* __restrict__ sqk)
{
    const int u = blockIdx.x * 8 + (threadIdx.x >> 5);   // unit over SQ*(NH+NG)
    const int j = threadIdx.x & 31;
    const int s = u / (NH + NG);
    const int z = u - s * (NH + NG);
    float* base = qkv + (long)s * QKV + ((z < NH) ? z * HDIM : DM + (z - NH) * HDIM);
    float x1 = base[j], x2 = base[j + 32];

    float inv = powf(10000.0f, -(float)j / 32.0f);
    float ang = (float)s * inv;
    float sn, cs; sincosf(ang, &sn, &cs);
    float o1 = x1 * cs - x2 * sn;
    float o2 = x2 * cs + x1 * sn;

    float ss = o1 * o1 + o2 * o2;
#pragma unroll
    for (int off = 16; off > 0; off >>= 1)
        ss += __shfl_xor_sync(0xffffffffu, ss, off);
    float n = fmaxf(sqrtf(ss), 1e-6f);

    if (z < NH) {
        float e1 = sqk[z * HDIM + j]      * RTD;
        float e2 = sqk[z * HDIM + j + 32] * RTD;
        base[j]      = (o1 / n) * e1 * e1 * RTD;
        base[j + 32] = (o2 / n) * e2 * e2 * RTD;
    } else {
        base[j]      = o1 / n;
        base[j + 32] = o2 / n;
    }
}

// ---------------- residual lerp + cosine norm (writes fp32 + bf16) ----------------
__global__ void resid_norm_k(float* __restrict__ h, __nv_bfloat16* __restrict__ hb,
                             const float* __restrict__ t, const float* __restrict__ eig)
{
    int row = blockIdx.x;
    int tid = threadIdx.x;
    __shared__ float red[256];

    float4 tv = ((const float4*)(t + (long)row * DM))[tid];
    float ss = tv.x * tv.x + tv.y * tv.y + tv.z * tv.z + tv.w * tv.w;
    red[tid] = ss; __syncthreads();
    for (int o = 128; o > 0; o >>= 1) { if (tid < o) red[tid] += red[tid + o]; __syncthreads(); }
    float nt = fmaxf(sqrtf(red[0]), 1e-6f);
    __syncthreads();

    float4 hv = ((const float4*)(h + (long)row * DM))[tid];
    float4 ev = ((const float4*)eig)[tid];
    float4 r;
    r.x = hv.x + ev.x * RTDM * (tv.x / nt - hv.x);
    r.y = hv.y + ev.y * RTDM * (tv.y / nt - hv.y);
    r.z = hv.z + ev.z * RTDM * (tv.z / nt - hv.z);
    r.w = hv.w + ev.w * RTDM * (tv.w / nt - hv.w);

    float ss2 = r.x * r.x + r.y * r.y + r.z * r.z + r.w * r.w;
    red[tid] = ss2; __syncthreads();
    for (int o = 128; o > 0; o >>= 1) { if (tid < o) red[tid] += red[tid + o]; __syncthreads(); }
    float nr = fmaxf(sqrtf(red[0]), 1e-6f);

    r.x /= nr; r.y /= nr; r.z /= nr; r.w /= nr;
    ((float4*)(h + (long)row * DM))[tid] = r;
    uint32_t* d = (uint32_t*)(hb + (long)row * DM) + tid * 2;
    d[0] = packbf(r.x, r.y);
    d[1] = packbf(r.z, r.w);
}

// ---------------- final row softmax (online: 3 memory passes) ----------------
__global__ void softmax_full_k(float* __restrict__ out)
{
    int row = blockIdx.x;
    float* p = out + (long)row * NV;
    int t = threadIdx.x;
    __shared__ float rm[256], rs[256];

    float m = -1e30f, s = 0.0f;
    for (int j = t; j < NV; j += 256) {
        float v = p[j];
        if (v > m) { s = s * __expf(m - v) + 1.0f; m = v; }
        else       { s += __expf(v - m); }
    }
    rm[t] = m; rs[t] = s; __syncthreads();
    for (int o = 128; o > 0; o >>= 1) {
        if (t < o) {
            float m2 = rm[t + o], s2 = rs[t + o];
            float M = fmaxf(rm[t], m2);
            rs[t] = rs[t] * __expf(rm[t] - M) + s2 * __expf(m2 - M);
            rm[t] = M;
        }
        __syncthreads();
    }
    float M = rm[0];
    float inv = 1.0f / rs[0];
    for (int j = t; j < NV; j += 256) p[j] = __expf(p[j] - M) * inv;
}

// ---------------- host-side launchers ----------------
static void gemm128(const __nv_bfloat16* A, const __nv_bfloat16* B, float* C,
                    int M, int N, int K, int lda, int ldb, int ldc,
                    float alpha, const float* bias, const float* scalev, float beta)
{
    dim3 grid(N / 128, M / 128);
    bf16_gemm_k<128, 128, 0><<<grid, 256>>>(A, B, C, K, lda, ldb, ldc, alpha, bias, scalev, beta);
}
static void gemm_qkv(const __nv_bfloat16* A, const __nv_bfloat16* B, float* C,
                     int M, int N, int K, int lda, int ldb, int ldc,
                     float alpha, const float* bias)
{
    dim3 grid(N / 128, M / 64);
    bf16_gemm_k<64, 128, 0><<<grid, 256>>>(A, B, C, K, lda, ldb, ldc, alpha, bias, nullptr, 0.0f);
}
static void gemm_sm(const __nv_bfloat16* A, const __nv_bfloat16* B, float* C,
                    int M, int N, int K, int lda, int ldb, int ldc,
                    float alpha, const float* bias)
{
    dim3 grid(N / 64, M / 64);
    bf16_gemm_k<64, 64, 0><<<grid, 256>>>(A, B, C, K, lda, ldb, ldc, alpha, bias, nullptr, 0.0f);
}
static void gemm_swiglu(const __nv_bfloat16* A, const __nv_bfloat16* B, __nv_bfloat16* C,
                        int M, int N, int K, int lda, int ldb, int ldc,
                        const float* bias, const float* scalev)
{
    dim3 grid(N / 128, M / 128);
    bf16_gemm_k<128, 128, 1><<<grid, 256>>>(A, B, C, K, lda, ldb, ldc, 1.0f, bias, scalev, 1.0f);
}

extern "C" void kernel_launch(void* const* d_in, const int* in_sizes, int n_in,
                              void* d_out, int out_size)
{
    const int*   x      = (const int*)  d_in[0];
    const float* emb    = (const float*)d_in[1];
    const float* qw     = (const float*)d_in[2];
    const float* qb     = (const float*)d_in[3];
    const float* kw     = (const float*)d_in[4];
    const float* kb     = (const float*)d_in[5];
    const float* vw     = (const float*)d_in[6];
    const float* vb     = (const float*)d_in[7];
    const float* sqk    = (const float*)d_in[8];
    const float* ow     = (const float*)d_in[9];
    const float* ob     = (const float*)d_in[10];
    const float* w_in   = (const float*)d_in[11];
    const float* b_in   = (const float*)d_in[12];
    const float* w_gate = (const float*)d_in[13];
    const float* b_gate = (const float*)d_in[14];
    const float* w_out  = (const float*)d_in[15];
    const float* b_out  = (const float*)d_in[16];
    const float* s_u    = (const float*)d_in[17];
    const float* s_v    = (const float*)d_in[18];
    const float* eig_a  = (const float*)d_in[19];
    const float* eig_m  = (const float*)d_in[20];
    const float* out_w  = (const float*)d_in[21];
    const float* out_b  = (const float*)d_in[22];
    const float* s_z    = (const float*)d_in[23];
    float* out = (float*)d_out;

    float *h, *qkv, *t, *qkvb, *biog, *siog;
    __nv_bfloat16 *hb, *attnb, *ub, *qkvw, *wiog, *wout, *owb, *outwb;
    cudaGetSymbolAddress((void**)&h,     g_h);
    cudaGetSymbolAddress((void**)&qkv,   g_qkv);
    cudaGetSymbolAddress((void**)&t,     g_t);
    cudaGetSymbolAddress((void**)&qkvb,  g_qkvb);
    cudaGetSymbolAddress((void**)&biog,  g_biog);
    cudaGetSymbolAddress((void**)&siog,  g_siog);
    cudaGetSymbolAddress((void**)&hb,    g_hb);
    cudaGetSymbolAddress((void**)&attnb, g_attnb);
    cudaGetSymbolAddress((void**)&ub,    g_ub);
    cudaGetSymbolAddress((void**)&qkvw,  g_qkvw);
    cudaGetSymbolAddress((void**)&wiog,  g_wiog);
    cudaGetSymbolAddress((void**)&wout,  g_wout);
    cudaGetSymbolAddress((void**)&owb,   g_ow);
    cudaGetSymbolAddress((void**)&outwb, g_outw);

    cvt_all_k<<<8192, 256>>>(qw, kw, vw, w_in, w_gate, w_out, ow, out_w,
                             qb, kb, vb, b_in, b_gate, s_u, s_v);

    embed_k<<<SQ, 256>>>(x, emb, h, hb);

    for (int i = 0; i < NL; i++) {
        gemm_qkv(hb, qkvw + (long)i * QKV * DM, qkv, SQ, QKV, DM, DM, DM, QKV,
                 1.0f, qkvb + i * QKV);

        rope_norm_k<<<SQ * (NH + NG) / 8, 256>>>(qkv, sqk + (long)i * NH * HDIM);

        flash_attn_k<<<dim3(SQ / 128, NH), 256>>>(qkv, attnb);

        gemm_sm(attnb, owb + (long)i * DM * DM, t, SQ, DM, DM, DM, DM, DM,
                1.0f, ob + (long)i * DM);
        resid_norm_k<<<SQ, 256>>>(h, hb, t, eig_a + (long)i * DM);

        gemm_swiglu(hb, wiog + (long)i * 2 * DFF * DM, ub, SQ, 2 * DFF, DM, DM, DM, DFF,
                    biog + (long)i * 2 * DFF, siog + (long)i * 2 * DFF);
        gemm_sm(ub, wout + (long)i * DM * DFF, t, SQ, DM, DFF, DFF, DFF, DM,
                1.0f, b_out + (long)i * DM);
        resid_norm_k<<<SQ, 256>>>(h, hb, t, eig_m + (long)i * DM);
    }

    gemm128(hb, outwb, out, SQ, NV, DM, DM, DM, NV,
            1.0f, out_b, s_z, RTDM);
    softmax_full_k<<<SQ, 256>>>(out);
}